// round 2
// baseline (speedup 1.0000x reference)
#include <cuda_runtime.h>

#define NOBJ 20000
#define NTRI 60000
#define DD   256
#define HH   512
#define LL   5
#define K1   768    // 3*D
#define N1   1280   // 2H+D

static inline int cdiv_h(int a, int b) { return (a + b - 1) / b; }

// ---------------- scratch (device globals; no allocation) ----------------
__device__ float g_objA[NOBJ * DD];
__device__ float g_objB[NOBJ * DD];
__device__ float g_predA[NTRI * DD];
__device__ float g_predB[NTRI * DD];
__device__ float g_pooled[NOBJ * HH];
__device__ float g_W12[LL * K1 * N1];     // 5*768*1280
__device__ float g_b12[LL * N1];
__device__ float g_W34[LL * HH * DD];     // 5*512*256
__device__ float g_b34[LL * DD];
__device__ int   g_sidx[NTRI];
__device__ int   g_oidx[NTRI];
__device__ int   g_cnt[NOBJ];
__device__ float g_inv[NOBJ];
__device__ int   g_is64;

// ---------------- small utility kernels ----------------
__global__ void zero_cnt_kernel() {
    int i = blockIdx.x * blockDim.x + threadIdx.x;
    if (i < NOBJ) g_cnt[i] = 0;
}

__global__ void zero_pooled_kernel() {
    long i = (long)blockIdx.x * blockDim.x + threadIdx.x;
    float4* p = (float4*)g_pooled;
    if (i < (long)NOBJ * HH / 4) p[i] = make_float4(0.f, 0.f, 0.f, 0.f);
}

// Detect whether edges arrived as int64 (high 32-bit words all zero, since
// values < 20000) or int32. Checks 8 odd words -> false positive prob ~0.
__global__ void detect_kernel(const int* e) {
    int ok = 1;
    #pragma unroll
    for (int w = 1; w < 16; w += 2) ok &= (e[w] == 0);
    g_is64 = ok;
}

__global__ void convert_kernel(const void* edges) {
    int i = blockIdx.x * blockDim.x + threadIdx.x;
    if (i >= NTRI) return;
    int s, o;
    if (g_is64) {
        const long long* p = (const long long*)edges;
        s = (int)p[2 * i]; o = (int)p[2 * i + 1];
    } else {
        const int* p = (const int*)edges;
        s = p[2 * i]; o = p[2 * i + 1];
    }
    g_sidx[i] = s;
    g_oidx[i] = o;
    atomicAdd(&g_cnt[s], 1);
    atomicAdd(&g_cnt[o], 1);
}

__global__ void inv_kernel() {
    int i = blockIdx.x * blockDim.x + threadIdx.x;
    if (i < NOBJ) {
        int c = g_cnt[i];
        g_inv[i] = 1.0f / (float)(c > 0 ? c : 1);
    }
}

// b12 = b1 @ W2 + b2  (per layer)
__global__ void bias12_kernel(const float* __restrict__ b1,
                              const float* __restrict__ W2,
                              const float* __restrict__ b2) {
    int l = blockIdx.z;
    int c = blockIdx.x * blockDim.x + threadIdx.x;
    if (c >= N1) return;
    const float* b1l = b1 + l * HH;
    const float* W2l = W2 + (long)l * HH * N1;
    float s = b2[(long)l * N1 + c];
    for (int k = 0; k < HH; k++) s = fmaf(b1l[k], W2l[(long)k * N1 + c], s);
    g_b12[l * N1 + c] = s;
}

// b34 = b3 @ W4 + b4  (per layer)
__global__ void bias34_kernel(const float* __restrict__ b3,
                              const float* __restrict__ W4,
                              const float* __restrict__ b4) {
    int l = blockIdx.z;
    int c = blockIdx.x * blockDim.x + threadIdx.x;
    if (c >= DD) return;
    const float* b3l = b3 + l * HH;
    const float* W4l = W4 + (long)l * HH * DD;
    float s = b4[(long)l * DD + c];
    for (int k = 0; k < HH; k++) s = fmaf(b3l[k], W4l[(long)k * DD + c], s);
    g_b34[l * DD + c] = s;
}

// ---------------- weight-prep GEMM: C = A @ B, batched over layers ----------------
// which==0 -> C = g_W12 (M=768,K=512,N=1280), which==1 -> C = g_W34 (M=512,K=512,N=256)
__global__ __launch_bounds__(256, 2)
void sgemm_prep(const float* __restrict__ A, const float* __restrict__ B,
                int which, int M, int N, int K) {
    float* C = (which == 0) ? g_W12 : g_W34;
    long z = blockIdx.z;
    A += z * (long)M * K;
    B += z * (long)K * N;
    C += z * (long)M * N;

    __shared__ float As[16][128];
    __shared__ float Bs[16][128];
    int tid = threadIdx.x;
    int tx = tid & 15, ty = tid >> 4;
    int blockRow = blockIdx.y * 128;
    int blockCol = blockIdx.x * 128;

    float acc[8][8];
    #pragma unroll
    for (int i = 0; i < 8; i++)
        #pragma unroll
        for (int j = 0; j < 8; j++) acc[i][j] = 0.f;

    int lr = tid >> 1;
    int lc = (tid & 1) * 8;
    int br = tid >> 4;
    int bc = (tid & 15) * 8;

    for (int k0 = 0; k0 < K; k0 += 16) {
        int gr = blockRow + lr;
        float4 a0, a1;
        if (gr < M) {
            const float* rp = A + (long)gr * K + k0;
            a0 = *(const float4*)(rp + lc);
            a1 = *(const float4*)(rp + lc + 4);
        } else { a0 = make_float4(0,0,0,0); a1 = a0; }
        As[lc+0][lr]=a0.x; As[lc+1][lr]=a0.y; As[lc+2][lr]=a0.z; As[lc+3][lr]=a0.w;
        As[lc+4][lr]=a1.x; As[lc+5][lr]=a1.y; As[lc+6][lr]=a1.z; As[lc+7][lr]=a1.w;

        const float* bp = B + (long)(k0 + br) * N + blockCol + bc;
        float4 b0 = *(const float4*)bp;
        float4 b1 = *(const float4*)(bp + 4);
        *(float4*)&Bs[br][bc]     = b0;
        *(float4*)&Bs[br][bc + 4] = b1;
        __syncthreads();

        #pragma unroll
        for (int k = 0; k < 16; k++) {
            float4 x0 = *(float4*)&As[k][ty * 8];
            float4 x1 = *(float4*)&As[k][ty * 8 + 4];
            float4 y0 = *(float4*)&Bs[k][tx * 8];
            float4 y1 = *(float4*)&Bs[k][tx * 8 + 4];
            float ra[8] = {x0.x,x0.y,x0.z,x0.w,x1.x,x1.y,x1.z,x1.w};
            float rb[8] = {y0.x,y0.y,y0.z,y0.w,y1.x,y1.y,y1.z,y1.w};
            #pragma unroll
            for (int i = 0; i < 8; i++)
                #pragma unroll
                for (int j = 0; j < 8; j++) acc[i][j] = fmaf(ra[i], rb[j], acc[i][j]);
        }
        __syncthreads();
    }

    #pragma unroll
    for (int i = 0; i < 8; i++) {
        int gr = blockRow + ty * 8 + i;
        if (gr >= M) continue;
        #pragma unroll
        for (int j = 0; j < 8; j++) {
            int gc = blockCol + tx * 8 + j;
            if (gc < N) C[(long)gr * N + gc] = acc[i][j];
        }
    }
}

// ---------------- main GEMM A: new_t = gather(obj,pred) @ W12 + b12, fused scatter ----------------
// srcSel: 0 = external inputs, 1 = (g_objA,g_predA), 2 = (g_objB,g_predB)
// dstSel (pred out): 1 = g_predA, 2 = g_predB, 3 = external
__global__ __launch_bounds__(256, 2)
void gemmA_kernel(const float* __restrict__ objExt, const float* __restrict__ predExt,
                  int srcSel, int dstSel, float* __restrict__ predExtOut, int layer) {
    const float* obj  = (srcSel == 0) ? objExt  : (srcSel == 1 ? g_objA  : g_objB);
    const float* pred = (srcSel == 0) ? predExt : (srcSel == 1 ? g_predA : g_predB);
    float* predOut = (dstSel == 1) ? g_predA : (dstSel == 2 ? g_predB : predExtOut);
    const float* W    = g_W12 + (long)layer * K1 * N1;
    const float* bias = g_b12 + layer * N1;

    __shared__ float As[16][128];
    __shared__ float Bs[16][128];
    int tid = threadIdx.x;
    int tx = tid & 15, ty = tid >> 4;
    int blockRow = blockIdx.y * 128;
    int blockCol = blockIdx.x * 128;

    float acc[8][8];
    #pragma unroll
    for (int i = 0; i < 8; i++)
        #pragma unroll
        for (int j = 0; j < 8; j++) acc[i][j] = 0.f;

    int lr = tid >> 1;          // 0..127 (A load row within tile)
    int lc = (tid & 1) * 8;     // 0 or 8
    int grl = blockRow + lr;
    int sI = 0, oI = 0;
    if (grl < NTRI) { sI = g_sidx[grl]; oI = g_oidx[grl]; }

    int br = tid >> 4;          // 0..15 (B load row)
    int bc = (tid & 15) * 8;

    for (int k0 = 0; k0 < K1; k0 += 16) {
        float4 a0, a1;
        if (grl < NTRI) {
            const float* rp;
            if (k0 < 256)      rp = obj  + (long)sI  * DD + k0;
            else if (k0 < 512) rp = pred + (long)grl * DD + (k0 - 256);
            else               rp = obj  + (long)oI  * DD + (k0 - 512);
            a0 = *(const float4*)(rp + lc);
            a1 = *(const float4*)(rp + lc + 4);
        } else { a0 = make_float4(0,0,0,0); a1 = a0; }
        As[lc+0][lr]=a0.x; As[lc+1][lr]=a0.y; As[lc+2][lr]=a0.z; As[lc+3][lr]=a0.w;
        As[lc+4][lr]=a1.x; As[lc+5][lr]=a1.y; As[lc+6][lr]=a1.z; As[lc+7][lr]=a1.w;

        const float* bp = W + (long)(k0 + br) * N1 + blockCol + bc;
        float4 b0 = *(const float4*)bp;
        float4 b1 = *(const float4*)(bp + 4);
        *(float4*)&Bs[br][bc]     = b0;
        *(float4*)&Bs[br][bc + 4] = b1;
        __syncthreads();

        #pragma unroll
        for (int k = 0; k < 16; k++) {
            float4 x0 = *(float4*)&As[k][ty * 8];
            float4 x1 = *(float4*)&As[k][ty * 8 + 4];
            float4 y0 = *(float4*)&Bs[k][tx * 8];
            float4 y1 = *(float4*)&Bs[k][tx * 8 + 4];
            float ra[8] = {x0.x,x0.y,x0.z,x0.w,x1.x,x1.y,x1.z,x1.w};
            float rb[8] = {y0.x,y0.y,y0.z,y0.w,y1.x,y1.y,y1.z,y1.w};
            #pragma unroll
            for (int i = 0; i < 8; i++)
                #pragma unroll
                for (int j = 0; j < 8; j++) acc[i][j] = fmaf(ra[i], rb[j], acc[i][j]);
        }
        __syncthreads();
    }

    // epilogue: cols [0,512) -> atomic into pooled[s]; [512,768) -> pred out;
    //           [768,1280) -> atomic into pooled[o]
    #pragma unroll
    for (int i = 0; i < 8; i++) {
        int gr = blockRow + ty * 8 + i;
        if (gr >= NTRI) continue;
        int s = g_sidx[gr], o = g_oidx[gr];
        #pragma unroll
        for (int j = 0; j < 8; j++) {
            int gc = blockCol + tx * 8 + j;
            float v = acc[i][j] + bias[gc];
            if (gc < HH)            atomicAdd(&g_pooled[(long)s * HH + gc], v);
            else if (gc < HH + DD)  predOut[(long)gr * DD + (gc - HH)] = v;
            else                    atomicAdd(&g_pooled[(long)o * HH + (gc - HH - DD)], v);
        }
    }
}

// ---------------- main GEMM B: obj' = (pooled * inv) @ W34 + b34 ----------------
// dstSel: 1 = g_objA, 2 = g_objB, 3 = external
__global__ __launch_bounds__(256, 2)
void gemmB_kernel(int dstSel, float* __restrict__ objExtOut, int layer) {
    float* objOut = (dstSel == 1) ? g_objA : (dstSel == 2 ? g_objB : objExtOut);
    const float* W    = g_W34 + (long)layer * HH * DD;
    const float* bias = g_b34 + layer * DD;

    __shared__ float As[16][128];
    __shared__ float Bs[16][128];
    int tid = threadIdx.x;
    int tx = tid & 15, ty = tid >> 4;
    int blockRow = blockIdx.y * 128;
    int blockCol = blockIdx.x * 128;

    float acc[8][8];
    #pragma unroll
    for (int i = 0; i < 8; i++)
        #pragma unroll
        for (int j = 0; j < 8; j++) acc[i][j] = 0.f;

    int lr = tid >> 1;
    int lc = (tid & 1) * 8;
    int grl = blockRow + lr;
    float inv = (grl < NOBJ) ? g_inv[grl] : 0.f;

    int br = tid >> 4;
    int bc = (tid & 15) * 8;

    for (int k0 = 0; k0 < HH; k0 += 16) {
        float4 a0, a1;
        if (grl < NOBJ) {
            const float* rp = g_pooled + (long)grl * HH + k0;
            a0 = *(const float4*)(rp + lc);
            a1 = *(const float4*)(rp + lc + 4);
            a0.x *= inv; a0.y *= inv; a0.z *= inv; a0.w *= inv;
            a1.x *= inv; a1.y *= inv; a1.z *= inv; a1.w *= inv;
        } else { a0 = make_float4(0,0,0,0); a1 = a0; }
        As[lc+0][lr]=a0.x; As[lc+1][lr]=a0.y; As[lc+2][lr]=a0.z; As[lc+3][lr]=a0.w;
        As[lc+4][lr]=a1.x; As[lc+5][lr]=a1.y; As[lc+6][lr]=a1.z; As[lc+7][lr]=a1.w;

        const float* bp = W + (long)(k0 + br) * DD + blockCol + bc;
        float4 b0 = *(const float4*)bp;
        float4 b1 = *(const float4*)(bp + 4);
        *(float4*)&Bs[br][bc]     = b0;
        *(float4*)&Bs[br][bc + 4] = b1;
        __syncthreads();

        #pragma unroll
        for (int k = 0; k < 16; k++) {
            float4 x0 = *(float4*)&As[k][ty * 8];
            float4 x1 = *(float4*)&As[k][ty * 8 + 4];
            float4 y0 = *(float4*)&Bs[k][tx * 8];
            float4 y1 = *(float4*)&Bs[k][tx * 8 + 4];
            float ra[8] = {x0.x,x0.y,x0.z,x0.w,x1.x,x1.y,x1.z,x1.w};
            float rb[8] = {y0.x,y0.y,y0.z,y0.w,y1.x,y1.y,y1.z,y1.w};
            #pragma unroll
            for (int i = 0; i < 8; i++)
                #pragma unroll
                for (int j = 0; j < 8; j++) acc[i][j] = fmaf(ra[i], rb[j], acc[i][j]);
        }
        __syncthreads();
    }

    #pragma unroll
    for (int i = 0; i < 8; i++) {
        int gr = blockRow + ty * 8 + i;
        if (gr >= NOBJ) continue;
        #pragma unroll
        for (int j = 0; j < 8; j++) {
            int gc = blockCol + tx * 8 + j;
            objOut[(long)gr * DD + gc] = acc[i][j] + bias[gc];
        }
    }
}

// ---------------- launcher ----------------
extern "C" void kernel_launch(void* const* d_in, const int* in_sizes, int n_in,
                              void* d_out, int out_size) {
    const float* obj_in  = (const float*)d_in[0];
    const float* pred_in = (const float*)d_in[1];
    const void*  edges   = d_in[2];
    const float* W1 = (const float*)d_in[3];
    const float* b1 = (const float*)d_in[4];
    const float* W2 = (const float*)d_in[5];
    const float* b2 = (const float*)d_in[6];
    const float* W3 = (const float*)d_in[7];
    const float* b3 = (const float*)d_in[8];
    const float* W4 = (const float*)d_in[9];
    const float* b4 = (const float*)d_in[10];

    float* out_obj  = (float*)d_out;                       // [20000, 256]
    float* out_pred = (float*)d_out + (long)NOBJ * DD;     // [60000, 256]

    // --- edge indices + counts (fixed across layers) ---
    zero_cnt_kernel<<<cdiv_h(NOBJ, 256), 256>>>();
    detect_kernel<<<1, 1>>>((const int*)edges);
    convert_kernel<<<cdiv_h(NTRI, 256), 256>>>(edges);
    inv_kernel<<<cdiv_h(NOBJ, 256), 256>>>();

    // --- composite weights (layers are affine -> fold GEMM pairs) ---
    sgemm_prep<<<dim3(N1 / 128, K1 / 128, LL), 256>>>(W1, W2, 0, K1, N1, HH);
    sgemm_prep<<<dim3(DD / 128, HH / 128, LL), 256>>>(W3, W4, 1, HH, DD, HH);
    bias12_kernel<<<dim3(cdiv_h(N1, 256), 1, LL), 256>>>(b1, W2, b2);
    bias34_kernel<<<dim3(cdiv_h(DD, 256), 1, LL), 256>>>(b3, W4, b4);

    dim3 gridA(N1 / 128, cdiv_h(NTRI, 128));   // (10, 469)
    dim3 gridB(DD / 128, cdiv_h(NOBJ, 128));   // (2, 157)
    int zpBlocks = cdiv_h(NOBJ * HH / 4, 256);

    // layer 0: ext -> A
    zero_pooled_kernel<<<zpBlocks, 256>>>();
    gemmA_kernel<<<gridA, 256>>>(obj_in, pred_in, 0, 1, nullptr, 0);
    gemmB_kernel<<<gridB, 256>>>(1, nullptr, 0);
    // layer 1: A -> B
    zero_pooled_kernel<<<zpBlocks, 256>>>();
    gemmA_kernel<<<gridA, 256>>>(nullptr, nullptr, 1, 2, nullptr, 1);
    gemmB_kernel<<<gridB, 256>>>(2, nullptr, 1);
    // layer 2: B -> A
    zero_pooled_kernel<<<zpBlocks, 256>>>();
    gemmA_kernel<<<gridA, 256>>>(nullptr, nullptr, 2, 1, nullptr, 2);
    gemmB_kernel<<<gridB, 256>>>(1, nullptr, 2);
    // layer 3: A -> B
    zero_pooled_kernel<<<zpBlocks, 256>>>();
    gemmA_kernel<<<gridA, 256>>>(nullptr, nullptr, 1, 2, nullptr, 3);
    gemmB_kernel<<<gridB, 256>>>(2, nullptr, 3);
    // layer 4: B -> external output
    zero_pooled_kernel<<<zpBlocks, 256>>>();
    gemmA_kernel<<<gridA, 256>>>(nullptr, nullptr, 2, 3, out_pred, 4);
    gemmB_kernel<<<gridB, 256>>>(3, out_obj, 4);
}

// round 6
// speedup vs baseline: 1.8482x; 1.8482x over previous
#include <cuda_runtime.h>
#include <cuda_bf16.h>
#include <cstdint>

#define NOBJ 20000
#define NTRI 60000
#define DD   256
#define HH   512
#define LL   5
#define K1   768    // 3*D
#define N1   1280   // 2H+D
#define KCH  64     // K chunk per SMEM stage

static inline int cdiv_h(int a, int b) { return (a + b - 1) / b; }

// ======================= PTX helpers =======================
__device__ __forceinline__ uint32_t smem_u32(const void* p) {
    uint32_t a;
    asm("{ .reg .u64 t; cvta.to.shared.u64 t, %1; cvt.u32.u64 %0, t; }" : "=r"(a) : "l"(p));
    return a;
}
#define SW128(off) ((off) ^ (((off) >> 3) & 0x70))

__device__ __forceinline__ void ldsm_x4(uint32_t& r0, uint32_t& r1, uint32_t& r2, uint32_t& r3,
                                        uint32_t addr) {
    asm volatile("ldmatrix.sync.aligned.m8n8.x4.shared.b16 {%0,%1,%2,%3}, [%4];"
                 : "=r"(r0), "=r"(r1), "=r"(r2), "=r"(r3) : "r"(addr));
}
__device__ __forceinline__ void mma_16816(float* c, const uint32_t* a, const uint32_t* b) {
    asm volatile("mma.sync.aligned.m16n8k16.row.col.f32.bf16.bf16.f32 "
                 "{%0,%1,%2,%3}, {%4,%5,%6,%7}, {%8,%9}, {%0,%1,%2,%3};"
                 : "+f"(c[0]), "+f"(c[1]), "+f"(c[2]), "+f"(c[3])
                 : "r"(a[0]), "r"(a[1]), "r"(a[2]), "r"(a[3]), "r"(b[0]), "r"(b[1]));
}
__device__ __forceinline__ void red_add4(float* p, float a, float b, float c, float d) {
    asm volatile("red.global.add.v4.f32 [%0], {%1, %2, %3, %4};"
                 :: "l"(p), "f"(a), "f"(b), "f"(c), "f"(d) : "memory");
}
__device__ __forceinline__ void split_bf16(float x, __nv_bfloat16& h, __nv_bfloat16& l) {
    h = __float2bfloat16(x);
    l = __float2bfloat16(x - __bfloat162float(h));
}
// pack 2 floats into bf16x2 hi word + bf16x2 lo word
__device__ __forceinline__ uint32_t pack_hi2(float a, float b, uint32_t& lo2) {
    __nv_bfloat16 ha, la, hb, lb;
    split_bf16(a, ha, la); split_bf16(b, hb, lb);
    __nv_bfloat162 H; H.x = ha; H.y = hb;
    __nv_bfloat162 L; L.x = la; L.y = lb;
    lo2 = *(uint32_t*)&L;
    return *(uint32_t*)&H;
}

// ======================= device globals (no allocation) =======================
__device__ __nv_bfloat16 g_objHi[2][NOBJ * DD];
__device__ __nv_bfloat16 g_objLo[2][NOBJ * DD];
__device__ __nv_bfloat16 g_predHi[2][NTRI * DD];
__device__ __nv_bfloat16 g_predLo[2][NTRI * DD];
__device__ __nv_bfloat16 g_WThi[LL * N1 * K1];     // W12 composite, [l][n][k]
__device__ __nv_bfloat16 g_WTlo[LL * N1 * K1];
__device__ __nv_bfloat16 g_W34Thi[LL * DD * HH];   // W34 composite, [l][n][k]
__device__ __nv_bfloat16 g_W34Tlo[LL * DD * HH];
__device__ float g_pooled[NOBJ * HH];
__device__ float g_W12[LL * K1 * N1];
__device__ float g_b12[LL * N1];
__device__ float g_W34[LL * HH * DD];
__device__ float g_b34[LL * DD];
__device__ int   g_sidx[NTRI];
__device__ int   g_oidx[NTRI];
__device__ int   g_cnt[NOBJ];
__device__ float g_inv[NOBJ];
__device__ int   g_is64;

// ======================= small utility kernels =======================
__global__ void zero_cnt_kernel() {
    int i = blockIdx.x * blockDim.x + threadIdx.x;
    if (i < NOBJ) g_cnt[i] = 0;
}
__global__ void zero_pooled_kernel() {
    long i = (long)blockIdx.x * blockDim.x + threadIdx.x;
    float4* p = (float4*)g_pooled;
    if (i < (long)NOBJ * HH / 4) p[i] = make_float4(0.f, 0.f, 0.f, 0.f);
}
__global__ void detect_kernel(const int* e) {
    int ok = 1;
    #pragma unroll
    for (int w = 1; w < 16; w += 2) ok &= (e[w] == 0);
    g_is64 = ok;
}
__global__ void convert_kernel(const void* edges) {
    int i = blockIdx.x * blockDim.x + threadIdx.x;
    if (i >= NTRI) return;
    int s, o;
    if (g_is64) {
        const long long* p = (const long long*)edges;
        s = (int)p[2 * i]; o = (int)p[2 * i + 1];
    } else {
        const int* p = (const int*)edges;
        s = p[2 * i]; o = p[2 * i + 1];
    }
    g_sidx[i] = s; g_oidx[i] = o;
    atomicAdd(&g_cnt[s], 1);
    atomicAdd(&g_cnt[o], 1);
}
__global__ void inv_kernel() {
    int i = blockIdx.x * blockDim.x + threadIdx.x;
    if (i < NOBJ) {
        int c = g_cnt[i];
        g_inv[i] = 1.0f / (float)(c > 0 ? c : 1);
    }
}
__global__ void cvt_obj_kernel(const float* __restrict__ src) {
    int i = blockIdx.x * blockDim.x + threadIdx.x;
    if (i < NOBJ * DD) {
        __nv_bfloat16 h, l; split_bf16(src[i], h, l);
        g_objHi[0][i] = h; g_objLo[0][i] = l;
    }
}
__global__ void cvt_pred_kernel(const float* __restrict__ src) {
    int i = blockIdx.x * blockDim.x + threadIdx.x;
    if (i < NTRI * DD) {
        __nv_bfloat16 h, l; split_bf16(src[i], h, l);
        g_predHi[0][i] = h; g_predLo[0][i] = l;
    }
}
__global__ void bias12_kernel(const float* __restrict__ b1, const float* __restrict__ W2,
                              const float* __restrict__ b2) {
    int l = blockIdx.z;
    int c = blockIdx.x * blockDim.x + threadIdx.x;
    if (c >= N1) return;
    const float* b1l = b1 + l * HH;
    const float* W2l = W2 + (long)l * HH * N1;
    float s = b2[(long)l * N1 + c];
    for (int k = 0; k < HH; k++) s = fmaf(b1l[k], W2l[(long)k * N1 + c], s);
    g_b12[l * N1 + c] = s;
}
__global__ void bias34_kernel(const float* __restrict__ b3, const float* __restrict__ W4,
                              const float* __restrict__ b4) {
    int l = blockIdx.z;
    int c = blockIdx.x * blockDim.x + threadIdx.x;
    if (c >= DD) return;
    const float* b3l = b3 + l * HH;
    const float* W4l = W4 + (long)l * HH * DD;
    float s = b4[(long)l * DD + c];
    for (int k = 0; k < HH; k++) s = fmaf(b3l[k], W4l[(long)k * DD + c], s);
    g_b34[l * DD + c] = s;
}

// transpose + hi/lo split of a composite weight:  src [l][k][n] -> dst [l][n][k]
// which==0: W12 (K=K1, N=N1); which==1: W34 (K=HH, N=DD)
__global__ void transpose_split_kernel(int which) {
    __shared__ float tile[32][33];
    int l = blockIdx.z;
    int K = which ? HH : K1;
    int N = which ? DD : N1;
    const float* W = (which ? g_W34 : g_W12) + (long)l * K * N;
    __nv_bfloat16* Hp = (which ? g_W34Thi : g_WThi) + (long)l * N * K;
    __nv_bfloat16* Lp = (which ? g_W34Tlo : g_WTlo) + (long)l * N * K;
    int k0 = blockIdx.x * 32;
    int n0 = blockIdx.y * 32;
    int tx = threadIdx.x, ty = threadIdx.y;
    #pragma unroll
    for (int i = 0; i < 32; i += 8)
        tile[ty + i][tx] = W[(long)(k0 + ty + i) * N + n0 + tx];
    __syncthreads();
    #pragma unroll
    for (int i = 0; i < 32; i += 8) {
        float v = tile[tx][ty + i];
        __nv_bfloat16 h, lo; split_bf16(v, h, lo);
        long o = (long)(n0 + ty + i) * K + k0 + tx;
        Hp[o] = h; Lp[o] = lo;
    }
}

// ---------------- weight-prep GEMM (fp32, once per replay) ----------------
__global__ __launch_bounds__(256, 2)
void sgemm_prep(const float* __restrict__ A, const float* __restrict__ B,
                int which, int M, int N, int K) {
    float* C = (which == 0) ? g_W12 : g_W34;
    long z = blockIdx.z;
    A += z * (long)M * K; B += z * (long)K * N; C += z * (long)M * N;
    __shared__ float As[16][128];
    __shared__ float Bs[16][128];
    int tid = threadIdx.x;
    int tx = tid & 15, ty = tid >> 4;
    int blockRow = blockIdx.y * 128, blockCol = blockIdx.x * 128;
    float acc[8][8];
    #pragma unroll
    for (int i = 0; i < 8; i++)
        #pragma unroll
        for (int j = 0; j < 8; j++) acc[i][j] = 0.f;
    int lr = tid >> 1, lc = (tid & 1) * 8;
    int br = tid >> 4, bc = (tid & 15) * 8;
    for (int k0 = 0; k0 < K; k0 += 16) {
        int gr = blockRow + lr;
        float4 a0, a1;
        if (gr < M) {
            const float* rp = A + (long)gr * K + k0;
            a0 = *(const float4*)(rp + lc); a1 = *(const float4*)(rp + lc + 4);
        } else { a0 = make_float4(0,0,0,0); a1 = a0; }
        As[lc+0][lr]=a0.x; As[lc+1][lr]=a0.y; As[lc+2][lr]=a0.z; As[lc+3][lr]=a0.w;
        As[lc+4][lr]=a1.x; As[lc+5][lr]=a1.y; As[lc+6][lr]=a1.z; As[lc+7][lr]=a1.w;
        const float* bp = B + (long)(k0 + br) * N + blockCol + bc;
        *(float4*)&Bs[br][bc]     = *(const float4*)bp;
        *(float4*)&Bs[br][bc + 4] = *(const float4*)(bp + 4);
        __syncthreads();
        #pragma unroll
        for (int k = 0; k < 16; k++) {
            float4 x0 = *(float4*)&As[k][ty * 8];
            float4 x1 = *(float4*)&As[k][ty * 8 + 4];
            float4 y0 = *(float4*)&Bs[k][tx * 8];
            float4 y1 = *(float4*)&Bs[k][tx * 8 + 4];
            float ra[8] = {x0.x,x0.y,x0.z,x0.w,x1.x,x1.y,x1.z,x1.w};
            float rb[8] = {y0.x,y0.y,y0.z,y0.w,y1.x,y1.y,y1.z,y1.w};
            #pragma unroll
            for (int i = 0; i < 8; i++)
                #pragma unroll
                for (int j = 0; j < 8; j++) acc[i][j] = fmaf(ra[i], rb[j], acc[i][j]);
        }
        __syncthreads();
    }
    #pragma unroll
    for (int i = 0; i < 8; i++) {
        int gr = blockRow + ty * 8 + i;
        if (gr >= M) continue;
        #pragma unroll
        for (int j = 0; j < 8; j++) {
            int gc = blockCol + tx * 8 + j;
            if (gc < N) C[(long)gr * N + gc] = acc[i][j];
        }
    }
}

// ======================= MMA GEMMs (bf16x3 via mma.sync) =======================
// SMEM layout (1024-aligned base): sIdx[128] @0, oIdx[128] @512, planes @1024:
//   A_hi 16KB | A_lo 16KB | B_hi 16KB | B_lo 16KB  (128 rows x 128B, SW128)
// C (fp32 128x128, 64KB) reuses plane space in the epilogue.
#define MM_SMEM (1024 + 1024 + 4 * 16384)

// gemmA: new_t = gather(obj,pred) @ W12 + b12, fused scatter
__global__ __launch_bounds__(256)
void gemmA_mma(int srcBuf, int layer, int last, float* __restrict__ predExtOut) {
    extern __shared__ char smem[];
    uint32_t raw  = smem_u32(smem);
    uint32_t base = (raw + 1023u) & ~1023u;
    char* pal = smem + (base - raw);
    int* sIdxS = (int*)(pal);
    int* oIdxS = (int*)(pal + 512);
    const uint32_t uAhi = base + 1024;
    const uint32_t uAlo = uAhi + 16384;
    const uint32_t uBhi = uAlo + 16384;
    const uint32_t uBlo = uBhi + 16384;
    char* pAhi = pal + 1024;
    char* pAlo = pAhi + 16384;
    char* pBhi = pAlo + 16384;
    char* pBlo = pBhi + 16384;

    int tid = threadIdx.x;
    int wid = tid >> 5, lane = tid & 31;
    int warpM = wid & 3;        // 4 x 32 rows
    int warpN = wid >> 2;       // 2 x 64 cols
    int blockRow = blockIdx.y * 128;
    int blockCol = blockIdx.x * 128;

    if (tid < 128) {
        int gr = blockRow + tid; if (gr >= NTRI) gr = NTRI - 1;
        sIdxS[tid] = g_sidx[gr];
        oIdxS[tid] = g_oidx[gr];
    }
    __syncthreads();

    const __nv_bfloat16* objHi  = g_objHi[srcBuf];
    const __nv_bfloat16* objLo  = g_objLo[srcBuf];
    const __nv_bfloat16* predHi = g_predHi[srcBuf];
    const __nv_bfloat16* predLo = g_predLo[srcBuf];
    const __nv_bfloat16* WThi = g_WThi + (long)layer * N1 * K1;
    const __nv_bfloat16* WTlo = g_WTlo + (long)layer * N1 * K1;

    float acc[2][8][4];
    #pragma unroll
    for (int a = 0; a < 2; a++)
        #pragma unroll
        for (int b = 0; b < 8; b++)
            #pragma unroll
            for (int c = 0; c < 4; c++) acc[a][b][c] = 0.f;

    for (int ck = 0; ck < K1 / KCH; ck++) {
        int c0 = ck * KCH;
        // ---- fill 4 planes (each 128 rows x 128B = 1024 uint4) ----
        #pragma unroll
        for (int it = 0; it < 4; it++) {
            int idx = tid + it * 256;
            int row = idx >> 3, q = idx & 7;
            int gr = blockRow + row; if (gr >= NTRI) gr = NTRI - 1;
            const __nv_bfloat16 *srcH, *srcL;
            if (c0 < 256)      { long o = (long)sIdxS[row] * DD + c0;         srcH = objHi + o;  srcL = objLo + o; }
            else if (c0 < 512) { long o = (long)gr * DD + (c0 - 256);         srcH = predHi + o; srcL = predLo + o; }
            else               { long o = (long)oIdxS[row] * DD + (c0 - 512); srcH = objHi + o;  srcL = objLo + o; }
            uint32_t d = SW128((uint32_t)(row * 128 + q * 16));
            *(uint4*)(pAhi + d) = ((const uint4*)srcH)[q];
            *(uint4*)(pAlo + d) = ((const uint4*)srcL)[q];
            long bo = (long)(blockCol + row) * K1 + c0;
            *(uint4*)(pBhi + d) = ((const uint4*)(WThi + bo))[q];
            *(uint4*)(pBlo + d) = ((const uint4*)(WTlo + bo))[q];
        }
        __syncthreads();

        // ---- 4 k-steps of 16 ----
        #pragma unroll
        for (int ks = 0; ks < 4; ks++) {
            uint32_t ah[2][4], al[2][4];
            #pragma unroll
            for (int mt = 0; mt < 2; mt++) {
                int mrow = warpM * 32 + mt * 16 + (lane & 15);
                uint32_t cb = (uint32_t)(ks * 32) + ((lane >> 4) << 4);
                uint32_t ad = SW128((uint32_t)(mrow * 128) + cb);
                ldsm_x4(ah[mt][0], ah[mt][1], ah[mt][2], ah[mt][3], uAhi + ad);
                ldsm_x4(al[mt][0], al[mt][1], al[mt][2], al[mt][3], uAlo + ad);
            }
            #pragma unroll
            for (int np = 0; np < 4; np++) {
                int nrow = warpN * 64 + np * 16 + (lane & 7) + ((lane >> 4) << 3);
                uint32_t cb = (uint32_t)(ks * 32) + (((lane >> 3) & 1) << 4);
                uint32_t bd = SW128((uint32_t)(nrow * 128) + cb);
                uint32_t bh[4], bl[4];
                ldsm_x4(bh[0], bh[1], bh[2], bh[3], uBhi + bd);
                ldsm_x4(bl[0], bl[1], bl[2], bl[3], uBlo + bd);
                #pragma unroll
                for (int mt = 0; mt < 2; mt++)
                    #pragma unroll
                    for (int s = 0; s < 2; s++) {
                        float* c = acc[mt][np * 2 + s];
                        mma_16816(c, ah[mt], bh + s * 2);
                        mma_16816(c, ah[mt], bl + s * 2);
                        mma_16816(c, al[mt], bh + s * 2);
                    }
            }
        }
        __syncthreads();
    }

    // ---- stage C through SMEM (reuse plane space) ----
    float* Cs = (float*)pAhi;
    #pragma unroll
    for (int mt = 0; mt < 2; mt++)
        #pragma unroll
        for (int nt = 0; nt < 8; nt++) {
            int r0 = warpM * 32 + mt * 16 + (lane >> 2);
            int cc = warpN * 64 + nt * 8 + (lane & 3) * 2;
            float* c = acc[mt][nt];
            *(float2*)&Cs[r0 * 128 + cc]       = make_float2(c[0], c[1]);
            *(float2*)&Cs[(r0 + 8) * 128 + cc] = make_float2(c[2], c[3]);
        }
    __syncthreads();

    // ---- epilogue: bias + 3-way scatter (coalesced red.v4) ----
    const float* biasL = g_b12 + layer * N1;
    __nv_bfloat16* pHo = g_predHi[srcBuf ^ 1];
    __nv_bfloat16* pLo = g_predLo[srcBuf ^ 1];
    #pragma unroll
    for (int i = 0; i < 16; i++) {
        int f = tid + i * 256;          // 0..4095 float4s
        int row = f >> 5;
        int c4 = (f & 31) << 2;
        int gr = blockRow + row;
        if (gr >= NTRI) continue;
        int gc0 = blockCol + c4;
        float4 v = *(float4*)&Cs[row * 128 + c4];
        float4 bb = *(const float4*)&biasL[gc0];
        v.x += bb.x; v.y += bb.y; v.z += bb.z; v.w += bb.w;
        if (gc0 < HH) {
            red_add4(&g_pooled[(long)sIdxS[row] * HH + gc0], v.x, v.y, v.z, v.w);
        } else if (gc0 < HH + DD) {
            int pc = gc0 - HH;
            if (last) {
                *(float4*)&predExtOut[(long)gr * DD + pc] = v;
            } else {
                long o = (long)gr * DD + pc;
                uint32_t l01, l23;
                uint32_t h01 = pack_hi2(v.x, v.y, l01);
                uint32_t h23 = pack_hi2(v.z, v.w, l23);
                *(uint2*)(pHo + o) = make_uint2(h01, h23);
                *(uint2*)(pLo + o) = make_uint2(l01, l23);
            }
        } else {
            red_add4(&g_pooled[(long)oIdxS[row] * HH + (gc0 - HH - DD)], v.x, v.y, v.z, v.w);
        }
    }
}

// gemmB: obj' = (pooled*inv) @ W34 + b34   (M=NOBJ, N=256, K=512)
__global__ __launch_bounds__(256)
void gemmB_mma(int layer, int dstBuf, int last, float* __restrict__ objExtOut) {
    extern __shared__ char smem[];
    uint32_t raw  = smem_u32(smem);
    uint32_t base = (raw + 1023u) & ~1023u;
    char* pal = smem + (base - raw);
    const uint32_t uAhi = base + 1024;
    const uint32_t uAlo = uAhi + 16384;
    const uint32_t uBhi = uAlo + 16384;
    const uint32_t uBlo = uBhi + 16384;
    char* pAhi = pal + 1024;
    char* pAlo = pAhi + 16384;
    char* pBhi = pAlo + 16384;
    char* pBlo = pBhi + 16384;

    int tid = threadIdx.x;
    int wid = tid >> 5, lane = tid & 31;
    int warpM = wid & 3;
    int warpN = wid >> 2;
    int blockRow = blockIdx.y * 128;
    int blockCol = blockIdx.x * 128;

    const __nv_bfloat16* WThi = g_W34Thi + (long)layer * DD * HH;
    const __nv_bfloat16* WTlo = g_W34Tlo + (long)layer * DD * HH;

    float acc[2][8][4];
    #pragma unroll
    for (int a = 0; a < 2; a++)
        #pragma unroll
        for (int b = 0; b < 8; b++)
            #pragma unroll
            for (int c = 0; c < 4; c++) acc[a][b][c] = 0.f;

    for (int ck = 0; ck < HH / KCH; ck++) {
        int c0 = ck * KCH;
        #pragma unroll
        for (int it = 0; it < 4; it++) {
            int idx = tid + it * 256;
            int row = idx >> 3, q = idx & 7;
            int gr = blockRow + row; if (gr >= NOBJ) gr = NOBJ - 1;
            float inv = g_inv[gr];
            const float* src = g_pooled + (long)gr * HH + c0 + q * 8;
            float4 f0 = *(const float4*)src;
            float4 f1 = *(const float4*)(src + 4);
            uint4 hi, lo;
            hi.x = pack_hi2(f0.x * inv, f0.y * inv, lo.x);
            hi.y = pack_hi2(f0.z * inv, f0.w * inv, lo.y);
            hi.z = pack_hi2(f1.x * inv, f1.y * inv, lo.z);
            hi.w = pack_hi2(f1.z * inv, f1.w * inv, lo.w);
            uint32_t d = SW128((uint32_t)(row * 128 + q * 16));
            *(uint4*)(pAhi + d) = hi;
            *(uint4*)(pAlo + d) = lo;
            long bo = (long)(blockCol + row) * HH + c0;
            *(uint4*)(pBhi + d) = ((const uint4*)(WThi + bo))[q];
            *(uint4*)(pBlo + d) = ((const uint4*)(WTlo + bo))[q];
        }
        __syncthreads();

        #pragma unroll
        for (int ks = 0; ks < 4; ks++) {
            uint32_t ah[2][4], al[2][4];
            #pragma unroll
            for (int mt = 0; mt < 2; mt++) {
                int mrow = warpM * 32 + mt * 16 + (lane & 15);
                uint32_t cb = (uint32_t)(ks * 32) + ((lane >> 4) << 4);
                uint32_t ad = SW128((uint32_t)(mrow * 128) + cb);
                ldsm_x4(ah[mt][0], ah[mt][1], ah[mt][2], ah[mt][3], uAhi + ad);
                ldsm_x4(al[mt][0], al[mt][1], al[mt][2], al[mt][3], uAlo + ad);
            }
            #pragma unroll
            for (int np = 0; np < 4; np++) {
                int nrow = warpN * 64 + np * 16 + (lane & 7) + ((lane >> 4) << 3);
                uint32_t cb = (uint32_t)(ks * 32) + (((lane >> 3) & 1) << 4);
                uint32_t bd = SW128((uint32_t)(nrow * 128) + cb);
                uint32_t bh[4], bl[4];
                ldsm_x4(bh[0], bh[1], bh[2], bh[3], uBhi + bd);
                ldsm_x4(bl[0], bl[1], bl[2], bl[3], uBlo + bd);
                #pragma unroll
                for (int mt = 0; mt < 2; mt++)
                    #pragma unroll
                    for (int s = 0; s < 2; s++) {
                        float* c = acc[mt][np * 2 + s];
                        mma_16816(c, ah[mt], bh + s * 2);
                        mma_16816(c, ah[mt], bl + s * 2);
                        mma_16816(c, al[mt], bh + s * 2);
                    }
            }
        }
        __syncthreads();
    }

    float* Cs = (float*)pAhi;
    #pragma unroll
    for (int mt = 0; mt < 2; mt++)
        #pragma unroll
        for (int nt = 0; nt < 8; nt++) {
            int r0 = warpM * 32 + mt * 16 + (lane >> 2);
            int cc = warpN * 64 + nt * 8 + (lane & 3) * 2;
            float* c = acc[mt][nt];
            *(float2*)&Cs[r0 * 128 + cc]       = make_float2(c[0], c[1]);
            *(float2*)&Cs[(r0 + 8) * 128 + cc] = make_float2(c[2], c[3]);
        }
    __syncthreads();

    const float* biasL = g_b34 + layer * DD;
    __nv_bfloat16* oh = g_objHi[dstBuf];
    __nv_bfloat16* ol = g_objLo[dstBuf];
    #pragma unroll
    for (int i = 0; i < 16; i++) {
        int f = tid + i * 256;
        int row = f >> 5;
        int c4 = (f & 31) << 2;
        int gr = blockRow + row;
        if (gr >= NOBJ) continue;
        int gc0 = blockCol + c4;
        float4 v = *(float4*)&Cs[row * 128 + c4];
        float4 bb = *(const float4*)&biasL[gc0];
        v.x += bb.x; v.y += bb.y; v.z += bb.z; v.w += bb.w;
        if (last) {
            *(float4*)&objExtOut[(long)gr * DD + gc0] = v;
        } else {
            long o = (long)gr * DD + gc0;
            uint32_t l01, l23;
            uint32_t h01 = pack_hi2(v.x, v.y, l01);
            uint32_t h23 = pack_hi2(v.z, v.w, l23);
            *(uint2*)(oh + o) = make_uint2(h01, h23);
            *(uint2*)(ol + o) = make_uint2(l01, l23);
        }
    }
}

// ======================= launcher =======================
extern "C" void kernel_launch(void* const* d_in, const int* in_sizes, int n_in,
                              void* d_out, int out_size) {
    const float* obj_in  = (const float*)d_in[0];
    const float* pred_in = (const float*)d_in[1];
    const void*  edges   = d_in[2];
    const float* W1 = (const float*)d_in[3];
    const float* b1 = (const float*)d_in[4];
    const float* W2 = (const float*)d_in[5];
    const float* b2 = (const float*)d_in[6];
    const float* W3 = (const float*)d_in[7];
    const float* b3 = (const float*)d_in[8];
    const float* W4 = (const float*)d_in[9];
    const float* b4 = (const float*)d_in[10];

    float* out_obj  = (float*)d_out;                     // [20000, 256]
    float* out_pred = (float*)d_out + (long)NOBJ * DD;   // [60000, 256]

    static int attr_done = 0;
    if (!attr_done) {
        cudaFuncSetAttribute(gemmA_mma, cudaFuncAttributeMaxDynamicSharedMemorySize, MM_SMEM);
        cudaFuncSetAttribute(gemmB_mma, cudaFuncAttributeMaxDynamicSharedMemorySize, MM_SMEM);
        attr_done = 1;
    }

    // edge indices + counts
    zero_cnt_kernel<<<cdiv_h(NOBJ, 256), 256>>>();
    detect_kernel<<<1, 1>>>((const int*)edges);
    convert_kernel<<<cdiv_h(NTRI, 256), 256>>>(edges);
    inv_kernel<<<cdiv_h(NOBJ, 256), 256>>>();

    // composite weights + transposed hi/lo planes + biases
    sgemm_prep<<<dim3(N1 / 128, K1 / 128, LL), 256>>>(W1, W2, 0, K1, N1, HH);
    sgemm_prep<<<dim3(DD / 128, HH / 128, LL), 256>>>(W3, W4, 1, HH, DD, HH);
    bias12_kernel<<<dim3(cdiv_h(N1, 256), 1, LL), 256>>>(b1, W2, b2);
    bias34_kernel<<<dim3(cdiv_h(DD, 256), 1, LL), 256>>>(b3, W4, b4);
    transpose_split_kernel<<<dim3(K1 / 32, N1 / 32, LL), dim3(32, 8)>>>(0);
    transpose_split_kernel<<<dim3(HH / 32, DD / 32, LL), dim3(32, 8)>>>(1);

    // input activations -> hi/lo planes (buffer 0)
    cvt_obj_kernel<<<cdiv_h(NOBJ * DD, 256), 256>>>(obj_in);
    cvt_pred_kernel<<<cdiv_h(NTRI * DD, 256), 256>>>(pred_in);

    dim3 gridA(N1 / 128, cdiv_h(NTRI, 128));   // (10, 469)
    dim3 gridB(DD / 128, cdiv_h(NOBJ, 128));   // (2, 157)
    int zpBlocks = cdiv_h(NOBJ * HH / 4, 256);

    for (int l = 0; l < LL; l++) {
        int src = l & 1, dst = src ^ 1, last = (l == LL - 1);
        zero_pooled_kernel<<<zpBlocks, 256>>>();
        gemmA_mma<<<gridA, 256, MM_SMEM>>>(src, l, last, out_pred);
        gemmB_mma<<<gridB, 256, MM_SMEM>>>(l, dst, last, out_obj);
    }
}

// round 8
// speedup vs baseline: 2.4953x; 1.3502x over previous
#include <cuda_runtime.h>
#include <cuda_bf16.h>
#include <cstdint>

#define NOBJ 20000
#define NTRI 60000
#define DD   256
#define HH   512
#define LL   5
#define K1   768    // 3*D
#define N1   1280   // 2H+D
#define N13  2560   // 2*N1  (P13 = obj @ [Wa|Wc])
#define KCH  64     // K chunk per SMEM stage

static inline int cdiv_h(int a, int b) { return (a + b - 1) / b; }

// ======================= PTX helpers =======================
__device__ __forceinline__ uint32_t smem_u32(const void* p) {
    uint32_t a;
    asm("{ .reg .u64 t; cvta.to.shared.u64 t, %1; cvt.u32.u64 %0, t; }" : "=r"(a) : "l"(p));
    return a;
}
#define SW128(off) ((off) ^ (((off) >> 3) & 0x70))

__device__ __forceinline__ void ldsm_x4(uint32_t& r0, uint32_t& r1, uint32_t& r2, uint32_t& r3,
                                        uint32_t addr) {
    asm volatile("ldmatrix.sync.aligned.m8n8.x4.shared.b16 {%0,%1,%2,%3}, [%4];"
                 : "=r"(r0), "=r"(r1), "=r"(r2), "=r"(r3) : "r"(addr));
}
__device__ __forceinline__ void mma_16816(float* c, const uint32_t* a, const uint32_t* b) {
    asm volatile("mma.sync.aligned.m16n8k16.row.col.f32.bf16.bf16.f32 "
                 "{%0,%1,%2,%3}, {%4,%5,%6,%7}, {%8,%9}, {%0,%1,%2,%3};"
                 : "+f"(c[0]), "+f"(c[1]), "+f"(c[2]), "+f"(c[3])
                 : "r"(a[0]), "r"(a[1]), "r"(a[2]), "r"(a[3]), "r"(b[0]), "r"(b[1]));
}
__device__ __forceinline__ void red_add4(float* p, float a, float b, float c, float d) {
    asm volatile("red.global.add.v4.f32 [%0], {%1, %2, %3, %4};"
                 :: "l"(p), "f"(a), "f"(b), "f"(c), "f"(d) : "memory");
}
__device__ __forceinline__ void split_bf16(float x, __nv_bfloat16& h, __nv_bfloat16& l) {
    h = __float2bfloat16(x);
    l = __float2bfloat16(x - __bfloat162float(h));
}
__device__ __forceinline__ uint32_t pack_hi2(float a, float b, uint32_t& lo2) {
    __nv_bfloat16 ha, la, hb, lb;
    split_bf16(a, ha, la); split_bf16(b, hb, lb);
    __nv_bfloat162 H; H.x = ha; H.y = hb;
    __nv_bfloat162 L; L.x = la; L.y = lb;
    lo2 = *(uint32_t*)&L;
    return *(uint32_t*)&H;
}

// ======================= device globals (no allocation) =======================
__device__ __nv_bfloat16 g_objHi[2][NOBJ * DD];
__device__ __nv_bfloat16 g_objLo[2][NOBJ * DD];
__device__ __nv_bfloat16 g_predHi[2][NTRI * DD];
__device__ __nv_bfloat16 g_predLo[2][NTRI * DD];
__device__ __nv_bfloat16 g_WacThi[LL * N13 * DD];  // [l][n][k]  n<1280: Wa rows; n>=1280: Wc
__device__ __nv_bfloat16 g_WacTlo[LL * N13 * DD];
__device__ __nv_bfloat16 g_WbThi[LL * N1 * DD];    // [l][n][k]  Wb = W12 rows 256..511
__device__ __nv_bfloat16 g_WbTlo[LL * N1 * DD];
__device__ __nv_bfloat16 g_W34Thi[LL * DD * HH];   // [l][n][k]
__device__ __nv_bfloat16 g_W34Tlo[LL * DD * HH];
__device__ float g_P13[(long)NOBJ * N13];          // obj @ [Wa|Wc], fp32
__device__ float g_pooled[NOBJ * HH];
__device__ float g_W12[LL * K1 * N1];
__device__ float g_b12[LL * N1];
__device__ float g_W34[LL * HH * DD];
__device__ float g_b34[LL * DD];
__device__ int   g_sidx[NTRI];
__device__ int   g_oidx[NTRI];
__device__ int   g_cnt[NOBJ];
__device__ float g_inv[NOBJ];
__device__ int   g_is64;

// ======================= small utility kernels =======================
__global__ void zero_cnt_detect_kernel(const int* e) {
    int i = blockIdx.x * blockDim.x + threadIdx.x;
    if (i < NOBJ) g_cnt[i] = 0;
    if (i == 0) {
        int ok = 1;
        #pragma unroll
        for (int w = 1; w < 16; w += 2) ok &= (e[w] == 0);
        g_is64 = ok;
    }
}
__global__ void zero_pooled_kernel() {
    long i = (long)blockIdx.x * blockDim.x + threadIdx.x;
    float4* p = (float4*)g_pooled;
    if (i < (long)NOBJ * HH / 4) p[i] = make_float4(0.f, 0.f, 0.f, 0.f);
}
__global__ void convert_kernel(const void* edges) {
    int i = blockIdx.x * blockDim.x + threadIdx.x;
    if (i >= NTRI) return;
    int s, o;
    if (g_is64) {
        const long long* p = (const long long*)edges;
        s = (int)p[2 * i]; o = (int)p[2 * i + 1];
    } else {
        const int* p = (const int*)edges;
        s = p[2 * i]; o = p[2 * i + 1];
    }
    g_sidx[i] = s; g_oidx[i] = o;
    atomicAdd(&g_cnt[s], 1);
    atomicAdd(&g_cnt[o], 1);
}
__global__ void inv_kernel() {
    int i = blockIdx.x * blockDim.x + threadIdx.x;
    if (i < NOBJ) {
        int c = g_cnt[i];
        g_inv[i] = 1.0f / (float)(c > 0 ? c : 1);
    }
}
__global__ void cvt_obj_kernel(const float* __restrict__ src) {
    int i = blockIdx.x * blockDim.x + threadIdx.x;
    if (i < NOBJ * DD) {
        __nv_bfloat16 h, l; split_bf16(src[i], h, l);
        g_objHi[0][i] = h; g_objLo[0][i] = l;
    }
}
__global__ void cvt_pred_kernel(const float* __restrict__ src) {
    int i = blockIdx.x * blockDim.x + threadIdx.x;
    if (i < NTRI * DD) {
        __nv_bfloat16 h, l; split_bf16(src[i], h, l);
        g_predHi[0][i] = h; g_predLo[0][i] = l;
    }
}
__global__ void bias12_kernel(const float* __restrict__ b1, const float* __restrict__ W2,
                              const float* __restrict__ b2) {
    int l = blockIdx.z;
    int c = blockIdx.x * blockDim.x + threadIdx.x;
    if (c >= N1) return;
    const float* b1l = b1 + l * HH;
    const float* W2l = W2 + (long)l * HH * N1;
    float s = b2[(long)l * N1 + c];
    for (int k = 0; k < HH; k++) s = fmaf(b1l[k], W2l[(long)k * N1 + c], s);
    g_b12[l * N1 + c] = s;
}
__global__ void bias34_kernel(const float* __restrict__ b3, const float* __restrict__ W4,
                              const float* __restrict__ b4) {
    int l = blockIdx.z;
    int c = blockIdx.x * blockDim.x + threadIdx.x;
    if (c >= DD) return;
    const float* b3l = b3 + l * HH;
    const float* W4l = W4 + (long)l * HH * DD;
    float s = b4[(long)l * DD + c];
    for (int k = 0; k < HH; k++) s = fmaf(b3l[k], W4l[(long)k * DD + c], s);
    g_b34[l * DD + c] = s;
}

// transpose + hi/lo split: produce [n][k] bf16 planes from fp32 composites.
// mode 0: WacT (K=DD, N=N13) from W12 (n<N1: rows k; n>=N1: rows 512+k)
// mode 1: WbT  (K=DD, N=N1)  from W12 rows 256+k
// mode 2: W34T (K=HH, N=DD)  from W34
__global__ void transpose_split_kernel(int mode) {
    __shared__ float tile[32][33];
    int l = blockIdx.z;
    int K = (mode == 2) ? HH : DD;
    int N = (mode == 0) ? N13 : ((mode == 1) ? N1 : DD);
    __nv_bfloat16* Hp; __nv_bfloat16* Lp;
    if (mode == 0)      { Hp = g_WacThi + (long)l * N13 * DD; Lp = g_WacTlo + (long)l * N13 * DD; }
    else if (mode == 1) { Hp = g_WbThi  + (long)l * N1  * DD; Lp = g_WbTlo  + (long)l * N1  * DD; }
    else                { Hp = g_W34Thi + (long)l * DD  * HH; Lp = g_W34Tlo + (long)l * DD  * HH; }
    int k0 = blockIdx.x * 32;
    int n0 = blockIdx.y * 32;
    int tx = threadIdx.x, ty = threadIdx.y;
    #pragma unroll
    for (int i = 0; i < 32; i += 8) {
        int k = k0 + ty + i, n = n0 + tx;
        float v;
        if (mode == 0) {
            int ksrc = (n < N1) ? k : (512 + k);
            int nsrc = (n < N1) ? n : (n - N1);
            v = g_W12[(long)l * K1 * N1 + (long)ksrc * N1 + nsrc];
        } else if (mode == 1) {
            v = g_W12[(long)l * K1 * N1 + (long)(256 + k) * N1 + n];
        } else {
            v = g_W34[(long)l * HH * DD + (long)k * DD + n];
        }
        tile[ty + i][tx] = v;
    }
    __syncthreads();
    #pragma unroll
    for (int i = 0; i < 32; i += 8) {
        float v = tile[tx][ty + i];
        __nv_bfloat16 h, lo; split_bf16(v, h, lo);
        long o = (long)(n0 + ty + i) * K + k0 + tx;
        Hp[o] = h; Lp[o] = lo;
    }
}

// ---------------- weight-prep GEMM (fp32, once per replay) ----------------
__global__ __launch_bounds__(256, 2)
void sgemm_prep(const float* __restrict__ A, const float* __restrict__ B,
                int which, int M, int N, int K) {
    float* C = (which == 0) ? g_W12 : g_W34;
    long z = blockIdx.z;
    A += z * (long)M * K; B += z * (long)K * N; C += z * (long)M * N;
    __shared__ float As[16][128];
    __shared__ float Bs[16][128];
    int tid = threadIdx.x;
    int tx = tid & 15, ty = tid >> 4;
    int blockRow = blockIdx.y * 128, blockCol = blockIdx.x * 128;
    float acc[8][8];
    #pragma unroll
    for (int i = 0; i < 8; i++)
        #pragma unroll
        for (int j = 0; j < 8; j++) acc[i][j] = 0.f;
    int lr = tid >> 1, lc = (tid & 1) * 8;
    int br = tid >> 4, bc = (tid & 15) * 8;
    for (int k0 = 0; k0 < K; k0 += 16) {
        int gr = blockRow + lr;
        float4 a0, a1;
        if (gr < M) {
            const float* rp = A + (long)gr * K + k0;
            a0 = *(const float4*)(rp + lc); a1 = *(const float4*)(rp + lc + 4);
        } else { a0 = make_float4(0,0,0,0); a1 = a0; }
        As[lc+0][lr]=a0.x; As[lc+1][lr]=a0.y; As[lc+2][lr]=a0.z; As[lc+3][lr]=a0.w;
        As[lc+4][lr]=a1.x; As[lc+5][lr]=a1.y; As[lc+6][lr]=a1.z; As[lc+7][lr]=a1.w;
        const float* bp = B + (long)(k0 + br) * N + blockCol + bc;
        *(float4*)&Bs[br][bc]     = *(const float4*)bp;
        *(float4*)&Bs[br][bc + 4] = *(const float4*)(bp + 4);
        __syncthreads();
        #pragma unroll
        for (int k = 0; k < 16; k++) {
            float4 x0 = *(float4*)&As[k][ty * 8];
            float4 x1 = *(float4*)&As[k][ty * 8 + 4];
            float4 y0 = *(float4*)&Bs[k][tx * 8];
            float4 y1 = *(float4*)&Bs[k][tx * 8 + 4];
            float ra[8] = {x0.x,x0.y,x0.z,x0.w,x1.x,x1.y,x1.z,x1.w};
            float rb[8] = {y0.x,y0.y,y0.z,y0.w,y1.x,y1.y,y1.z,y1.w};
            #pragma unroll
            for (int i = 0; i < 8; i++)
                #pragma unroll
                for (int j = 0; j < 8; j++) acc[i][j] = fmaf(ra[i], rb[j], acc[i][j]);
        }
        __syncthreads();
    }
    #pragma unroll
    for (int i = 0; i < 8; i++) {
        int gr = blockRow + ty * 8 + i;
        if (gr >= M) continue;
        #pragma unroll
        for (int j = 0; j < 8; j++) {
            int gc = blockCol + tx * 8 + j;
            if (gc < N) C[(long)gr * N + gc] = acc[i][j];
        }
    }
}

// ======================= MMA core macros (validated round-6 mapping) =======================
#define MM_SMEM (1024 + 1024 + 4 * 16384)

#define MMA_COMPUTE_CHUNK()                                                          \
    _Pragma("unroll")                                                                \
    for (int ks = 0; ks < 4; ks++) {                                                 \
        uint32_t ah[2][4], al[2][4];                                                 \
        _Pragma("unroll")                                                            \
        for (int mt = 0; mt < 2; mt++) {                                             \
            int mrow = warpM * 32 + mt * 16 + (lane & 15);                           \
            uint32_t cb = (uint32_t)(ks * 32) + ((lane >> 4) << 4);                  \
            uint32_t ad = SW128((uint32_t)(mrow * 128) + cb);                        \
            ldsm_x4(ah[mt][0], ah[mt][1], ah[mt][2], ah[mt][3], uAhi + ad);          \
            ldsm_x4(al[mt][0], al[mt][1], al[mt][2], al[mt][3], uAlo + ad);          \
        }                                                                            \
        _Pragma("unroll")                                                            \
        for (int np = 0; np < 4; np++) {                                             \
            int nrow = warpN * 64 + np * 16 + (lane & 7) + ((lane >> 4) << 3);       \
            uint32_t cb = (uint32_t)(ks * 32) + (((lane >> 3) & 1) << 4);            \
            uint32_t bd = SW128((uint32_t)(nrow * 128) + cb);                        \
            uint32_t bh[4], bl[4];                                                   \
            ldsm_x4(bh[0], bh[1], bh[2], bh[3], uBhi + bd);                          \
            ldsm_x4(bl[0], bl[1], bl[2], bl[3], uBlo + bd);                          \
            _Pragma("unroll")                                                        \
            for (int mt = 0; mt < 2; mt++)                                           \
                _Pragma("unroll")                                                    \
                for (int s = 0; s < 2; s++) {                                        \
                    float* c = acc[mt][np * 2 + s];                                  \
                    mma_16816(c, ah[mt], bh + s * 2);                                \
                    mma_16816(c, ah[mt], bl + s * 2);                                \
                    mma_16816(c, al[mt], bh + s * 2);                                \
                }                                                                    \
        }                                                                            \
    }

#define MMA_STAGE_C()                                                                \
    _Pragma("unroll")                                                                \
    for (int mt = 0; mt < 2; mt++)                                                   \
        _Pragma("unroll")                                                            \
        for (int nt = 0; nt < 8; nt++) {                                             \
            int r0 = warpM * 32 + mt * 16 + (lane >> 2);                             \
            int cc = warpN * 64 + nt * 8 + (lane & 3) * 2;                           \
            float* c = acc[mt][nt];                                                  \
            *(float2*)&Cs[r0 * 128 + cc]       = make_float2(c[0], c[1]);            \
            *(float2*)&Cs[(r0 + 8) * 128 + cc] = make_float2(c[2], c[3]);            \
        }

// ================ gemmP13: P13 = obj @ [Wa|Wc]   (M=NOBJ, N=2560, K=256) ================
__global__ __launch_bounds__(256)
void gemmP13(int srcBuf, int layer) {
    extern __shared__ char smem[];
    uint32_t raw  = smem_u32(smem);
    uint32_t base = (raw + 1023u) & ~1023u;
    char* pal = smem + (base - raw);
    const uint32_t uAhi = base + 1024;
    const uint32_t uAlo = uAhi + 16384;
    const uint32_t uBhi = uAlo + 16384;
    const uint32_t uBlo = uBhi + 16384;
    char* pAhi = pal + 1024;
    char* pAlo = pAhi + 16384;
    char* pBhi = pAlo + 16384;
    char* pBlo = pBhi + 16384;

    int tid = threadIdx.x;
    int wid = tid >> 5, lane = tid & 31;
    int warpM = wid & 3, warpN = wid >> 2;
    int blockRow = blockIdx.y * 128;
    int blockCol = blockIdx.x * 128;

    const __nv_bfloat16* objHi = g_objHi[srcBuf];
    const __nv_bfloat16* objLo = g_objLo[srcBuf];
    const __nv_bfloat16* WThi = g_WacThi + (long)layer * N13 * DD;
    const __nv_bfloat16* WTlo = g_WacTlo + (long)layer * N13 * DD;

    float acc[2][8][4];
    #pragma unroll
    for (int a = 0; a < 2; a++)
        #pragma unroll
        for (int b = 0; b < 8; b++)
            #pragma unroll
            for (int c = 0; c < 4; c++) acc[a][b][c] = 0.f;

    for (int ck = 0; ck < DD / KCH; ck++) {
        int c0 = ck * KCH;
        #pragma unroll
        for (int it = 0; it < 4; it++) {
            int idx = tid + it * 256;
            int row = idx >> 3, q = idx & 7;
            int gr = blockRow + row; if (gr >= NOBJ) gr = NOBJ - 1;
            long ao = (long)gr * DD + c0;
            uint32_t d = SW128((uint32_t)(row * 128 + q * 16));
            *(uint4*)(pAhi + d) = ((const uint4*)(objHi + ao))[q];
            *(uint4*)(pAlo + d) = ((const uint4*)(objLo + ao))[q];
            long bo = (long)(blockCol + row) * DD + c0;
            *(uint4*)(pBhi + d) = ((const uint4*)(WThi + bo))[q];
            *(uint4*)(pBlo + d) = ((const uint4*)(WTlo + bo))[q];
        }
        __syncthreads();
        MMA_COMPUTE_CHUNK();
        __syncthreads();
    }

    float* Cs = (float*)pAhi;
    MMA_STAGE_C();
    __syncthreads();

    #pragma unroll
    for (int i = 0; i < 16; i++) {
        int f = tid + i * 256;
        int row = f >> 5;
        int c4 = (f & 31) << 2;
        int gr = blockRow + row;
        if (gr >= NOBJ) continue;
        *(float4*)&g_P13[(long)gr * N13 + blockCol + c4] = *(float4*)&Cs[row * 128 + c4];
    }
}

// ========== gemmP2: new_t = pred@Wb + P13[s] + P13[o,+N1] + b12, fused scatter ==========
__global__ __launch_bounds__(256)
void gemmP2(int srcBuf, int layer, int last, float* __restrict__ predExtOut) {
    extern __shared__ char smem[];
    uint32_t raw  = smem_u32(smem);
    uint32_t base = (raw + 1023u) & ~1023u;
    char* pal = smem + (base - raw);
    int* sIdxS = (int*)(pal);
    int* oIdxS = (int*)(pal + 512);
    const uint32_t uAhi = base + 1024;
    const uint32_t uAlo = uAhi + 16384;
    const uint32_t uBhi = uAlo + 16384;
    const uint32_t uBlo = uBhi + 16384;
    char* pAhi = pal + 1024;
    char* pAlo = pAhi + 16384;
    char* pBhi = pAlo + 16384;
    char* pBlo = pBhi + 16384;

    int tid = threadIdx.x;
    int wid = tid >> 5, lane = tid & 31;
    int warpM = wid & 3, warpN = wid >> 2;
    int blockRow = blockIdx.y * 128;
    int blockCol = blockIdx.x * 128;

    if (tid < 128) {
        int gr = blockRow + tid; if (gr >= NTRI) gr = NTRI - 1;
        sIdxS[tid] = g_sidx[gr];
        oIdxS[tid] = g_oidx[gr];
    }
    __syncthreads();

    const __nv_bfloat16* predHi = g_predHi[srcBuf];
    const __nv_bfloat16* predLo = g_predLo[srcBuf];
    const __nv_bfloat16* WThi = g_WbThi + (long)layer * N1 * DD;
    const __nv_bfloat16* WTlo = g_WbTlo + (long)layer * N1 * DD;

    float acc[2][8][4];
    #pragma unroll
    for (int a = 0; a < 2; a++)
        #pragma unroll
        for (int b = 0; b < 8; b++)
            #pragma unroll
            for (int c = 0; c < 4; c++) acc[a][b][c] = 0.f;

    for (int ck = 0; ck < DD / KCH; ck++) {
        int c0 = ck * KCH;
        #pragma unroll
        for (int it = 0; it < 4; it++) {
            int idx = tid + it * 256;
            int row = idx >> 3, q = idx & 7;
            int gr = blockRow + row; if (gr >= NTRI) gr = NTRI - 1;
            long ao = (long)gr * DD + c0;
            uint32_t d = SW128((uint32_t)(row * 128 + q * 16));
            *(uint4*)(pAhi + d) = ((const uint4*)(predHi + ao))[q];
            *(uint4*)(pAlo + d) = ((const uint4*)(predLo + ao))[q];
            long bo = (long)(blockCol + row) * DD + c0;
            *(uint4*)(pBhi + d) = ((const uint4*)(WThi + bo))[q];
            *(uint4*)(pBlo + d) = ((const uint4*)(WTlo + bo))[q];
        }
        __syncthreads();
        MMA_COMPUTE_CHUNK();
        __syncthreads();
    }

    float* Cs = (float*)pAhi;
    MMA_STAGE_C();
    __syncthreads();

    const float* biasL = g_b12 + layer * N1;
    __nv_bfloat16* pHo = g_predHi[srcBuf ^ 1];
    __nv_bfloat16* pLo = g_predLo[srcBuf ^ 1];
    #pragma unroll
    for (int i = 0; i < 16; i++) {
        int f = tid + i * 256;
        int row = f >> 5;
        int c4 = (f & 31) << 2;
        int gr = blockRow + row;
        if (gr >= NTRI) continue;
        int sI = sIdxS[row], oI = oIdxS[row];
        int gc0 = blockCol + c4;
        float4 v  = *(float4*)&Cs[row * 128 + c4];
        float4 bb = *(const float4*)&biasL[gc0];
        float4 ps = *(const float4*)&g_P13[(long)sI * N13 + gc0];
        float4 po = *(const float4*)&g_P13[(long)oI * N13 + N1 + gc0];
        v.x += bb.x + ps.x + po.x;
        v.y += bb.y + ps.y + po.y;
        v.z += bb.z + ps.z + po.z;
        v.w += bb.w + ps.w + po.w;
        if (gc0 < HH) {
            red_add4(&g_pooled[(long)sI * HH + gc0], v.x, v.y, v.z, v.w);
        } else if (gc0 < HH + DD) {
            int pc = gc0 - HH;
            if (last) {
                *(float4*)&predExtOut[(long)gr * DD + pc] = v;
            } else {
                long o = (long)gr * DD + pc;
                uint32_t l01, l23;
                uint32_t h01 = pack_hi2(v.x, v.y, l01);
                uint32_t h23 = pack_hi2(v.z, v.w, l23);
                *(uint2*)(pHo + o) = make_uint2(h01, h23);
                *(uint2*)(pLo + o) = make_uint2(l01, l23);
            }
        } else {
            red_add4(&g_pooled[(long)oI * HH + (gc0 - HH - DD)], v.x, v.y, v.z, v.w);
        }
    }
}

// ================ gemmB: obj' = (pooled*inv) @ W34 + b34   (K=512) ================
__global__ __launch_bounds__(256)
void gemmB_mma(int layer, int dstBuf, int last, float* __restrict__ objExtOut) {
    extern __shared__ char smem[];
    uint32_t raw  = smem_u32(smem);
    uint32_t base = (raw + 1023u) & ~1023u;
    char* pal = smem + (base - raw);
    const uint32_t uAhi = base + 1024;
    const uint32_t uAlo = uAhi + 16384;
    const uint32_t uBhi = uAlo + 16384;
    const uint32_t uBlo = uBhi + 16384;
    char* pAhi = pal + 1024;
    char* pAlo = pAhi + 16384;
    char* pBhi = pAlo + 16384;
    char* pBlo = pBhi + 16384;

    int tid = threadIdx.x;
    int wid = tid >> 5, lane = tid & 31;
    int warpM = wid & 3, warpN = wid >> 2;
    int blockRow = blockIdx.y * 128;
    int blockCol = blockIdx.x * 128;

    const __nv_bfloat16* WThi = g_W34Thi + (long)layer * DD * HH;
    const __nv_bfloat16* WTlo = g_W34Tlo + (long)layer * DD * HH;

    float acc[2][8][4];
    #pragma unroll
    for (int a = 0; a < 2; a++)
        #pragma unroll
        for (int b = 0; b < 8; b++)
            #pragma unroll
            for (int c = 0; c < 4; c++) acc[a][b][c] = 0.f;

    for (int ck = 0; ck < HH / KCH; ck++) {
        int c0 = ck * KCH;
        #pragma unroll
        for (int it = 0; it < 4; it++) {
            int idx = tid + it * 256;
            int row = idx >> 3, q = idx & 7;
            int gr = blockRow + row; if (gr >= NOBJ) gr = NOBJ - 1;
            float inv = g_inv[gr];
            const float* src = g_pooled + (long)gr * HH + c0 + q * 8;
            float4 f0 = *(const float4*)src;
            float4 f1 = *(const float4*)(src + 4);
            uint4 hi, lo;
            hi.x = pack_hi2(f0.x * inv, f0.y * inv, lo.x);
            hi.y = pack_hi2(f0.z * inv, f0.w * inv, lo.y);
            hi.z = pack_hi2(f1.x * inv, f1.y * inv, lo.z);
            hi.w = pack_hi2(f1.z * inv, f1.w * inv, lo.w);
            uint32_t d = SW128((uint32_t)(row * 128 + q * 16));
            *(uint4*)(pAhi + d) = hi;
            *(uint4*)(pAlo + d) = lo;
            long bo = (long)(blockCol + row) * HH + c0;
            *(uint4*)(pBhi + d) = ((const uint4*)(WThi + bo))[q];
            *(uint4*)(pBlo + d) = ((const uint4*)(WTlo + bo))[q];
        }
        __syncthreads();
        MMA_COMPUTE_CHUNK();
        __syncthreads();
    }

    float* Cs = (float*)pAhi;
    MMA_STAGE_C();
    __syncthreads();

    const float* biasL = g_b34 + layer * DD;
    __nv_bfloat16* oh = g_objHi[dstBuf];
    __nv_bfloat16* ol = g_objLo[dstBuf];
    #pragma unroll
    for (int i = 0; i < 16; i++) {
        int f = tid + i * 256;
        int row = f >> 5;
        int c4 = (f & 31) << 2;
        int gr = blockRow + row;
        if (gr >= NOBJ) continue;
        int gc0 = blockCol + c4;
        float4 v = *(float4*)&Cs[row * 128 + c4];
        float4 bb = *(const float4*)&biasL[gc0];
        v.x += bb.x; v.y += bb.y; v.z += bb.z; v.w += bb.w;
        if (last) {
            *(float4*)&objExtOut[(long)gr * DD + gc0] = v;
        } else {
            long o = (long)gr * DD + gc0;
            uint32_t l01, l23;
            uint32_t h01 = pack_hi2(v.x, v.y, l01);
            uint32_t h23 = pack_hi2(v.z, v.w, l23);
            *(uint2*)(oh + o) = make_uint2(h01, h23);
            *(uint2*)(ol + o) = make_uint2(l01, l23);
        }
    }
}

// ======================= launcher =======================
extern "C" void kernel_launch(void* const* d_in, const int* in_sizes, int n_in,
                              void* d_out, int out_size) {
    const float* obj_in  = (const float*)d_in[0];
    const float* pred_in = (const float*)d_in[1];
    const void*  edges   = d_in[2];
    const float* W1 = (const float*)d_in[3];
    const float* b1 = (const float*)d_in[4];
    const float* W2 = (const float*)d_in[5];
    const float* b2 = (const float*)d_in[6];
    const float* W3 = (const float*)d_in[7];
    const float* b3 = (const float*)d_in[8];
    const float* W4 = (const float*)d_in[9];
    const float* b4 = (const float*)d_in[10];

    float* out_obj  = (float*)d_out;                     // [20000, 256]
    float* out_pred = (float*)d_out + (long)NOBJ * DD;   // [60000, 256]

    static int attr_done = 0;
    if (!attr_done) {
        cudaFuncSetAttribute(gemmP13,  cudaFuncAttributeMaxDynamicSharedMemorySize, MM_SMEM);
        cudaFuncSetAttribute(gemmP2,   cudaFuncAttributeMaxDynamicSharedMemorySize, MM_SMEM);
        cudaFuncSetAttribute(gemmB_mma, cudaFuncAttributeMaxDynamicSharedMemorySize, MM_SMEM);
        attr_done = 1;
    }

    // edges
    zero_cnt_detect_kernel<<<cdiv_h(NOBJ, 256), 256>>>((const int*)edges);
    convert_kernel<<<cdiv_h(NTRI, 256), 256>>>(edges);
    inv_kernel<<<cdiv_h(NOBJ, 256), 256>>>();

    // composite weights + biases + bf16 planes
    sgemm_prep<<<dim3(N1 / 128, K1 / 128, LL), 256>>>(W1, W2, 0, K1, N1, HH);
    sgemm_prep<<<dim3(DD / 128, HH / 128, LL), 256>>>(W3, W4, 1, HH, DD, HH);
    bias12_kernel<<<dim3(cdiv_h(N1, 256), 1, LL), 256>>>(b1, W2, b2);
    bias34_kernel<<<dim3(cdiv_h(DD, 256), 1, LL), 256>>>(b3, W4, b4);
    transpose_split_kernel<<<dim3(DD / 32, N13 / 32, LL), dim3(32, 8)>>>(0);
    transpose_split_kernel<<<dim3(DD / 32, N1 / 32, LL), dim3(32, 8)>>>(1);
    transpose_split_kernel<<<dim3(HH / 32, DD / 32, LL), dim3(32, 8)>>>(2);

    // input activations -> hi/lo planes (buffer 0)
    cvt_obj_kernel<<<cdiv_h(NOBJ * DD, 256), 256>>>(obj_in);
    cvt_pred_kernel<<<cdiv_h(NTRI * DD, 256), 256>>>(pred_in);

    dim3 gridP13(N13 / 128, cdiv_h(NOBJ, 128));  // (20, 157)
    dim3 gridP2(N1 / 128, cdiv_h(NTRI, 128));    // (10, 469)
    dim3 gridB(DD / 128, cdiv_h(NOBJ, 128));     // (2, 157)
    int zpBlocks = cdiv_h(NOBJ * HH / 4, 256);

    for (int l = 0; l < LL; l++) {
        int src = l & 1, dst = src ^ 1, last = (l == LL - 1);
        zero_pooled_kernel<<<zpBlocks, 256>>>();
        gemmP13<<<gridP13, 256, MM_SMEM>>>(src, l);
        gemmP2<<<gridP2, 256, MM_SMEM>>>(src, l, last, out_pred);
        gemmB_mma<<<gridB, 256, MM_SMEM>>>(l, dst, last, out_obj);
    }
}

// round 9
// speedup vs baseline: 2.9710x; 1.1906x over previous
#include <cuda_runtime.h>
#include <cuda_bf16.h>
#include <cstdint>

#define NOBJ 20000
#define NTRI 60000
#define DD   256
#define HH   512
#define LL   5
#define K1   768    // 3*D
#define N1   1280   // 2H+D
#define N13  2560   // 2*N1  (P13 = obj @ [Wa|Wc])
#define KCH  64     // K chunk per SMEM stage

static inline int cdiv_h(int a, int b) { return (a + b - 1) / b; }

// ======================= PTX helpers =======================
__device__ __forceinline__ uint32_t smem_u32(const void* p) {
    uint32_t a;
    asm("{ .reg .u64 t; cvta.to.shared.u64 t, %1; cvt.u32.u64 %0, t; }" : "=r"(a) : "l"(p));
    return a;
}
#define SW128(off) ((off) ^ (((off) >> 3) & 0x70))

__device__ __forceinline__ void ldsm_x4(uint32_t& r0, uint32_t& r1, uint32_t& r2, uint32_t& r3,
                                        uint32_t addr) {
    asm volatile("ldmatrix.sync.aligned.m8n8.x4.shared.b16 {%0,%1,%2,%3}, [%4];"
                 : "=r"(r0), "=r"(r1), "=r"(r2), "=r"(r3) : "r"(addr));
}
__device__ __forceinline__ void mma_16816(float* c, const uint32_t* a, const uint32_t* b) {
    asm volatile("mma.sync.aligned.m16n8k16.row.col.f32.bf16.bf16.f32 "
                 "{%0,%1,%2,%3}, {%4,%5,%6,%7}, {%8,%9}, {%0,%1,%2,%3};"
                 : "+f"(c[0]), "+f"(c[1]), "+f"(c[2]), "+f"(c[3])
                 : "r"(a[0]), "r"(a[1]), "r"(a[2]), "r"(a[3]), "r"(b[0]), "r"(b[1]));
}
__device__ __forceinline__ void red_add4(float* p, float a, float b, float c, float d) {
    asm volatile("red.global.add.v4.f32 [%0], {%1, %2, %3, %4};"
                 :: "l"(p), "f"(a), "f"(b), "f"(c), "f"(d) : "memory");
}
__device__ __forceinline__ void cp_async16(uint32_t s, const void* g) {
    asm volatile("cp.async.cg.shared.global [%0], [%1], 16;" :: "r"(s), "l"(g));
}
#define CP_COMMIT() asm volatile("cp.async.commit_group;" ::: "memory")
#define CP_WAIT1()  asm volatile("cp.async.wait_group 1;" ::: "memory")
#define CP_WAIT0()  asm volatile("cp.async.wait_group 0;" ::: "memory")

__device__ __forceinline__ void split_bf16(float x, __nv_bfloat16& h, __nv_bfloat16& l) {
    h = __float2bfloat16(x);
    l = __float2bfloat16(x - __bfloat162float(h));
}
__device__ __forceinline__ uint32_t pack_hi2(float a, float b, uint32_t& lo2) {
    __nv_bfloat16 ha, la, hb, lb;
    split_bf16(a, ha, la); split_bf16(b, hb, lb);
    __nv_bfloat162 H; H.x = ha; H.y = hb;
    __nv_bfloat162 L; L.x = la; L.y = lb;
    lo2 = *(uint32_t*)&L;
    return *(uint32_t*)&H;
}

// ======================= device globals (no allocation) =======================
__device__ __nv_bfloat16 g_objHi[2][NOBJ * DD];
__device__ __nv_bfloat16 g_objLo[2][NOBJ * DD];
__device__ __nv_bfloat16 g_predHi[2][NTRI * DD];
__device__ __nv_bfloat16 g_predLo[2][NTRI * DD];
__device__ __nv_bfloat16 g_WacThi[LL * N13 * DD];  // [l][n][k]  n<1280: Wa rows; n>=1280: Wc
__device__ __nv_bfloat16 g_WacTlo[LL * N13 * DD];
__device__ __nv_bfloat16 g_WbThi[LL * N1 * DD];    // [l][n][k]  Wb = W12 rows 256..511
__device__ __nv_bfloat16 g_WbTlo[LL * N1 * DD];
__device__ __nv_bfloat16 g_W34Thi[LL * DD * HH];   // [l][n][k]
__device__ __nv_bfloat16 g_W34Tlo[LL * DD * HH];
__device__ float g_P13[(long)NOBJ * N13];          // obj @ [Wa|Wc], fp32
__device__ float g_pooled[NOBJ * HH];
__device__ float g_W12[LL * K1 * N1];
__device__ float g_b12[LL * N1];
__device__ float g_W34[LL * HH * DD];
__device__ float g_b34[LL * DD];
__device__ int   g_sidx[NTRI];
__device__ int   g_oidx[NTRI];
__device__ int   g_cnt[NOBJ];
__device__ float g_inv[NOBJ];
__device__ int   g_is64;

// ======================= small utility kernels =======================
__global__ void zero_cnt_detect_kernel(const int* e) {
    int i = blockIdx.x * blockDim.x + threadIdx.x;
    if (i < NOBJ) g_cnt[i] = 0;
    if (i == 0) {
        int ok = 1;
        #pragma unroll
        for (int w = 1; w < 16; w += 2) ok &= (e[w] == 0);
        g_is64 = ok;
    }
}
__global__ void zero_pooled_kernel() {
    long i = (long)blockIdx.x * blockDim.x + threadIdx.x;
    float4* p = (float4*)g_pooled;
    if (i < (long)NOBJ * HH / 4) p[i] = make_float4(0.f, 0.f, 0.f, 0.f);
}
__global__ void convert_kernel(const void* edges) {
    int i = blockIdx.x * blockDim.x + threadIdx.x;
    if (i >= NTRI) return;
    int s, o;
    if (g_is64) {
        const long long* p = (const long long*)edges;
        s = (int)p[2 * i]; o = (int)p[2 * i + 1];
    } else {
        const int* p = (const int*)edges;
        s = p[2 * i]; o = p[2 * i + 1];
    }
    g_sidx[i] = s; g_oidx[i] = o;
    atomicAdd(&g_cnt[s], 1);
    atomicAdd(&g_cnt[o], 1);
}
__global__ void inv_kernel() {
    int i = blockIdx.x * blockDim.x + threadIdx.x;
    if (i < NOBJ) {
        int c = g_cnt[i];
        g_inv[i] = 1.0f / (float)(c > 0 ? c : 1);
    }
}
__global__ void cvt_obj_kernel(const float* __restrict__ src) {
    int i = blockIdx.x * blockDim.x + threadIdx.x;
    if (i < NOBJ * DD) {
        __nv_bfloat16 h, l; split_bf16(src[i], h, l);
        g_objHi[0][i] = h; g_objLo[0][i] = l;
    }
}
__global__ void cvt_pred_kernel(const float* __restrict__ src) {
    int i = blockIdx.x * blockDim.x + threadIdx.x;
    if (i < NTRI * DD) {
        __nv_bfloat16 h, l; split_bf16(src[i], h, l);
        g_predHi[0][i] = h; g_predLo[0][i] = l;
    }
}
__global__ void bias12_kernel(const float* __restrict__ b1, const float* __restrict__ W2,
                              const float* __restrict__ b2) {
    int l = blockIdx.z;
    int c = blockIdx.x * blockDim.x + threadIdx.x;
    if (c >= N1) return;
    const float* b1l = b1 + l * HH;
    const float* W2l = W2 + (long)l * HH * N1;
    float s = b2[(long)l * N1 + c];
    for (int k = 0; k < HH; k++) s = fmaf(b1l[k], W2l[(long)k * N1 + c], s);
    g_b12[l * N1 + c] = s;
}
__global__ void bias34_kernel(const float* __restrict__ b3, const float* __restrict__ W4,
                              const float* __restrict__ b4) {
    int l = blockIdx.z;
    int c = blockIdx.x * blockDim.x + threadIdx.x;
    if (c >= DD) return;
    const float* b3l = b3 + l * HH;
    const float* W4l = W4 + (long)l * HH * DD;
    float s = b4[(long)l * DD + c];
    for (int k = 0; k < HH; k++) s = fmaf(b3l[k], W4l[(long)k * DD + c], s);
    g_b34[l * DD + c] = s;
}

// transpose + hi/lo split: produce [n][k] bf16 planes from fp32 composites.
// mode 0: WacT (K=DD, N=N13) from W12 (n<N1: rows k; n>=N1: rows 512+k)
// mode 1: WbT  (K=DD, N=N1)  from W12 rows 256+k
// mode 2: W34T (K=HH, N=DD)  from W34
__global__ void transpose_split_kernel(int mode) {
    __shared__ float tile[32][33];
    int l = blockIdx.z;
    int K = (mode == 2) ? HH : DD;
    __nv_bfloat16* Hp; __nv_bfloat16* Lp;
    if (mode == 0)      { Hp = g_WacThi + (long)l * N13 * DD; Lp = g_WacTlo + (long)l * N13 * DD; }
    else if (mode == 1) { Hp = g_WbThi  + (long)l * N1  * DD; Lp = g_WbTlo  + (long)l * N1  * DD; }
    else                { Hp = g_W34Thi + (long)l * DD  * HH; Lp = g_W34Tlo + (long)l * DD  * HH; }
    int k0 = blockIdx.x * 32;
    int n0 = blockIdx.y * 32;
    int tx = threadIdx.x, ty = threadIdx.y;
    #pragma unroll
    for (int i = 0; i < 32; i += 8) {
        int k = k0 + ty + i, n = n0 + tx;
        float v;
        if (mode == 0) {
            int ksrc = (n < N1) ? k : (512 + k);
            int nsrc = (n < N1) ? n : (n - N1);
            v = g_W12[(long)l * K1 * N1 + (long)ksrc * N1 + nsrc];
        } else if (mode == 1) {
            v = g_W12[(long)l * K1 * N1 + (long)(256 + k) * N1 + n];
        } else {
            v = g_W34[(long)l * HH * DD + (long)k * DD + n];
        }
        tile[ty + i][tx] = v;
    }
    __syncthreads();
    #pragma unroll
    for (int i = 0; i < 32; i += 8) {
        float v = tile[tx][ty + i];
        __nv_bfloat16 h, lo; split_bf16(v, h, lo);
        long o = (long)(n0 + ty + i) * K + k0 + tx;
        Hp[o] = h; Lp[o] = lo;
    }
}

// ---------------- weight-prep GEMM (fp32, once per replay) ----------------
__global__ __launch_bounds__(256, 2)
void sgemm_prep(const float* __restrict__ A, const float* __restrict__ B,
                int which, int M, int N, int K) {
    float* C = (which == 0) ? g_W12 : g_W34;
    long z = blockIdx.z;
    A += z * (long)M * K; B += z * (long)K * N; C += z * (long)M * N;
    __shared__ float As[16][128];
    __shared__ float Bs[16][128];
    int tid = threadIdx.x;
    int tx = tid & 15, ty = tid >> 4;
    int blockRow = blockIdx.y * 128, blockCol = blockIdx.x * 128;
    float acc[8][8];
    #pragma unroll
    for (int i = 0; i < 8; i++)
        #pragma unroll
        for (int j = 0; j < 8; j++) acc[i][j] = 0.f;
    int lr = tid >> 1, lc = (tid & 1) * 8;
    int br = tid >> 4, bc = (tid & 15) * 8;
    for (int k0 = 0; k0 < K; k0 += 16) {
        int gr = blockRow + lr;
        float4 a0, a1;
        if (gr < M) {
            const float* rp = A + (long)gr * K + k0;
            a0 = *(const float4*)(rp + lc); a1 = *(const float4*)(rp + lc + 4);
        } else { a0 = make_float4(0,0,0,0); a1 = a0; }
        As[lc+0][lr]=a0.x; As[lc+1][lr]=a0.y; As[lc+2][lr]=a0.z; As[lc+3][lr]=a0.w;
        As[lc+4][lr]=a1.x; As[lc+5][lr]=a1.y; As[lc+6][lr]=a1.z; As[lc+7][lr]=a1.w;
        const float* bp = B + (long)(k0 + br) * N + blockCol + bc;
        *(float4*)&Bs[br][bc]     = *(const float4*)bp;
        *(float4*)&Bs[br][bc + 4] = *(const float4*)(bp + 4);
        __syncthreads();
        #pragma unroll
        for (int k = 0; k < 16; k++) {
            float4 x0 = *(float4*)&As[k][ty * 8];
            float4 x1 = *(float4*)&As[k][ty * 8 + 4];
            float4 y0 = *(float4*)&Bs[k][tx * 8];
            float4 y1 = *(float4*)&Bs[k][tx * 8 + 4];
            float ra[8] = {x0.x,x0.y,x0.z,x0.w,x1.x,x1.y,x1.z,x1.w};
            float rb[8] = {y0.x,y0.y,y0.z,y0.w,y1.x,y1.y,y1.z,y1.w};
            #pragma unroll
            for (int i = 0; i < 8; i++)
                #pragma unroll
                for (int j = 0; j < 8; j++) acc[i][j] = fmaf(ra[i], rb[j], acc[i][j]);
        }
        __syncthreads();
    }
    #pragma unroll
    for (int i = 0; i < 8; i++) {
        int gr = blockRow + ty * 8 + i;
        if (gr >= M) continue;
        #pragma unroll
        for (int j = 0; j < 8; j++) {
            int gc = blockCol + tx * 8 + j;
            if (gc < N) C[(long)gr * N + gc] = acc[i][j];
        }
    }
}

// ======================= MMA core macros (validated round-6/8 mapping) =======================
#define MM_SMEM  (1024 + 1024 + 4 * 16384)          // gemmB (single stage)
#define MM_SMEMP (1024 + 1024 + 2 * 4 * 16384)      // pipelined kernels: 2 stages of 64KB

#define MMA_COMPUTE_CHUNK()                                                          \
    _Pragma("unroll")                                                                \
    for (int ks = 0; ks < 4; ks++) {                                                 \
        uint32_t ah[2][4], al[2][4];                                                 \
        _Pragma("unroll")                                                            \
        for (int mt = 0; mt < 2; mt++) {                                             \
            int mrow = warpM * 32 + mt * 16 + (lane & 15);                           \
            uint32_t cb = (uint32_t)(ks * 32) + ((lane >> 4) << 4);                  \
            uint32_t ad = SW128((uint32_t)(mrow * 128) + cb);                        \
            ldsm_x4(ah[mt][0], ah[mt][1], ah[mt][2], ah[mt][3], uAhi + ad);          \
            ldsm_x4(al[mt][0], al[mt][1], al[mt][2], al[mt][3], uAlo + ad);          \
        }                                                                            \
        _Pragma("unroll")                                                            \
        for (int np = 0; np < 4; np++) {                                             \
            int nrow = warpN * 64 + np * 16 + (lane & 7) + ((lane >> 4) << 3);       \
            uint32_t cb = (uint32_t)(ks * 32) + (((lane >> 3) & 1) << 4);            \
            uint32_t bd = SW128((uint32_t)(nrow * 128) + cb);                        \
            uint32_t bh[4], bl[4];                                                   \
            ldsm_x4(bh[0], bh[1], bh[2], bh[3], uBhi + bd);                          \
            ldsm_x4(bl[0], bl[1], bl[2], bl[3], uBlo + bd);                          \
            _Pragma("unroll")                                                        \
            for (int mt = 0; mt < 2; mt++)                                           \
                _Pragma("unroll")                                                    \
                for (int s = 0; s < 2; s++) {                                        \
                    float* c = acc[mt][np * 2 + s];                                  \
                    mma_16816(c, ah[mt], bh + s * 2);                                \
                    mma_16816(c, ah[mt], bl + s * 2);                                \
                    mma_16816(c, al[mt], bh + s * 2);                                \
                }                                                                    \
        }                                                                            \
    }

#define MMA_STAGE_C()                                                                \
    _Pragma("unroll")                                                                \
    for (int mt = 0; mt < 2; mt++)                                                   \
        _Pragma("unroll")                                                            \
        for (int nt = 0; nt < 8; nt++) {                                             \
            int r0 = warpM * 32 + mt * 16 + (lane >> 2);                             \
            int cc = warpN * 64 + nt * 8 + (lane & 3) * 2;                           \
            float* c = acc[mt][nt];                                                  \
            *(float2*)&Cs[r0 * 128 + cc]       = make_float2(c[0], c[1]);            \
            *(float2*)&Cs[(r0 + 8) * 128 + cc] = make_float2(c[2], c[3]);            \
        }

// cp.async fill of one 64KB stage: A rows linear (clamped), B = weight rows (K=DD).
#define PIPE_FILL(stg, c0_, srcHi_, srcLo_, Mmax_)                                   \
    do {                                                                             \
        uint32_t sb_ = stage0 + (uint32_t)(stg) * 65536u;                            \
        _Pragma("unroll")                                                            \
        for (int it = 0; it < 4; it++) {                                             \
            int idx = tid + it * 256;                                                \
            int row = idx >> 3, q = idx & 7;                                         \
            int gr = blockRow + row; if (gr >= (Mmax_)) gr = (Mmax_) - 1;            \
            uint32_t d_ = sb_ + SW128((uint32_t)(row * 128 + q * 16));               \
            cp_async16(d_,          (const char*)((srcHi_) + (long)gr * DD + (c0_)) + q * 16); \
            cp_async16(d_ + 16384u, (const char*)((srcLo_) + (long)gr * DD + (c0_)) + q * 16); \
            long bo_ = (long)(blockCol + row) * DD + (c0_);                          \
            cp_async16(d_ + 32768u, (const char*)(WThi + bo_) + q * 16);             \
            cp_async16(d_ + 49152u, (const char*)(WTlo + bo_) + q * 16);             \
        }                                                                            \
    } while (0)

// ================ gemmP13: P13 = obj @ [Wa|Wc]   (M=NOBJ, N=2560, K=256) ================
__global__ __launch_bounds__(256)
void gemmP13(int srcBuf, int layer) {
    extern __shared__ char smem[];
    uint32_t raw  = smem_u32(smem);
    uint32_t base = (raw + 1023u) & ~1023u;
    char* pal = smem + (base - raw);
    const uint32_t stage0 = base + 1024;

    int tid = threadIdx.x;
    int wid = tid >> 5, lane = tid & 31;
    int warpM = wid & 3, warpN = wid >> 2;
    int blockRow = blockIdx.y * 128;
    int blockCol = blockIdx.x * 128;

    const __nv_bfloat16* aHi = g_objHi[srcBuf];
    const __nv_bfloat16* aLo = g_objLo[srcBuf];
    const __nv_bfloat16* WThi = g_WacThi + (long)layer * N13 * DD;
    const __nv_bfloat16* WTlo = g_WacTlo + (long)layer * N13 * DD;

    float acc[2][8][4];
    #pragma unroll
    for (int a = 0; a < 2; a++)
        #pragma unroll
        for (int b = 0; b < 8; b++)
            #pragma unroll
            for (int c = 0; c < 4; c++) acc[a][b][c] = 0.f;

    const int NCH = DD / KCH;   // 4
    PIPE_FILL(0, 0, aHi, aLo, NOBJ);
    CP_COMMIT();
    for (int ck = 0; ck < NCH; ck++) {
        int cur = ck & 1;
        if (ck + 1 < NCH) {
            PIPE_FILL((ck + 1) & 1, (ck + 1) * KCH, aHi, aLo, NOBJ);
            CP_COMMIT();
            CP_WAIT1();
        } else {
            CP_WAIT0();
        }
        __syncthreads();
        uint32_t sb = stage0 + (uint32_t)cur * 65536u;
        uint32_t uAhi = sb, uAlo = sb + 16384u, uBhi = sb + 32768u, uBlo = sb + 49152u;
        MMA_COMPUTE_CHUNK();
        __syncthreads();
    }

    float* Cs = (float*)(pal + 1024);
    MMA_STAGE_C();
    __syncthreads();

    #pragma unroll
    for (int i = 0; i < 16; i++) {
        int f = tid + i * 256;
        int row = f >> 5;
        int c4 = (f & 31) << 2;
        int gr = blockRow + row;
        if (gr >= NOBJ) continue;
        *(float4*)&g_P13[(long)gr * N13 + blockCol + c4] = *(float4*)&Cs[row * 128 + c4];
    }
}

// ========== gemmP2: new_t = pred@Wb + P13[s] + P13[o,+N1] + b12, fused scatter ==========
__global__ __launch_bounds__(256)
void gemmP2(int srcBuf, int layer, int last, float* __restrict__ predExtOut) {
    extern __shared__ char smem[];
    uint32_t raw  = smem_u32(smem);
    uint32_t base = (raw + 1023u) & ~1023u;
    char* pal = smem + (base - raw);
    int* sIdxS = (int*)(pal);
    int* oIdxS = (int*)(pal + 512);
    const uint32_t stage0 = base + 1024;

    int tid = threadIdx.x;
    int wid = tid >> 5, lane = tid & 31;
    int warpM = wid & 3, warpN = wid >> 2;
    int blockRow = blockIdx.y * 128;
    int blockCol = blockIdx.x * 128;

    const __nv_bfloat16* aHi = g_predHi[srcBuf];
    const __nv_bfloat16* aLo = g_predLo[srcBuf];
    const __nv_bfloat16* WThi = g_WbThi + (long)layer * N1 * DD;
    const __nv_bfloat16* WTlo = g_WbTlo + (long)layer * N1 * DD;

    if (tid < 128) {
        int gr = blockRow + tid; if (gr >= NTRI) gr = NTRI - 1;
        sIdxS[tid] = g_sidx[gr];
        oIdxS[tid] = g_oidx[gr];
    }

    float acc[2][8][4];
    #pragma unroll
    for (int a = 0; a < 2; a++)
        #pragma unroll
        for (int b = 0; b < 8; b++)
            #pragma unroll
            for (int c = 0; c < 4; c++) acc[a][b][c] = 0.f;

    const int NCH = DD / KCH;   // 4
    PIPE_FILL(0, 0, aHi, aLo, NTRI);
    CP_COMMIT();
    for (int ck = 0; ck < NCH; ck++) {
        int cur = ck & 1;
        if (ck + 1 < NCH) {
            PIPE_FILL((ck + 1) & 1, (ck + 1) * KCH, aHi, aLo, NTRI);
            CP_COMMIT();
            CP_WAIT1();
        } else {
            CP_WAIT0();
        }
        __syncthreads();
        uint32_t sb = stage0 + (uint32_t)cur * 65536u;
        uint32_t uAhi = sb, uAlo = sb + 16384u, uBhi = sb + 32768u, uBlo = sb + 49152u;
        MMA_COMPUTE_CHUNK();
        __syncthreads();
    }

    float* Cs = (float*)(pal + 1024);
    MMA_STAGE_C();
    __syncthreads();

    const float* biasL = g_b12 + layer * N1;
    __nv_bfloat16* pHo = g_predHi[srcBuf ^ 1];
    __nv_bfloat16* pLo = g_predLo[srcBuf ^ 1];
    #pragma unroll
    for (int i = 0; i < 16; i++) {
        int f = tid + i * 256;
        int row = f >> 5;
        int c4 = (f & 31) << 2;
        int gr = blockRow + row;
        if (gr >= NTRI) continue;
        int sI = sIdxS[row], oI = oIdxS[row];
        int gc0 = blockCol + c4;
        float4 v  = *(float4*)&Cs[row * 128 + c4];
        float4 bb = *(const float4*)&biasL[gc0];
        float4 ps = *(const float4*)&g_P13[(long)sI * N13 + gc0];
        float4 po = *(const float4*)&g_P13[(long)oI * N13 + N1 + gc0];
        v.x += bb.x + ps.x + po.x;
        v.y += bb.y + ps.y + po.y;
        v.z += bb.z + ps.z + po.z;
        v.w += bb.w + ps.w + po.w;
        if (gc0 < HH) {
            red_add4(&g_pooled[(long)sI * HH + gc0], v.x, v.y, v.z, v.w);
        } else if (gc0 < HH + DD) {
            int pc = gc0 - HH;
            if (last) {
                *(float4*)&predExtOut[(long)gr * DD + pc] = v;
            } else {
                long o = (long)gr * DD + pc;
                uint32_t l01, l23;
                uint32_t h01 = pack_hi2(v.x, v.y, l01);
                uint32_t h23 = pack_hi2(v.z, v.w, l23);
                *(uint2*)(pHo + o) = make_uint2(h01, h23);
                *(uint2*)(pLo + o) = make_uint2(l01, l23);
            }
        } else {
            red_add4(&g_pooled[(long)oI * HH + (gc0 - HH - DD)], v.x, v.y, v.z, v.w);
        }
    }
}

// ================ gemmB: obj' = (pooled*inv) @ W34 + b34   (K=512) ================
__global__ __launch_bounds__(256)
void gemmB_mma(int layer, int dstBuf, int last, float* __restrict__ objExtOut) {
    extern __shared__ char smem[];
    uint32_t raw  = smem_u32(smem);
    uint32_t base = (raw + 1023u) & ~1023u;
    char* pal = smem + (base - raw);
    const uint32_t uAhi = base + 1024;
    const uint32_t uAlo = uAhi + 16384;
    const uint32_t uBhi = uAlo + 16384;
    const uint32_t uBlo = uBhi + 16384;
    char* pAhi = pal + 1024;
    char* pAlo = pAhi + 16384;
    char* pBhi = pAlo + 16384;
    char* pBlo = pBhi + 16384;

    int tid = threadIdx.x;
    int wid = tid >> 5, lane = tid & 31;
    int warpM = wid & 3, warpN = wid >> 2;
    int blockRow = blockIdx.y * 128;
    int blockCol = blockIdx.x * 128;

    const __nv_bfloat16* WThi = g_W34Thi + (long)layer * DD * HH;
    const __nv_bfloat16* WTlo = g_W34Tlo + (long)layer * DD * HH;

    float acc[2][8][4];
    #pragma unroll
    for (int a = 0; a < 2; a++)
        #pragma unroll
        for (int b = 0; b < 8; b++)
            #pragma unroll
            for (int c = 0; c < 4; c++) acc[a][b][c] = 0.f;

    for (int ck = 0; ck < HH / KCH; ck++) {
        int c0 = ck * KCH;
        #pragma unroll
        for (int it = 0; it < 4; it++) {
            int idx = tid + it * 256;
            int row = idx >> 3, q = idx & 7;
            int gr = blockRow + row; if (gr >= NOBJ) gr = NOBJ - 1;
            float inv = g_inv[gr];
            const float* src = g_pooled + (long)gr * HH + c0 + q * 8;
            float4 f0 = *(const float4*)src;
            float4 f1 = *(const float4*)(src + 4);
            uint4 hi, lo;
            hi.x = pack_hi2(f0.x * inv, f0.y * inv, lo.x);
            hi.y = pack_hi2(f0.z * inv, f0.w * inv, lo.y);
            hi.z = pack_hi2(f1.x * inv, f1.y * inv, lo.z);
            hi.w = pack_hi2(f1.z * inv, f1.w * inv, lo.w);
            uint32_t d = SW128((uint32_t)(row * 128 + q * 16));
            *(uint4*)(pAhi + d) = hi;
            *(uint4*)(pAlo + d) = lo;
            long bo = (long)(blockCol + row) * HH + c0;
            *(uint4*)(pBhi + d) = ((const uint4*)(WThi + bo))[q];
            *(uint4*)(pBlo + d) = ((const uint4*)(WTlo + bo))[q];
        }
        __syncthreads();
        MMA_COMPUTE_CHUNK();
        __syncthreads();
    }

    float* Cs = (float*)pAhi;
    MMA_STAGE_C();
    __syncthreads();

    const float* biasL = g_b34 + layer * DD;
    __nv_bfloat16* oh = g_objHi[dstBuf];
    __nv_bfloat16* ol = g_objLo[dstBuf];
    #pragma unroll
    for (int i = 0; i < 16; i++) {
        int f = tid + i * 256;
        int row = f >> 5;
        int c4 = (f & 31) << 2;
        int gr = blockRow + row;
        if (gr >= NOBJ) continue;
        int gc0 = blockCol + c4;
        float4 v = *(float4*)&Cs[row * 128 + c4];
        float4 bb = *(const float4*)&biasL[gc0];
        v.x += bb.x; v.y += bb.y; v.z += bb.z; v.w += bb.w;
        if (last) {
            *(float4*)&objExtOut[(long)gr * DD + gc0] = v;
        } else {
            long o = (long)gr * DD + gc0;
            uint32_t l01, l23;
            uint32_t h01 = pack_hi2(v.x, v.y, l01);
            uint32_t h23 = pack_hi2(v.z, v.w, l23);
            *(uint2*)(oh + o) = make_uint2(h01, h23);
            *(uint2*)(ol + o) = make_uint2(l01, l23);
        }
    }
}

// ======================= launcher =======================
extern "C" void kernel_launch(void* const* d_in, const int* in_sizes, int n_in,
                              void* d_out, int out_size) {
    const float* obj_in  = (const float*)d_in[0];
    const float* pred_in = (const float*)d_in[1];
    const void*  edges   = d_in[2];
    const float* W1 = (const float*)d_in[3];
    const float* b1 = (const float*)d_in[4];
    const float* W2 = (const float*)d_in[5];
    const float* b2 = (const float*)d_in[6];
    const float* W3 = (const float*)d_in[7];
    const float* b3 = (const float*)d_in[8];
    const float* W4 = (const float*)d_in[9];
    const float* b4 = (const float*)d_in[10];

    float* out_obj  = (float*)d_out;                     // [20000, 256]
    float* out_pred = (float*)d_out + (long)NOBJ * DD;   // [60000, 256]

    static int attr_done = 0;
    if (!attr_done) {
        cudaFuncSetAttribute(gemmP13,   cudaFuncAttributeMaxDynamicSharedMemorySize, MM_SMEMP);
        cudaFuncSetAttribute(gemmP2,    cudaFuncAttributeMaxDynamicSharedMemorySize, MM_SMEMP);
        cudaFuncSetAttribute(gemmB_mma, cudaFuncAttributeMaxDynamicSharedMemorySize, MM_SMEM);
        attr_done = 1;
    }

    // edges
    zero_cnt_detect_kernel<<<cdiv_h(NOBJ, 256), 256>>>((const int*)edges);
    convert_kernel<<<cdiv_h(NTRI, 256), 256>>>(edges);
    inv_kernel<<<cdiv_h(NOBJ, 256), 256>>>();

    // composite weights + biases + bf16 planes
    sgemm_prep<<<dim3(N1 / 128, K1 / 128, LL), 256>>>(W1, W2, 0, K1, N1, HH);
    sgemm_prep<<<dim3(DD / 128, HH / 128, LL), 256>>>(W3, W4, 1, HH, DD, HH);
    bias12_kernel<<<dim3(cdiv_h(N1, 256), 1, LL), 256>>>(b1, W2, b2);
    bias34_kernel<<<dim3(cdiv_h(DD, 256), 1, LL), 256>>>(b3, W4, b4);
    transpose_split_kernel<<<dim3(DD / 32, N13 / 32, LL), dim3(32, 8)>>>(0);
    transpose_split_kernel<<<dim3(DD / 32, N1 / 32, LL), dim3(32, 8)>>>(1);
    transpose_split_kernel<<<dim3(HH / 32, DD / 32, LL), dim3(32, 8)>>>(2);

    // input activations -> hi/lo planes (buffer 0)
    cvt_obj_kernel<<<cdiv_h(NOBJ * DD, 256), 256>>>(obj_in);
    cvt_pred_kernel<<<cdiv_h(NTRI * DD, 256), 256>>>(pred_in);

    dim3 gridP13(N13 / 128, cdiv_h(NOBJ, 128));  // (20, 157)
    dim3 gridP2(N1 / 128, cdiv_h(NTRI, 128));    // (10, 469)
    dim3 gridB(DD / 128, cdiv_h(NOBJ, 128));     // (2, 157)
    int zpBlocks = cdiv_h(NOBJ * HH / 4, 256);

    for (int l = 0; l < LL; l++) {
        int src = l & 1, dst = src ^ 1, last = (l == LL - 1);
        zero_pooled_kernel<<<zpBlocks, 256>>>();
        gemmP13<<<gridP13, 256, MM_SMEMP>>>(src, l);
        gemmP2<<<gridP2, 256, MM_SMEMP>>>(src, l, last, out_pred);
        gemmB_mma<<<gridB, 256, MM_SMEM>>>(l, dst, last, out_obj);
    }
}

// round 10
// speedup vs baseline: 5.8199x; 1.9589x over previous
#include <cuda_runtime.h>
#include <cuda_fp16.h>
#include <cstdint>

#define NOBJ 20000
#define NTRI 60000
#define DD   256
#define HH   512
#define LL   5
#define K1   768    // 3*D
#define N1   1280   // 2H+D
#define N13  2560   // 2*N1  (P13 = obj @ [Wa|Wc])
#define KCH  64     // K chunk per SMEM stage

static inline int cdiv_h(int a, int b) { return (a + b - 1) / b; }

// ======================= PTX helpers =======================
__device__ __forceinline__ uint32_t smem_u32(const void* p) {
    uint32_t a;
    asm("{ .reg .u64 t; cvta.to.shared.u64 t, %1; cvt.u32.u64 %0, t; }" : "=r"(a) : "l"(p));
    return a;
}
#define SW128(off) ((off) ^ (((off) >> 3) & 0x70))

__device__ __forceinline__ void ldsm_x4(uint32_t& r0, uint32_t& r1, uint32_t& r2, uint32_t& r3,
                                        uint32_t addr) {
    asm volatile("ldmatrix.sync.aligned.m8n8.x4.shared.b16 {%0,%1,%2,%3}, [%4];"
                 : "=r"(r0), "=r"(r1), "=r"(r2), "=r"(r3) : "r"(addr));
}
__device__ __forceinline__ void mma_f16(float* c, const uint32_t* a, const uint32_t* b) {
    asm volatile("mma.sync.aligned.m16n8k16.row.col.f32.f16.f16.f32 "
                 "{%0,%1,%2,%3}, {%4,%5,%6,%7}, {%8,%9}, {%0,%1,%2,%3};"
                 : "+f"(c[0]), "+f"(c[1]), "+f"(c[2]), "+f"(c[3])
                 : "r"(a[0]), "r"(a[1]), "r"(a[2]), "r"(a[3]), "r"(b[0]), "r"(b[1]));
}
__device__ __forceinline__ void red_add4(float* p, float a, float b, float c, float d) {
    asm volatile("red.global.add.v4.f32 [%0], {%1, %2, %3, %4};"
                 :: "l"(p), "f"(a), "f"(b), "f"(c), "f"(d) : "memory");
}
__device__ __forceinline__ void cp_async16(uint32_t s, const void* g) {
    asm volatile("cp.async.cg.shared.global [%0], [%1], 16;" :: "r"(s), "l"(g));
}
#define CP_COMMIT() asm volatile("cp.async.commit_group;" ::: "memory")
#define CP_WAIT1()  asm volatile("cp.async.wait_group 1;" ::: "memory")
#define CP_WAIT0()  asm volatile("cp.async.wait_group 0;" ::: "memory")

__device__ __forceinline__ uint32_t pack_h2(float a, float b) {
    __half2 h = __floats2half2_rn(a, b);
    return *(uint32_t*)&h;
}

// ======================= device globals (no allocation) =======================
__device__ __half g_objF[2][NOBJ * DD];
__device__ __half g_predF[2][NTRI * DD];
__device__ __half g_WacT[LL * N13 * DD];    // [l][n][k]  n<1280: Wa rows; n>=1280: Wc
__device__ __half g_WbT[LL * N1 * DD];      // [l][n][k]  Wb = W12 rows 256..511
__device__ __half g_W34T[LL * DD * HH];     // [l][n][k]
__device__ float g_P13[(long)NOBJ * N13];   // obj @ [Wa|Wc], fp32
__device__ float g_pooled[NOBJ * HH];
__device__ float g_W12[LL * K1 * N1];
__device__ float g_b12[LL * N1];
__device__ float g_W34[LL * HH * DD];
__device__ float g_b34[LL * DD];
__device__ int   g_sidx[NTRI];
__device__ int   g_oidx[NTRI];
__device__ int   g_cnt[NOBJ];
__device__ float g_inv[NOBJ];

// ======================= small utility kernels =======================
__global__ void convert_kernel(const void* edges) {
    int i = blockIdx.x * blockDim.x + threadIdx.x;
    if (i >= NTRI) return;
    // per-thread int64/int32 detection (values < 20000 => high words zero)
    const int* e32 = (const int*)edges;
    int ok = 1;
    #pragma unroll
    for (int w = 1; w < 16; w += 2) ok &= (e32[w] == 0);
    int s, o;
    if (ok) {
        const long long* p = (const long long*)edges;
        s = (int)p[2 * i]; o = (int)p[2 * i + 1];
    } else {
        s = e32[2 * i]; o = e32[2 * i + 1];
    }
    g_sidx[i] = s; g_oidx[i] = o;
    atomicAdd(&g_cnt[s], 1);
    atomicAdd(&g_cnt[o], 1);
}
__global__ void inv_kernel() {
    int i = blockIdx.x * blockDim.x + threadIdx.x;
    if (i < NOBJ) {
        int c = g_cnt[i];
        g_inv[i] = 1.0f / (float)(c > 0 ? c : 1);
    }
}
__global__ void cvt_obj_kernel(const float* __restrict__ src) {
    int i = blockIdx.x * blockDim.x + threadIdx.x;
    if (i < NOBJ * DD / 2) {
        float2 v = ((const float2*)src)[i];
        ((uint32_t*)g_objF[0])[i] = pack_h2(v.x, v.y);
    }
}
__global__ void cvt_pred_kernel(const float* __restrict__ src) {
    int i = blockIdx.x * blockDim.x + threadIdx.x;
    if (i < NTRI * DD / 2) {
        float2 v = ((const float2*)src)[i];
        ((uint32_t*)g_predF[0])[i] = pack_h2(v.x, v.y);
    }
}
__global__ void bias12_kernel(const float* __restrict__ b1, const float* __restrict__ W2,
                              const float* __restrict__ b2) {
    int l = blockIdx.z;
    int c = blockIdx.x * blockDim.x + threadIdx.x;
    if (c >= N1) return;
    const float* b1l = b1 + l * HH;
    const float* W2l = W2 + (long)l * HH * N1;
    float s = b2[(long)l * N1 + c];
    for (int k = 0; k < HH; k++) s = fmaf(b1l[k], W2l[(long)k * N1 + c], s);
    g_b12[l * N1 + c] = s;
}
__global__ void bias34_kernel(const float* __restrict__ b3, const float* __restrict__ W4,
                              const float* __restrict__ b4) {
    int l = blockIdx.z;
    int c = blockIdx.x * blockDim.x + threadIdx.x;
    if (c >= DD) return;
    const float* b3l = b3 + l * HH;
    const float* W4l = W4 + (long)l * HH * DD;
    float s = b4[(long)l * DD + c];
    for (int k = 0; k < HH; k++) s = fmaf(b3l[k], W4l[(long)k * DD + c], s);
    g_b34[l * DD + c] = s;
}

// transpose + fp16 cvt: produce [n][k] fp16 planes from fp32 composites.
// mode 0: WacT (K=DD, N=N13) from W12 (n<N1: rows k; n>=N1: rows 512+k)
// mode 1: WbT  (K=DD, N=N1)  from W12 rows 256+k
// mode 2: W34T (K=HH, N=DD)  from W34
__global__ void transpose_cvt_kernel(int mode) {
    __shared__ float tile[32][33];
    int l = blockIdx.z;
    int K = (mode == 2) ? HH : DD;
    __half* Hp;
    if (mode == 0)      Hp = g_WacT + (long)l * N13 * DD;
    else if (mode == 1) Hp = g_WbT  + (long)l * N1  * DD;
    else                Hp = g_W34T + (long)l * DD  * HH;
    int k0 = blockIdx.x * 32;
    int n0 = blockIdx.y * 32;
    int tx = threadIdx.x, ty = threadIdx.y;
    #pragma unroll
    for (int i = 0; i < 32; i += 8) {
        int k = k0 + ty + i, n = n0 + tx;
        float v;
        if (mode == 0) {
            int ksrc = (n < N1) ? k : (512 + k);
            int nsrc = (n < N1) ? n : (n - N1);
            v = g_W12[(long)l * K1 * N1 + (long)ksrc * N1 + nsrc];
        } else if (mode == 1) {
            v = g_W12[(long)l * K1 * N1 + (long)(256 + k) * N1 + n];
        } else {
            v = g_W34[(long)l * HH * DD + (long)k * DD + n];
        }
        tile[ty + i][tx] = v;
    }
    __syncthreads();
    #pragma unroll
    for (int i = 0; i < 32; i += 8) {
        float v = tile[tx][ty + i];
        Hp[(long)(n0 + ty + i) * K + k0 + tx] = __float2half_rn(v);
    }
}

// ---------------- weight-prep GEMM (fp32, once per replay) ----------------
__global__ __launch_bounds__(256, 2)
void sgemm_prep(const float* __restrict__ A, const float* __restrict__ B,
                int which, int M, int N, int K) {
    float* C = (which == 0) ? g_W12 : g_W34;
    long z = blockIdx.z;
    A += z * (long)M * K; B += z * (long)K * N; C += z * (long)M * N;
    __shared__ float As[16][128];
    __shared__ float Bs[16][128];
    int tid = threadIdx.x;
    int tx = tid & 15, ty = tid >> 4;
    int blockRow = blockIdx.y * 128, blockCol = blockIdx.x * 128;
    float acc[8][8];
    #pragma unroll
    for (int i = 0; i < 8; i++)
        #pragma unroll
        for (int j = 0; j < 8; j++) acc[i][j] = 0.f;
    int lr = tid >> 1, lc = (tid & 1) * 8;
    int br = tid >> 4, bc = (tid & 15) * 8;
    for (int k0 = 0; k0 < K; k0 += 16) {
        int gr = blockRow + lr;
        float4 a0, a1;
        if (gr < M) {
            const float* rp = A + (long)gr * K + k0;
            a0 = *(const float4*)(rp + lc); a1 = *(const float4*)(rp + lc + 4);
        } else { a0 = make_float4(0,0,0,0); a1 = a0; }
        As[lc+0][lr]=a0.x; As[lc+1][lr]=a0.y; As[lc+2][lr]=a0.z; As[lc+3][lr]=a0.w;
        As[lc+4][lr]=a1.x; As[lc+5][lr]=a1.y; As[lc+6][lr]=a1.z; As[lc+7][lr]=a1.w;
        const float* bp = B + (long)(k0 + br) * N + blockCol + bc;
        *(float4*)&Bs[br][bc]     = *(const float4*)bp;
        *(float4*)&Bs[br][bc + 4] = *(const float4*)(bp + 4);
        __syncthreads();
        #pragma unroll
        for (int k = 0; k < 16; k++) {
            float4 x0 = *(float4*)&As[k][ty * 8];
            float4 x1 = *(float4*)&As[k][ty * 8 + 4];
            float4 y0 = *(float4*)&Bs[k][tx * 8];
            float4 y1 = *(float4*)&Bs[k][tx * 8 + 4];
            float ra[8] = {x0.x,x0.y,x0.z,x0.w,x1.x,x1.y,x1.z,x1.w};
            float rb[8] = {y0.x,y0.y,y0.z,y0.w,y1.x,y1.y,y1.z,y1.w};
            #pragma unroll
            for (int i = 0; i < 8; i++)
                #pragma unroll
                for (int j = 0; j < 8; j++) acc[i][j] = fmaf(ra[i], rb[j], acc[i][j]);
        }
        __syncthreads();
    }
    #pragma unroll
    for (int i = 0; i < 8; i++) {
        int gr = blockRow + ty * 8 + i;
        if (gr >= M) continue;
        #pragma unroll
        for (int j = 0; j < 8; j++) {
            int gc = blockCol + tx * 8 + j;
            if (gc < N) C[(long)gr * N + gc] = acc[i][j];
        }
    }
}

// ======================= fp16 MMA core =======================
// SMEM layout (1024-aligned base): sIdx[128] @0, oIdx[128] @512; stages @1024.
// Stage = A plane 16KB + B plane 16KB = 32KB; 2 stages. C (fp32 64KB) overlays both.
#define MM_SMEMP (1024 + 1024 + 2 * 32768)

#define MMA_COMPUTE_CHUNK()                                                          \
    _Pragma("unroll")                                                                \
    for (int ks = 0; ks < 4; ks++) {                                                 \
        uint32_t af[2][4];                                                           \
        _Pragma("unroll")                                                            \
        for (int mt = 0; mt < 2; mt++) {                                             \
            int mrow = warpM * 32 + mt * 16 + (lane & 15);                           \
            uint32_t cb = (uint32_t)(ks * 32) + ((lane >> 4) << 4);                  \
            uint32_t ad = SW128((uint32_t)(mrow * 128) + cb);                        \
            ldsm_x4(af[mt][0], af[mt][1], af[mt][2], af[mt][3], uA + ad);            \
        }                                                                            \
        _Pragma("unroll")                                                            \
        for (int np = 0; np < 4; np++) {                                             \
            int nrow = warpN * 64 + np * 16 + (lane & 7) + ((lane >> 4) << 3);       \
            uint32_t cb = (uint32_t)(ks * 32) + (((lane >> 3) & 1) << 4);            \
            uint32_t bd = SW128((uint32_t)(nrow * 128) + cb);                        \
            uint32_t bf[4];                                                          \
            ldsm_x4(bf[0], bf[1], bf[2], bf[3], uB + bd);                            \
            _Pragma("unroll")                                                        \
            for (int mt = 0; mt < 2; mt++)                                           \
                _Pragma("unroll")                                                    \
                for (int s = 0; s < 2; s++)                                          \
                    mma_f16(acc[mt][np * 2 + s], af[mt], bf + s * 2);                \
        }                                                                            \
    }

#define MMA_STAGE_C()                                                                \
    _Pragma("unroll")                                                                \
    for (int mt = 0; mt < 2; mt++)                                                   \
        _Pragma("unroll")                                                            \
        for (int nt = 0; nt < 8; nt++) {                                             \
            int r0 = warpM * 32 + mt * 16 + (lane >> 2);                             \
            int cc = warpN * 64 + nt * 8 + (lane & 3) * 2;                           \
            float* c = acc[mt][nt];                                                  \
            *(float2*)&Cs[r0 * 128 + cc]       = make_float2(c[0], c[1]);            \
            *(float2*)&Cs[(r0 + 8) * 128 + cc] = make_float2(c[2], c[3]);            \
        }

// cp.async fill of one 32KB stage (A rows linear+clamped, B weight rows, K-stride DD)
#define PIPE_FILL(stg, c0_, srcF_, Mmax_)                                            \
    do {                                                                             \
        uint32_t sb_ = stage0 + (uint32_t)(stg) * 32768u;                            \
        _Pragma("unroll")                                                            \
        for (int it = 0; it < 4; it++) {                                             \
            int idx = tid + it * 256;                                                \
            int row = idx >> 3, q = idx & 7;                                         \
            int gr = blockRow + row; if (gr >= (Mmax_)) gr = (Mmax_) - 1;            \
            uint32_t d_ = sb_ + SW128((uint32_t)(row * 128 + q * 16));               \
            cp_async16(d_, (const char*)((srcF_) + (long)gr * DD + (c0_)) + q * 16); \
            long bo_ = (long)(blockCol + row) * DD + (c0_);                          \
            cp_async16(d_ + 16384u, (const char*)(WT + bo_) + q * 16);               \
        }                                                                            \
    } while (0)

// ================ gemmP13: P13 = obj @ [Wa|Wc]   (M=NOBJ, N=2560, K=256) ================
__global__ __launch_bounds__(256)
void gemmP13(int srcBuf, int layer) {
    extern __shared__ char smem[];
    uint32_t raw  = smem_u32(smem);
    uint32_t base = (raw + 1023u) & ~1023u;
    char* pal = smem + (base - raw);
    const uint32_t stage0 = base + 1024;

    int tid = threadIdx.x;
    int wid = tid >> 5, lane = tid & 31;
    int warpM = wid & 3, warpN = wid >> 2;
    int blockRow = blockIdx.y * 128;
    int blockCol = blockIdx.x * 128;

    const __half* aF = g_objF[srcBuf];
    const __half* WT = g_WacT + (long)layer * N13 * DD;

    float acc[2][8][4];
    #pragma unroll
    for (int a = 0; a < 2; a++)
        #pragma unroll
        for (int b = 0; b < 8; b++)
            #pragma unroll
            for (int c = 0; c < 4; c++) acc[a][b][c] = 0.f;

    const int NCH = DD / KCH;   // 4
    PIPE_FILL(0, 0, aF, NOBJ);
    CP_COMMIT();
    for (int ck = 0; ck < NCH; ck++) {
        int cur = ck & 1;
        if (ck + 1 < NCH) {
            PIPE_FILL((ck + 1) & 1, (ck + 1) * KCH, aF, NOBJ);
            CP_COMMIT();
            CP_WAIT1();
        } else {
            CP_WAIT0();
        }
        __syncthreads();
        uint32_t sb = stage0 + (uint32_t)cur * 32768u;
        uint32_t uA = sb, uB = sb + 16384u;
        MMA_COMPUTE_CHUNK();
        __syncthreads();
    }

    float* Cs = (float*)(pal + 1024);
    MMA_STAGE_C();
    __syncthreads();

    #pragma unroll
    for (int i = 0; i < 16; i++) {
        int f = tid + i * 256;
        int row = f >> 5;
        int c4 = (f & 31) << 2;
        int gr = blockRow + row;
        if (gr >= NOBJ) continue;
        *(float4*)&g_P13[(long)gr * N13 + blockCol + c4] = *(float4*)&Cs[row * 128 + c4];
    }
}

// ========== gemmP2: new_t = pred@Wb + P13[s] + P13[o,+N1] + b12, fused scatter ==========
__global__ __launch_bounds__(256)
void gemmP2(int srcBuf, int layer, int last, float* __restrict__ predExtOut) {
    extern __shared__ char smem[];
    uint32_t raw  = smem_u32(smem);
    uint32_t base = (raw + 1023u) & ~1023u;
    char* pal = smem + (base - raw);
    int* sIdxS = (int*)(pal);
    int* oIdxS = (int*)(pal + 512);
    const uint32_t stage0 = base + 1024;

    int tid = threadIdx.x;
    int wid = tid >> 5, lane = tid & 31;
    int warpM = wid & 3, warpN = wid >> 2;
    int blockRow = blockIdx.y * 128;
    int blockCol = blockIdx.x * 128;

    const __half* aF = g_predF[srcBuf];
    const __half* WT = g_WbT + (long)layer * N1 * DD;

    if (tid < 128) {
        int gr = blockRow + tid; if (gr >= NTRI) gr = NTRI - 1;
        sIdxS[tid] = g_sidx[gr];
        oIdxS[tid] = g_oidx[gr];
    }

    float acc[2][8][4];
    #pragma unroll
    for (int a = 0; a < 2; a++)
        #pragma unroll
        for (int b = 0; b < 8; b++)
            #pragma unroll
            for (int c = 0; c < 4; c++) acc[a][b][c] = 0.f;

    const int NCH = DD / KCH;   // 4
    PIPE_FILL(0, 0, aF, NTRI);
    CP_COMMIT();
    for (int ck = 0; ck < NCH; ck++) {
        int cur = ck & 1;
        if (ck + 1 < NCH) {
            PIPE_FILL((ck + 1) & 1, (ck + 1) * KCH, aF, NTRI);
            CP_COMMIT();
            CP_WAIT1();
        } else {
            CP_WAIT0();
        }
        __syncthreads();
        uint32_t sb = stage0 + (uint32_t)cur * 32768u;
        uint32_t uA = sb, uB = sb + 16384u;
        MMA_COMPUTE_CHUNK();
        __syncthreads();
    }

    float* Cs = (float*)(pal + 1024);
    MMA_STAGE_C();
    __syncthreads();

    const float* biasL = g_b12 + layer * N1;
    __half* pOut = g_predF[srcBuf ^ 1];
    #pragma unroll
    for (int i = 0; i < 16; i++) {
        int f = tid + i * 256;
        int row = f >> 5;
        int c4 = (f & 31) << 2;
        int gr = blockRow + row;
        if (gr >= NTRI) continue;
        int sI = sIdxS[row], oI = oIdxS[row];
        int gc0 = blockCol + c4;
        float4 v  = *(float4*)&Cs[row * 128 + c4];
        float4 bb = *(const float4*)&biasL[gc0];
        float4 ps = *(const float4*)&g_P13[(long)sI * N13 + gc0];
        float4 po = *(const float4*)&g_P13[(long)oI * N13 + N1 + gc0];
        v.x += bb.x + ps.x + po.x;
        v.y += bb.y + ps.y + po.y;
        v.z += bb.z + ps.z + po.z;
        v.w += bb.w + ps.w + po.w;
        if (gc0 < HH) {
            red_add4(&g_pooled[(long)sI * HH + gc0], v.x, v.y, v.z, v.w);
        } else if (gc0 < HH + DD) {
            int pc = gc0 - HH;
            if (last) {
                *(float4*)&predExtOut[(long)gr * DD + pc] = v;
            } else {
                *(uint2*)(pOut + (long)gr * DD + pc) =
                    make_uint2(pack_h2(v.x, v.y), pack_h2(v.z, v.w));
            }
        } else {
            red_add4(&g_pooled[(long)oI * HH + (gc0 - HH - DD)], v.x, v.y, v.z, v.w);
        }
    }
}

// ================ gemmB: obj' = (pooled*inv) @ W34 + b34   (M=NOBJ, N=256, K=512) ================
__global__ __launch_bounds__(256)
void gemmB_mma(int layer, int dstBuf, int last, float* __restrict__ objExtOut) {
    extern __shared__ char smem[];
    uint32_t raw  = smem_u32(smem);
    uint32_t base = (raw + 1023u) & ~1023u;
    char* pal = smem + (base - raw);
    const uint32_t uA = base + 1024;
    const uint32_t uB = uA + 16384;
    char* pA = pal + 1024;
    char* pB = pA + 16384;

    int tid = threadIdx.x;
    int wid = tid >> 5, lane = tid & 31;
    int warpM = wid & 3, warpN = wid >> 2;
    int blockRow = blockIdx.y * 128;
    int blockCol = blockIdx.x * 128;

    const __half* WT = g_W34T + (long)layer * DD * HH;

    float acc[2][8][4];
    #pragma unroll
    for (int a = 0; a < 2; a++)
        #pragma unroll
        for (int b = 0; b < 8; b++)
            #pragma unroll
            for (int c = 0; c < 4; c++) acc[a][b][c] = 0.f;

    for (int ck = 0; ck < HH / KCH; ck++) {
        int c0 = ck * KCH;
        #pragma unroll
        for (int it = 0; it < 4; it++) {
            int idx = tid + it * 256;
            int row = idx >> 3, q = idx & 7;
            int gr = blockRow + row; if (gr >= NOBJ) gr = NOBJ - 1;
            float inv = g_inv[gr];
            const float* src = g_pooled + (long)gr * HH + c0 + q * 8;
            float4 f0 = *(const float4*)src;
            float4 f1 = *(const float4*)(src + 4);
            uint4 hv;
            hv.x = pack_h2(f0.x * inv, f0.y * inv);
            hv.y = pack_h2(f0.z * inv, f0.w * inv);
            hv.z = pack_h2(f1.x * inv, f1.y * inv);
            hv.w = pack_h2(f1.z * inv, f1.w * inv);
            uint32_t d = SW128((uint32_t)(row * 128 + q * 16));
            *(uint4*)(pA + d) = hv;
            long bo = (long)(blockCol + row) * HH + c0;
            *(uint4*)(pB + d) = ((const uint4*)(WT + bo))[q];
        }
        __syncthreads();
        MMA_COMPUTE_CHUNK();
        __syncthreads();
    }

    float* Cs = (float*)pA;
    MMA_STAGE_C();
    __syncthreads();

    const float* biasL = g_b34 + layer * DD;
    __half* oOut = g_objF[dstBuf];
    #pragma unroll
    for (int i = 0; i < 16; i++) {
        int f = tid + i * 256;
        int row = f >> 5;
        int c4 = (f & 31) << 2;
        int gr = blockRow + row;
        if (gr >= NOBJ) continue;
        int gc0 = blockCol + c4;
        float4 v = *(float4*)&Cs[row * 128 + c4];
        float4 bb = *(const float4*)&biasL[gc0];
        v.x += bb.x; v.y += bb.y; v.z += bb.z; v.w += bb.w;
        if (last) {
            *(float4*)&objExtOut[(long)gr * DD + gc0] = v;
        } else {
            *(uint2*)(oOut + (long)gr * DD + gc0) =
                make_uint2(pack_h2(v.x, v.y), pack_h2(v.z, v.w));
        }
    }
}

// ======================= launcher =======================
extern "C" void kernel_launch(void* const* d_in, const int* in_sizes, int n_in,
                              void* d_out, int out_size) {
    const float* obj_in  = (const float*)d_in[0];
    const float* pred_in = (const float*)d_in[1];
    const void*  edges   = d_in[2];
    const float* W1 = (const float*)d_in[3];
    const float* b1 = (const float*)d_in[4];
    const float* W2 = (const float*)d_in[5];
    const float* b2 = (const float*)d_in[6];
    const float* W3 = (const float*)d_in[7];
    const float* b3 = (const float*)d_in[8];
    const float* W4 = (const float*)d_in[9];
    const float* b4 = (const float*)d_in[10];

    float* out_obj  = (float*)d_out;                     // [20000, 256]
    float* out_pred = (float*)d_out + (long)NOBJ * DD;   // [60000, 256]

    static int attr_done = 0;
    static void *cnt_addr = nullptr, *pooled_addr = nullptr;
    if (!attr_done) {
        cudaFuncSetAttribute(gemmP13,   cudaFuncAttributeMaxDynamicSharedMemorySize, MM_SMEMP);
        cudaFuncSetAttribute(gemmP2,    cudaFuncAttributeMaxDynamicSharedMemorySize, MM_SMEMP);
        cudaFuncSetAttribute(gemmB_mma, cudaFuncAttributeMaxDynamicSharedMemorySize, MM_SMEMP);
        cudaGetSymbolAddress(&cnt_addr, g_cnt);
        cudaGetSymbolAddress(&pooled_addr, g_pooled);
        attr_done = 1;
    }

    dim3 gridP13(N13 / 128, cdiv_h(NOBJ, 128));  // (20, 157)
    dim3 gridP2(N1 / 128, cdiv_h(NTRI, 128));    // (10, 469)
    dim3 gridB(DD / 128, cdiv_h(NOBJ, 128));     // (2, 157)

    // ---- launches 1-3: minimal chain for gemmP13 (launch 4 = ncu capture target) ----
    sgemm_prep<<<dim3(N1 / 128, K1 / 128, LL), 256>>>(W1, W2, 0, K1, N1, HH);       // 1
    transpose_cvt_kernel<<<dim3(DD / 32, N13 / 32, LL), dim3(32, 8)>>>(0);          // 2
    cvt_obj_kernel<<<cdiv_h(NOBJ * DD / 2, 256), 256>>>(obj_in);                    // 3
    gemmP13<<<gridP13, 256, MM_SMEMP>>>(0, 0);                                      // 4 (profiled)

    // ---- remaining prep ----
    cudaMemsetAsync(cnt_addr, 0, NOBJ * sizeof(int));
    convert_kernel<<<cdiv_h(NTRI, 256), 256>>>(edges);
    inv_kernel<<<cdiv_h(NOBJ, 256), 256>>>();
    sgemm_prep<<<dim3(DD / 128, HH / 128, LL), 256>>>(W3, W4, 1, HH, DD, HH);
    bias12_kernel<<<dim3(cdiv_h(N1, 256), 1, LL), 256>>>(b1, W2, b2);
    bias34_kernel<<<dim3(cdiv_h(DD, 256), 1, LL), 256>>>(b3, W4, b4);
    transpose_cvt_kernel<<<dim3(DD / 32, N1 / 32, LL), dim3(32, 8)>>>(1);
    transpose_cvt_kernel<<<dim3(HH / 32, DD / 32, LL), dim3(32, 8)>>>(2);
    cvt_pred_kernel<<<cdiv_h(NTRI * DD / 2, 256), 256>>>(pred_in);

    // ---- layer 0 (P13 already computed) ----
    cudaMemsetAsync(pooled_addr, 0, (size_t)NOBJ * HH * sizeof(float));
    gemmP2<<<gridP2, 256, MM_SMEMP>>>(0, 0, 0, nullptr);
    gemmB_mma<<<gridB, 256, MM_SMEMP>>>(0, 1, 0, nullptr);

    // ---- layers 1..4 ----
    for (int l = 1; l < LL; l++) {
        int src = l & 1, dst = src ^ 1, last = (l == LL - 1);
        cudaMemsetAsync(pooled_addr, 0, (size_t)NOBJ * HH * sizeof(float));
        gemmP13<<<gridP13, 256, MM_SMEMP>>>(src, l);
        gemmP2<<<gridP2, 256, MM_SMEMP>>>(src, l, last, out_pred);
        gemmB_mma<<<gridB, 256, MM_SMEMP>>>(l, dst, last, out_obj);
    }
}

// round 15
// speedup vs baseline: 6.1135x; 1.0505x over previous
#include <cuda_runtime.h>
#include <cuda_fp16.h>
#include <cstdint>

#define NOBJ 20000
#define NTRI 60000
#define DD   256
#define HH   512
#define LL   5
#define K1   768    // 3*D
#define N1   1280   // 2H+D
#define N13  2560   // 2*N1  (P13 = obj @ [Wa|Wc])
#define KCH  64     // K chunk per SMEM stage

static inline int cdiv_h(int a, int b) { return (a + b - 1) / b; }

// ======================= PTX helpers =======================
__device__ __forceinline__ uint32_t smem_u32(const void* p) {
    uint32_t a;
    asm("{ .reg .u64 t; cvta.to.shared.u64 t, %1; cvt.u32.u64 %0, t; }" : "=r"(a) : "l"(p));
    return a;
}
#define SW128(off) ((off) ^ (((off) >> 3) & 0x70))

__device__ __forceinline__ void ldsm_x4(uint32_t& r0, uint32_t& r1, uint32_t& r2, uint32_t& r3,
                                        uint32_t addr) {
    asm volatile("ldmatrix.sync.aligned.m8n8.x4.shared.b16 {%0,%1,%2,%3}, [%4];"
                 : "=r"(r0), "=r"(r1), "=r"(r2), "=r"(r3) : "r"(addr));
}
__device__ __forceinline__ void mma_f16(float* c, const uint32_t* a, const uint32_t* b) {
    asm volatile("mma.sync.aligned.m16n8k16.row.col.f32.f16.f16.f32 "
                 "{%0,%1,%2,%3}, {%4,%5,%6,%7}, {%8,%9}, {%0,%1,%2,%3};"
                 : "+f"(c[0]), "+f"(c[1]), "+f"(c[2]), "+f"(c[3])
                 : "r"(a[0]), "r"(a[1]), "r"(a[2]), "r"(a[3]), "r"(b[0]), "r"(b[1]));
}
__device__ __forceinline__ void red_add4(float* p, float a, float b, float c, float d) {
    asm volatile("red.global.add.v4.f32 [%0], {%1, %2, %3, %4};"
                 :: "l"(p), "f"(a), "f"(b), "f"(c), "f"(d) : "memory");
}
__device__ __forceinline__ void cp_async16(uint32_t s, const void* g) {
    asm volatile("cp.async.cg.shared.global [%0], [%1], 16;" :: "r"(s), "l"(g));
}
#define CP_COMMIT() asm volatile("cp.async.commit_group;" ::: "memory")
#define CP_WAIT1()  asm volatile("cp.async.wait_group 1;" ::: "memory")
#define CP_WAIT0()  asm volatile("cp.async.wait_group 0;" ::: "memory")

__device__ __forceinline__ uint32_t pack_h2(float a, float b) {
    __half2 h = __floats2half2_rn(a, b);
    return *(uint32_t*)&h;
}
__device__ __forceinline__ void split_h16(float x, __half& h, __half& l) {
    h = __float2half_rn(x);
    l = __float2half_rn(x - __half2float(h));
}

// ========== device globals (no allocation; 128B-aligned — vector/cp.async accessed) ==========
__device__ __align__(128) __half g_objF[2][NOBJ * DD];
__device__ __align__(128) __half g_predF[2][NTRI * DD];
__device__ __align__(128) __half g_WacT[LL * N13 * DD];   // [l][n][k] n<1280: Wa; n>=1280: Wc
__device__ __align__(128) __half g_WbT[LL * N1 * DD];     // [l][n][k] Wb = W12 rows 256..511
__device__ __align__(128) __half g_W34T[LL * DD * HH];    // [l][n][k]
__device__ __align__(128) __half g_W2Thi[LL * N1 * HH];   // W2 transposed, fp16 hi plane
__device__ __align__(128) __half g_W2Tlo[LL * N1 * HH];   // fp16 lo plane
__device__ __align__(128) __half g_pooledF[NOBJ * HH];    // (pooled * inv) fp16
__device__ __align__(128) float g_P13[(long)NOBJ * N13];  // obj @ [Wa|Wc], fp32
__device__ __align__(128) float g_pooled[NOBJ * HH];
__device__ __align__(128) float g_b12[LL * N1];
__device__ __align__(128) float g_W34[LL * HH * DD];
__device__ __align__(128) float g_b34[LL * DD];
__device__ __align__(128) int   g_sidx[NTRI];
__device__ __align__(128) int   g_oidx[NTRI];
__device__ __align__(128) int   g_cnt[NOBJ];
__device__ __align__(128) float g_inv[NOBJ];

// ======================= small utility kernels =======================
__global__ void convert_kernel(const void* edges) {
    int i = blockIdx.x * blockDim.x + threadIdx.x;
    if (i >= NTRI) return;
    const int* e32 = (const int*)edges;
    int ok = 1;
    #pragma unroll
    for (int w = 1; w < 16; w += 2) ok &= (e32[w] == 0);
    int s, o;
    if (ok) {
        const long long* p = (const long long*)edges;
        s = (int)p[2 * i]; o = (int)p[2 * i + 1];
    } else {
        s = e32[2 * i]; o = e32[2 * i + 1];
    }
    g_sidx[i] = s; g_oidx[i] = o;
    atomicAdd(&g_cnt[s], 1);
    atomicAdd(&g_cnt[o], 1);
}
__global__ void inv_kernel() {
    int i = blockIdx.x * blockDim.x + threadIdx.x;
    if (i < NOBJ) {
        int c = g_cnt[i];
        g_inv[i] = 1.0f / (float)(c > 0 ? c : 1);
    }
}
__global__ void cvt_obj_kernel(const float* __restrict__ src) {
    int i = blockIdx.x * blockDim.x + threadIdx.x;
    if (i < NOBJ * DD / 2) {
        float2 v = ((const float2*)src)[i];
        ((uint32_t*)g_objF[0])[i] = pack_h2(v.x, v.y);
    }
}
__global__ void cvt_pred_kernel(const float* __restrict__ src) {
    int i = blockIdx.x * blockDim.x + threadIdx.x;
    if (i < NTRI * DD / 2) {
        float2 v = ((const float2*)src)[i];
        ((uint32_t*)g_predF[0])[i] = pack_h2(v.x, v.y);
    }
}
// pooledF = fp16(pooled * inv)
__global__ void cvt_pooled_kernel() {
    int i = blockIdx.x * blockDim.x + threadIdx.x;
    if (i < NOBJ * HH / 2) {
        float2 v = ((const float2*)g_pooled)[i];
        float inv = g_inv[(i * 2) >> 9];
        ((uint32_t*)g_pooledF)[i] = pack_h2(v.x * inv, v.y * inv);
    }
}
__global__ void bias12_kernel(const float* __restrict__ b1, const float* __restrict__ W2,
                              const float* __restrict__ b2) {
    int l = blockIdx.z;
    int c = blockIdx.x * blockDim.x + threadIdx.x;
    if (c >= N1) return;
    const float* b1l = b1 + l * HH;
    const float* W2l = W2 + (long)l * HH * N1;
    float s = b2[(long)l * N1 + c];
    for (int k = 0; k < HH; k++) s = fmaf(b1l[k], W2l[(long)k * N1 + c], s);
    g_b12[l * N1 + c] = s;
}
__global__ void bias34_kernel(const float* __restrict__ b3, const float* __restrict__ W4,
                              const float* __restrict__ b4) {
    int l = blockIdx.z;
    int c = blockIdx.x * blockDim.x + threadIdx.x;
    if (c >= DD) return;
    const float* b3l = b3 + l * HH;
    const float* W4l = W4 + (long)l * HH * DD;
    float s = b4[(long)l * DD + c];
    for (int k = 0; k < HH; k++) s = fmaf(b3l[k], W4l[(long)k * DD + c], s);
    g_b34[l * DD + c] = s;
}

// W2 [L][512][1280] fp32 -> W2T hi/lo fp16 planes [L][1280][512]
__global__ void transpose_w2hl_kernel(const float* __restrict__ W2) {
    __shared__ float tile[32][33];
    int l = blockIdx.z;
    const float* src = W2 + (long)l * HH * N1;
    __half* Hp = g_W2Thi + (long)l * N1 * HH;
    __half* Lp = g_W2Tlo + (long)l * N1 * HH;
    int k0 = blockIdx.x * 32;
    int n0 = blockIdx.y * 32;
    int tx = threadIdx.x, ty = threadIdx.y;
    #pragma unroll
    for (int i = 0; i < 32; i += 8)
        tile[ty + i][tx] = src[(long)(k0 + ty + i) * N1 + n0 + tx];
    __syncthreads();
    #pragma unroll
    for (int i = 0; i < 32; i += 8) {
        float v = tile[tx][ty + i];
        __half h, lo; split_h16(v, h, lo);
        long o = (long)(n0 + ty + i) * HH + k0 + tx;
        Hp[o] = h; Lp[o] = lo;
    }
}

// W34 composite [L][512][256] fp32 -> W34T fp16 [L][256][512]
__global__ void transpose_w34_kernel() {
    __shared__ float tile[32][33];
    int l = blockIdx.z;
    const float* src = g_W34 + (long)l * HH * DD;
    __half* Hp = g_W34T + (long)l * DD * HH;
    int k0 = blockIdx.x * 32;
    int n0 = blockIdx.y * 32;
    int tx = threadIdx.x, ty = threadIdx.y;
    #pragma unroll
    for (int i = 0; i < 32; i += 8)
        tile[ty + i][tx] = src[(long)(k0 + ty + i) * DD + n0 + tx];
    __syncthreads();
    #pragma unroll
    for (int i = 0; i < 32; i += 8) {
        float v = tile[tx][ty + i];
        Hp[(long)(n0 + ty + i) * HH + k0 + tx] = __float2half_rn(v);
    }
}

// ---------------- fp32 prep GEMM (W34 composite only; small) ----------------
__global__ __launch_bounds__(256, 2)
void sgemm_prep(const float* __restrict__ A, const float* __restrict__ B,
                int M, int N, int K) {
    float* C = g_W34;
    long z = blockIdx.z;
    A += z * (long)M * K; B += z * (long)K * N; C += z * (long)M * N;
    __shared__ float As[16][128];
    __shared__ float Bs[16][128];
    int tid = threadIdx.x;
    int tx = tid & 15, ty = tid >> 4;
    int blockRow = blockIdx.y * 128, blockCol = blockIdx.x * 128;
    float acc[8][8];
    #pragma unroll
    for (int i = 0; i < 8; i++)
        #pragma unroll
        for (int j = 0; j < 8; j++) acc[i][j] = 0.f;
    int lr = tid >> 1, lc = (tid & 1) * 8;
    int br = tid >> 4, bc = (tid & 15) * 8;
    for (int k0 = 0; k0 < K; k0 += 16) {
        int gr = blockRow + lr;
        float4 a0, a1;
        if (gr < M) {
            const float* rp = A + (long)gr * K + k0;
            a0 = *(const float4*)(rp + lc); a1 = *(const float4*)(rp + lc + 4);
        } else { a0 = make_float4(0,0,0,0); a1 = a0; }
        As[lc+0][lr]=a0.x; As[lc+1][lr]=a0.y; As[lc+2][lr]=a0.z; As[lc+3][lr]=a0.w;
        As[lc+4][lr]=a1.x; As[lc+5][lr]=a1.y; As[lc+6][lr]=a1.z; As[lc+7][lr]=a1.w;
        const float* bp = B + (long)(k0 + br) * N + blockCol + bc;
        *(float4*)&Bs[br][bc]     = *(const float4*)bp;
        *(float4*)&Bs[br][bc + 4] = *(const float4*)(bp + 4);
        __syncthreads();
        #pragma unroll
        for (int k = 0; k < 16; k++) {
            float4 x0 = *(float4*)&As[k][ty * 8];
            float4 x1 = *(float4*)&As[k][ty * 8 + 4];
            float4 y0 = *(float4*)&Bs[k][tx * 8];
            float4 y1 = *(float4*)&Bs[k][tx * 8 + 4];
            float ra[8] = {x0.x,x0.y,x0.z,x0.w,x1.x,x1.y,x1.z,x1.w};
            float rb[8] = {y0.x,y0.y,y0.z,y0.w,y1.x,y1.y,y1.z,y1.w};
            #pragma unroll
            for (int i = 0; i < 8; i++)
                #pragma unroll
                for (int j = 0; j < 8; j++) acc[i][j] = fmaf(ra[i], rb[j], acc[i][j]);
        }
        __syncthreads();
    }
    #pragma unroll
    for (int i = 0; i < 8; i++) {
        int gr = blockRow + ty * 8 + i;
        if (gr >= M) continue;
        #pragma unroll
        for (int j = 0; j < 8; j++) {
            int gc = blockCol + tx * 8 + j;
            if (gc < N) C[(long)gr * N + gc] = acc[i][j];
        }
    }
}

// ======================= fp16 MMA cores =======================
#define MM_SMEMP (1024 + 1024 + 2 * 32768)      // mainloop kernels: 2 stages of 32KB
#define PRE_SMEM (1024 + 129 * 128 * 4)         // prep16: 4 planes (64KB) overlaid by Cs(129-stride)

#define MMA_COMPUTE_CHUNK()                                                          \
    _Pragma("unroll")                                                                \
    for (int ks = 0; ks < 4; ks++) {                                                 \
        uint32_t af[2][4];                                                           \
        _Pragma("unroll")                                                            \
        for (int mt = 0; mt < 2; mt++) {                                             \
            int mrow = warpM * 32 + mt * 16 + (lane & 15);                           \
            uint32_t cb = (uint32_t)(ks * 32) + ((lane >> 4) << 4);                  \
            uint32_t ad = SW128((uint32_t)(mrow * 128) + cb);                        \
            ldsm_x4(af[mt][0], af[mt][1], af[mt][2], af[mt][3], uA + ad);            \
        }                                                                            \
        _Pragma("unroll")                                                            \
        for (int np = 0; np < 4; np++) {                                             \
            int nrow = warpN * 64 + np * 16 + (lane & 7) + ((lane >> 4) << 3);       \
            uint32_t cb = (uint32_t)(ks * 32) + (((lane >> 3) & 1) << 4);            \
            uint32_t bd = SW128((uint32_t)(nrow * 128) + cb);                        \
            uint32_t bf[4];                                                          \
            ldsm_x4(bf[0], bf[1], bf[2], bf[3], uB + bd);                            \
            _Pragma("unroll")                                                        \
            for (int mt = 0; mt < 2; mt++)                                           \
                _Pragma("unroll")                                                    \
                for (int s = 0; s < 2; s++)                                          \
                    mma_f16(acc[mt][np * 2 + s], af[mt], bf + s * 2);                \
        }                                                                            \
    }

// 3-term compensated (hi/lo planes both sides; drops lo*lo)
#define MMA_COMPUTE_CHUNK3()                                                         \
    _Pragma("unroll")                                                                \
    for (int ks = 0; ks < 4; ks++) {                                                 \
        uint32_t ah[2][4], al[2][4];                                                 \
        _Pragma("unroll")                                                            \
        for (int mt = 0; mt < 2; mt++) {                                             \
            int mrow = warpM * 32 + mt * 16 + (lane & 15);                           \
            uint32_t cb = (uint32_t)(ks * 32) + ((lane >> 4) << 4);                  \
            uint32_t ad = SW128((uint32_t)(mrow * 128) + cb);                        \
            ldsm_x4(ah[mt][0], ah[mt][1], ah[mt][2], ah[mt][3], uAh + ad);           \
            ldsm_x4(al[mt][0], al[mt][1], al[mt][2], al[mt][3], uAl + ad);           \
        }                                                                            \
        _Pragma("unroll")                                                            \
        for (int np = 0; np < 4; np++) {                                             \
            int nrow = warpN * 64 + np * 16 + (lane & 7) + ((lane >> 4) << 3);       \
            uint32_t cb = (uint32_t)(ks * 32) + (((lane >> 3) & 1) << 4);            \
            uint32_t bd = SW128((uint32_t)(nrow * 128) + cb);                        \
            uint32_t bh[4], bl[4];                                                   \
            ldsm_x4(bh[0], bh[1], bh[2], bh[3], uBh + bd);                           \
            ldsm_x4(bl[0], bl[1], bl[2], bl[3], uBl + bd);                           \
            _Pragma("unroll")                                                        \
            for (int mt = 0; mt < 2; mt++)                                           \
                _Pragma("unroll")                                                    \
                for (int s = 0; s < 2; s++) {                                        \
                    float* c = acc[mt][np * 2 + s];                                  \
                    mma_f16(c, ah[mt], bh + s * 2);                                  \
                    mma_f16(c, ah[mt], bl + s * 2);                                  \
                    mma_f16(c, al[mt], bh + s * 2);                                  \
                }                                                                    \
        }                                                                            \
    }

#define MMA_STAGE_C()                                                                \
    _Pragma("unroll")                                                                \
    for (int mt = 0; mt < 2; mt++)                                                   \
        _Pragma("unroll")                                                            \
        for (int nt = 0; nt < 8; nt++) {                                             \
            int r0 = warpM * 32 + mt * 16 + (lane >> 2);                             \
            int cc = warpN * 64 + nt * 8 + (lane & 3) * 2;                           \
            float* c = acc[mt][nt];                                                  \
            *(float2*)&Cs[r0 * 128 + cc]       = make_float2(c[0], c[1]);            \
            *(float2*)&Cs[(r0 + 8) * 128 + cc] = make_float2(c[2], c[3]);            \
        }

// cp.async fill of one 32KB stage (A rows linear+clamped, B weight rows), K-stride Kstr_
#define PIPE_FILL(stg, c0_, srcF_, Mmax_, Kstr_)                                     \
    do {                                                                             \
        uint32_t sb_ = stage0 + (uint32_t)(stg) * 32768u;                            \
        _Pragma("unroll")                                                            \
        for (int it = 0; it < 4; it++) {                                             \
            int idx = tid + it * 256;                                                \
            int row = idx >> 3, q = idx & 7;                                         \
            int gr = blockRow + row; if (gr >= (Mmax_)) gr = (Mmax_) - 1;            \
            uint32_t d_ = sb_ + SW128((uint32_t)(row * 128 + q * 16));               \
            cp_async16(d_, (const char*)((srcF_) + (long)gr * (Kstr_) + (c0_)) + q * 16); \
            long bo_ = (long)(blockCol + row) * (Kstr_) + (c0_);                     \
            cp_async16(d_ + 16384u, (const char*)(WT + bo_) + q * 16);               \
        }                                                                            \
    } while (0)

// ====== gemm_prep16: W12 = W1@W2 (fp16x3), epilogue writes transposed WacT/WbT fp16 ======
// M=768 (y=6), N=1280 (x=10), K=512, z=layer. A = W1 fp32 (cvt+split in fill), B = W2T hi/lo.
__global__ __launch_bounds__(256)
void gemm_prep16(const float* __restrict__ W1) {
    extern __shared__ char smem[];
    uint32_t raw  = smem_u32(smem);
    uint32_t base = (raw + 1023u) & ~1023u;
    char* pal = smem + (base - raw);
    const uint32_t uAh = base, uAl = base + 16384u, uBh = base + 32768u, uBl = base + 49152u;
    char* pAh = pal; char* pAl = pAh + 16384; char* pBh = pAl + 16384; char* pBl = pBh + 16384;

    int tid = threadIdx.x;
    int wid = tid >> 5, lane = tid & 31;
    int warpM = wid & 3, warpN = wid >> 2;
    int l = blockIdx.z;
    int blockRow = blockIdx.y * 128;   // m (768)
    int blockCol = blockIdx.x * 128;   // n (1280)

    const float* W1l = W1 + (long)l * K1 * HH;
    const __half* W2h = g_W2Thi + (long)l * N1 * HH;
    const __half* W2l_ = g_W2Tlo + (long)l * N1 * HH;

    float acc[2][8][4];
    #pragma unroll
    for (int a = 0; a < 2; a++)
        #pragma unroll
        for (int b = 0; b < 8; b++)
            #pragma unroll
            for (int c = 0; c < 4; c++) acc[a][b][c] = 0.f;

    for (int ck = 0; ck < HH / KCH; ck++) {   // 8 chunks
        int c0 = ck * KCH;
        #pragma unroll
        for (int it = 0; it < 4; it++) {
            int idx = tid + it * 256;
            int row = idx >> 3, q = idx & 7;
            // A: W1 fp32 -> hi/lo fp16 (16B-aligned staging)
            const float* ap = W1l + (long)(blockRow + row) * HH + c0 + q * 8;
            float4 f0 = *(const float4*)ap;
            float4 f1 = *(const float4*)(ap + 4);
            __align__(16) __half h[8];
            __align__(16) __half lo[8];
            split_h16(f0.x, h[0], lo[0]); split_h16(f0.y, h[1], lo[1]);
            split_h16(f0.z, h[2], lo[2]); split_h16(f0.w, h[3], lo[3]);
            split_h16(f1.x, h[4], lo[4]); split_h16(f1.y, h[5], lo[5]);
            split_h16(f1.z, h[6], lo[6]); split_h16(f1.w, h[7], lo[7]);
            uint32_t d = SW128((uint32_t)(row * 128 + q * 16));
            *(uint4*)(pAh + d) = *(uint4*)h;
            *(uint4*)(pAl + d) = *(uint4*)lo;
            // B: precomputed fp16 planes
            long bo = (long)(blockCol + row) * HH + c0;
            *(uint4*)(pBh + d) = ((const uint4*)(W2h + bo))[q];
            *(uint4*)(pBl + d) = ((const uint4*)(W2l_ + bo))[q];
        }
        __syncthreads();
        MMA_COMPUTE_CHUNK3();
        __syncthreads();
    }

    // stage C with 129-stride (conflict-free column reads).
    // SCALAR stores only: odd stride 129 makes r0*129+cc odd for odd r0, so a
    // float2 (STS.64) here is a misaligned-address trap — the round-11..14 bug.
    float* Cs = (float*)pal;
    #pragma unroll
    for (int mt = 0; mt < 2; mt++)
        #pragma unroll
        for (int nt = 0; nt < 8; nt++) {
            int r0 = warpM * 32 + mt * 16 + (lane >> 2);
            int cc = warpN * 64 + nt * 8 + (lane & 3) * 2;
            float* c = acc[mt][nt];
            Cs[r0 * 129 + cc]           = c[0];
            Cs[r0 * 129 + cc + 1]       = c[1];
            Cs[(r0 + 8) * 129 + cc]     = c[2];
            Cs[(r0 + 8) * 129 + cc + 1] = c[3];
        }
    __syncthreads();

    // transposed fp16 write: W12[m][n] -> WacT/WbT [n][k]
    {
        int c  = tid >> 1;             // local n
        int kp = (tid & 1) * 64;       // k half
        int n_global = blockCol + c;
        __half* dst;
        if (blockRow < 256)
            dst = g_WacT + (long)l * N13 * DD + (long)n_global * DD + blockRow + kp;
        else if (blockRow < 512)
            dst = g_WbT + (long)l * N1 * DD + (long)n_global * DD + (blockRow - 256) + kp;
        else
            dst = g_WacT + (long)l * N13 * DD + (long)(N1 + n_global) * DD + (blockRow - 512) + kp;
        #pragma unroll
        for (int i = 0; i < 64; i += 8) {
            __align__(16) __half h[8];
            #pragma unroll
            for (int j = 0; j < 8; j++)
                h[j] = __float2half_rn(Cs[(kp + i + j) * 129 + c]);
            *(uint4*)(dst + i) = *(uint4*)h;
        }
    }
}

// ================ gemmP13: P13 = obj @ [Wa|Wc]   (M=NOBJ, N=2560, K=256) ================
__global__ __launch_bounds__(256)
void gemmP13(int srcBuf, int layer) {
    extern __shared__ char smem[];
    uint32_t raw  = smem_u32(smem);
    uint32_t base = (raw + 1023u) & ~1023u;
    const uint32_t stage0 = base + 1024;

    int tid = threadIdx.x;
    int wid = tid >> 5, lane = tid & 31;
    int warpM = wid & 3, warpN = wid >> 2;
    int blockRow = blockIdx.y * 128;
    int blockCol = blockIdx.x * 128;

    const __half* aF = g_objF[srcBuf];
    const __half* WT = g_WacT + (long)layer * N13 * DD;

    float acc[2][8][4];
    #pragma unroll
    for (int a = 0; a < 2; a++)
        #pragma unroll
        for (int b = 0; b < 8; b++)
            #pragma unroll
            for (int c = 0; c < 4; c++) acc[a][b][c] = 0.f;

    const int NCH = DD / KCH;   // 4
    PIPE_FILL(0, 0, aF, NOBJ, DD);
    CP_COMMIT();
    for (int ck = 0; ck < NCH; ck++) {
        int cur = ck & 1;
        if (ck + 1 < NCH) {
            PIPE_FILL((ck + 1) & 1, (ck + 1) * KCH, aF, NOBJ, DD);
            CP_COMMIT();
            CP_WAIT1();
        } else {
            CP_WAIT0();
        }
        __syncthreads();
        uint32_t sb = stage0 + (uint32_t)cur * 32768u;
        uint32_t uA = sb, uB = sb + 16384u;
        MMA_COMPUTE_CHUNK();
        __syncthreads();
    }

    // direct epilogue: acc -> global (8B-aligned float2 per pair)
    #pragma unroll
    for (int mt = 0; mt < 2; mt++) {
        int r0 = blockRow + warpM * 32 + mt * 16 + (lane >> 2);
        #pragma unroll
        for (int nt = 0; nt < 8; nt++) {
            int gc = blockCol + warpN * 64 + nt * 8 + (lane & 3) * 2;
            float* c = acc[mt][nt];
            if (r0 < NOBJ)
                *(float2*)&g_P13[(long)r0 * N13 + gc] = make_float2(c[0], c[1]);
            if (r0 + 8 < NOBJ)
                *(float2*)&g_P13[(long)(r0 + 8) * N13 + gc] = make_float2(c[2], c[3]);
        }
    }
}

// ========== gemmP2: new_t = pred@Wb + P13[s] + P13[o,+N1] + b12, fused scatter ==========
__global__ __launch_bounds__(256)
void gemmP2(int srcBuf, int layer, int last, float* __restrict__ predExtOut) {
    extern __shared__ char smem[];
    uint32_t raw  = smem_u32(smem);
    uint32_t base = (raw + 1023u) & ~1023u;
    char* pal = smem + (base - raw);
    int* sIdxS = (int*)(pal);
    int* oIdxS = (int*)(pal + 512);
    const uint32_t stage0 = base + 1024;

    int tid = threadIdx.x;
    int wid = tid >> 5, lane = tid & 31;
    int warpM = wid & 3, warpN = wid >> 2;
    int blockRow = blockIdx.y * 128;
    int blockCol = blockIdx.x * 128;

    const __half* aF = g_predF[srcBuf];
    const __half* WT = g_WbT + (long)layer * N1 * DD;

    if (tid < 128) {
        int gr = blockRow + tid; if (gr >= NTRI) gr = NTRI - 1;
        sIdxS[tid] = g_sidx[gr];
        oIdxS[tid] = g_oidx[gr];
    }

    float acc[2][8][4];
    #pragma unroll
    for (int a = 0; a < 2; a++)
        #pragma unroll
        for (int b = 0; b < 8; b++)
            #pragma unroll
            for (int c = 0; c < 4; c++) acc[a][b][c] = 0.f;

    const int NCH = DD / KCH;   // 4
    PIPE_FILL(0, 0, aF, NTRI, DD);
    CP_COMMIT();
    for (int ck = 0; ck < NCH; ck++) {
        int cur = ck & 1;
        if (ck + 1 < NCH) {
            PIPE_FILL((ck + 1) & 1, (ck + 1) * KCH, aF, NTRI, DD);
            CP_COMMIT();
            CP_WAIT1();
        } else {
            CP_WAIT0();
        }
        __syncthreads();
        uint32_t sb = stage0 + (uint32_t)cur * 32768u;
        uint32_t uA = sb, uB = sb + 16384u;
        MMA_COMPUTE_CHUNK();
        __syncthreads();
    }

    float* Cs = (float*)(pal + 1024);
    MMA_STAGE_C();
    __syncthreads();

    const float* biasL = g_b12 + layer * N1;
    __half* pOut = g_predF[srcBuf ^ 1];
    #pragma unroll
    for (int i = 0; i < 16; i++) {
        int f = tid + i * 256;
        int row = f >> 5;
        int c4 = (f & 31) << 2;
        int gr = blockRow + row;
        if (gr >= NTRI) continue;
        int sI = sIdxS[row], oI = oIdxS[row];
        int gc0 = blockCol + c4;
        float4 v  = *(float4*)&Cs[row * 128 + c4];
        float4 bb = *(const float4*)&biasL[gc0];
        float4 ps = *(const float4*)&g_P13[(long)sI * N13 + gc0];
        float4 po = *(const float4*)&g_P13[(long)oI * N13 + N1 + gc0];
        v.x += bb.x + ps.x + po.x;
        v.y += bb.y + ps.y + po.y;
        v.z += bb.z + ps.z + po.z;
        v.w += bb.w + ps.w + po.w;
        if (gc0 < HH) {
            red_add4(&g_pooled[(long)sI * HH + gc0], v.x, v.y, v.z, v.w);
        } else if (gc0 < HH + DD) {
            int pc = gc0 - HH;
            if (last) {
                *(float4*)&predExtOut[(long)gr * DD + pc] = v;
            } else {
                *(uint2*)(pOut + (long)gr * DD + pc) =
                    make_uint2(pack_h2(v.x, v.y), pack_h2(v.z, v.w));
            }
        } else {
            red_add4(&g_pooled[(long)oI * HH + (gc0 - HH - DD)], v.x, v.y, v.z, v.w);
        }
    }
}

// ====== gemmB: obj' = pooledF @ W34 + b34 (M=NOBJ, N=256, K=512, pipelined fp16) ======
__global__ __launch_bounds__(256)
void gemmB_mma(int layer, int dstBuf, int last, float* __restrict__ objExtOut) {
    extern __shared__ char smem[];
    uint32_t raw  = smem_u32(smem);
    uint32_t base = (raw + 1023u) & ~1023u;
    char* pal = smem + (base - raw);
    const uint32_t stage0 = base + 1024;

    int tid = threadIdx.x;
    int wid = tid >> 5, lane = tid & 31;
    int warpM = wid & 3, warpN = wid >> 2;
    int blockRow = blockIdx.y * 128;
    int blockCol = blockIdx.x * 128;

    const __half* aF = g_pooledF;
    const __half* WT = g_W34T + (long)layer * DD * HH;

    float acc[2][8][4];
    #pragma unroll
    for (int a = 0; a < 2; a++)
        #pragma unroll
        for (int b = 0; b < 8; b++)
            #pragma unroll
            for (int c = 0; c < 4; c++) acc[a][b][c] = 0.f;

    const int NCH = HH / KCH;   // 8
    PIPE_FILL(0, 0, aF, NOBJ, HH);
    CP_COMMIT();
    for (int ck = 0; ck < NCH; ck++) {
        int cur = ck & 1;
        if (ck + 1 < NCH) {
            PIPE_FILL((ck + 1) & 1, (ck + 1) * KCH, aF, NOBJ, HH);
            CP_COMMIT();
            CP_WAIT1();
        } else {
            CP_WAIT0();
        }
        __syncthreads();
        uint32_t sb = stage0 + (uint32_t)cur * 32768u;
        uint32_t uA = sb, uB = sb + 16384u;
        MMA_COMPUTE_CHUNK();
        __syncthreads();
    }

    float* Cs = (float*)(pal + 1024);
    MMA_STAGE_C();
    __syncthreads();

    const float* biasL = g_b34 + layer * DD;
    __half* oOut = g_objF[dstBuf];
    #pragma unroll
    for (int i = 0; i < 16; i++) {
        int f = tid + i * 256;
        int row = f >> 5;
        int c4 = (f & 31) << 2;
        int gr = blockRow + row;
        if (gr >= NOBJ) continue;
        int gc0 = blockCol + c4;
        float4 v = *(float4*)&Cs[row * 128 + c4];
        float4 bb = *(const float4*)&biasL[gc0];
        v.x += bb.x; v.y += bb.y; v.z += bb.z; v.w += bb.w;
        if (last) {
            *(float4*)&objExtOut[(long)gr * DD + gc0] = v;
        } else {
            *(uint2*)(oOut + (long)gr * DD + gc0) =
                make_uint2(pack_h2(v.x, v.y), pack_h2(v.z, v.w));
        }
    }
}

// ======================= launcher =======================
extern "C" void kernel_launch(void* const* d_in, const int* in_sizes, int n_in,
                              void* d_out, int out_size) {
    const float* obj_in  = (const float*)d_in[0];
    const float* pred_in = (const float*)d_in[1];
    const void*  edges   = d_in[2];
    const float* W1 = (const float*)d_in[3];
    const float* b1 = (const float*)d_in[4];
    const float* W2 = (const float*)d_in[5];
    const float* b2 = (const float*)d_in[6];
    const float* W3 = (const float*)d_in[7];
    const float* b3 = (const float*)d_in[8];
    const float* W4 = (const float*)d_in[9];
    const float* b4 = (const float*)d_in[10];

    float* out_obj  = (float*)d_out;                     // [20000, 256]
    float* out_pred = (float*)d_out + (long)NOBJ * DD;   // [60000, 256]

    static int attr_done = 0;
    static void *cnt_addr = nullptr, *pooled_addr = nullptr;
    if (!attr_done) {
        cudaFuncSetAttribute(gemmP13,    cudaFuncAttributeMaxDynamicSharedMemorySize, MM_SMEMP);
        cudaFuncSetAttribute(gemmP2,     cudaFuncAttributeMaxDynamicSharedMemorySize, MM_SMEMP);
        cudaFuncSetAttribute(gemmB_mma,  cudaFuncAttributeMaxDynamicSharedMemorySize, MM_SMEMP);
        cudaFuncSetAttribute(gemm_prep16, cudaFuncAttributeMaxDynamicSharedMemorySize, PRE_SMEM);
        cudaGetSymbolAddress(&cnt_addr, g_cnt);
        cudaGetSymbolAddress(&pooled_addr, g_pooled);
        attr_done = 1;
    }

    dim3 gridP13(N13 / 128, cdiv_h(NOBJ, 128));  // (20, 157)
    dim3 gridP2(N1 / 128, cdiv_h(NTRI, 128));    // (10, 469)
    dim3 gridB(DD / 128, cdiv_h(NOBJ, 128));     // (2, 157)

    // ---- launches 1-3: minimal chain so launch 4 = gemmP13 (ncu capture slot) ----
    transpose_w2hl_kernel<<<dim3(HH / 32, N1 / 32, LL), dim3(32, 8)>>>(W2);         // 1
    gemm_prep16<<<dim3(N1 / 128, K1 / 128, LL), 256, PRE_SMEM>>>(W1);               // 2
    cvt_obj_kernel<<<cdiv_h(NOBJ * DD / 2, 256), 256>>>(obj_in);                    // 3
    gemmP13<<<gridP13, 256, MM_SMEMP>>>(0, 0);                                      // 4 (profiled)

    // ---- remaining prep ----
    cudaMemsetAsync(cnt_addr, 0, NOBJ * sizeof(int));
    convert_kernel<<<cdiv_h(NTRI, 256), 256>>>(edges);
    inv_kernel<<<cdiv_h(NOBJ, 256), 256>>>();
    sgemm_prep<<<dim3(DD / 128, HH / 128, LL), 256>>>(W3, W4, HH, DD, HH);
    transpose_w34_kernel<<<dim3(HH / 32, DD / 32, LL), dim3(32, 8)>>>();
    bias12_kernel<<<dim3(cdiv_h(N1, 256), 1, LL), 256>>>(b1, W2, b2);
    bias34_kernel<<<dim3(cdiv_h(DD, 256), 1, LL), 256>>>(b3, W4, b4);
    cvt_pred_kernel<<<cdiv_h(NTRI * DD / 2, 256), 256>>>(pred_in);

    // ---- layer 0 (P13 already computed) ----
    cudaMemsetAsync(pooled_addr, 0, (size_t)NOBJ * HH * sizeof(float));
    gemmP2<<<gridP2, 256, MM_SMEMP>>>(0, 0, 0, nullptr);
    cvt_pooled_kernel<<<cdiv_h(NOBJ * HH / 2, 256), 256>>>();
    gemmB_mma<<<gridB, 256, MM_SMEMP>>>(0, 1, 0, nullptr);

    // ---- layers 1..4 ----
    for (int l = 1; l < LL; l++) {
        int src = l & 1, dst = src ^ 1, last = (l == LL - 1);
        cudaMemsetAsync(pooled_addr, 0, (size_t)NOBJ * HH * sizeof(float));
        gemmP13<<<gridP13, 256, MM_SMEMP>>>(src, l);
        gemmP2<<<gridP2, 256, MM_SMEMP>>>(src, l, last, out_pred);
        cvt_pooled_kernel<<<cdiv_h(NOBJ * HH / 2, 256), 256>>>();
        gemmB_mma<<<gridB, 256, MM_SMEMP>>>(l, dst, last, out_obj);
    }
}

// round 16
// speedup vs baseline: 6.3017x; 1.0308x over previous
#include <cuda_runtime.h>
#include <cuda_fp16.h>
#include <cstdint>

#define NOBJ 20000
#define NTRI 60000
#define DD   256
#define HH   512
#define LL   5
#define K1   768    // 3*D
#define N1   1280   // 2H+D
#define N13  2560   // 2*N1  (P13 = obj @ [Wa|Wc])
#define KCH  64     // K chunk per SMEM stage

static inline int cdiv_h(int a, int b) { return (a + b - 1) / b; }

// ======================= PTX helpers =======================
__device__ __forceinline__ uint32_t smem_u32(const void* p) {
    uint32_t a;
    asm("{ .reg .u64 t; cvta.to.shared.u64 t, %1; cvt.u32.u64 %0, t; }" : "=r"(a) : "l"(p));
    return a;
}
#define SW128(off) ((off) ^ (((off) >> 3) & 0x70))

__device__ __forceinline__ void ldsm_x4(uint32_t& r0, uint32_t& r1, uint32_t& r2, uint32_t& r3,
                                        uint32_t addr) {
    asm volatile("ldmatrix.sync.aligned.m8n8.x4.shared.b16 {%0,%1,%2,%3}, [%4];"
                 : "=r"(r0), "=r"(r1), "=r"(r2), "=r"(r3) : "r"(addr));
}
__device__ __forceinline__ void mma_f16(float* c, const uint32_t* a, const uint32_t* b) {
    asm volatile("mma.sync.aligned.m16n8k16.row.col.f32.f16.f16.f32 "
                 "{%0,%1,%2,%3}, {%4,%5,%6,%7}, {%8,%9}, {%0,%1,%2,%3};"
                 : "+f"(c[0]), "+f"(c[1]), "+f"(c[2]), "+f"(c[3])
                 : "r"(a[0]), "r"(a[1]), "r"(a[2]), "r"(a[3]), "r"(b[0]), "r"(b[1]));
}
__device__ __forceinline__ void red_add4(float* p, float a, float b, float c, float d) {
    asm volatile("red.global.add.v4.f32 [%0], {%1, %2, %3, %4};"
                 :: "l"(p), "f"(a), "f"(b), "f"(c), "f"(d) : "memory");
}
__device__ __forceinline__ void cp_async16(uint32_t s, const void* g) {
    asm volatile("cp.async.cg.shared.global [%0], [%1], 16;" :: "r"(s), "l"(g));
}
#define CP_COMMIT() asm volatile("cp.async.commit_group;" ::: "memory")
#define CP_WAIT1()  asm volatile("cp.async.wait_group 1;" ::: "memory")
#define CP_WAIT0()  asm volatile("cp.async.wait_group 0;" ::: "memory")

__device__ __forceinline__ uint32_t pack_h2(float a, float b) {
    __half2 h = __floats2half2_rn(a, b);
    return *(uint32_t*)&h;
}
__device__ __forceinline__ void split_h16(float x, __half& h, __half& l) {
    h = __float2half_rn(x);
    l = __float2half_rn(x - __half2float(h));
}

// ========== device globals (no allocation; 128B-aligned — vector/cp.async accessed) ==========
__device__ __align__(128) __half g_objF[2][NOBJ * DD];
__device__ __align__(128) __half g_predF[2][NTRI * DD];
__device__ __align__(128) __half g_WacT[LL * N13 * DD];   // [l][n][k] n<1280: Wa; n>=1280: Wc
__device__ __align__(128) __half g_WbT[LL * N1 * DD];     // [l][n][k] Wb = W12 rows 256..511
__device__ __align__(128) __half g_W34T[LL * DD * HH];    // [l][n][k]
__device__ __align__(128) __half g_W2Thi[LL * N1 * HH];   // W2 transposed, fp16 hi plane
__device__ __align__(128) __half g_W2Tlo[LL * N1 * HH];   // fp16 lo plane
__device__ __align__(128) __half g_pooledF[NOBJ * HH];    // (pooled * inv) fp16
__device__ __align__(128) float g_P13[(long)NOBJ * N13];  // obj @ [Wa|Wc], fp32
__device__ __align__(128) float g_pooled[NOBJ * HH];
__device__ __align__(128) float g_b12[LL * N1];
__device__ __align__(128) float g_W34[LL * HH * DD];
__device__ __align__(128) float g_b34[LL * DD];
__device__ __align__(128) int   g_sidx[NTRI];
__device__ __align__(128) int   g_oidx[NTRI];
__device__ __align__(128) int   g_cnt[NOBJ];
__device__ __align__(128) float g_inv[NOBJ];

// ======================= small utility kernels =======================
__global__ void convert_kernel(const void* edges) {
    int i = blockIdx.x * blockDim.x + threadIdx.x;
    if (i >= NTRI) return;
    const int* e32 = (const int*)edges;
    int ok = 1;
    #pragma unroll
    for (int w = 1; w < 16; w += 2) ok &= (e32[w] == 0);
    int s, o;
    if (ok) {
        const long long* p = (const long long*)edges;
        s = (int)p[2 * i]; o = (int)p[2 * i + 1];
    } else {
        s = e32[2 * i]; o = e32[2 * i + 1];
    }
    g_sidx[i] = s; g_oidx[i] = o;
    atomicAdd(&g_cnt[s], 1);
    atomicAdd(&g_cnt[o], 1);
}
__global__ void inv_kernel() {
    int i = blockIdx.x * blockDim.x + threadIdx.x;
    if (i < NOBJ) {
        int c = g_cnt[i];
        g_inv[i] = 1.0f / (float)(c > 0 ? c : 1);
    }
}
__global__ void cvt_obj_kernel(const float* __restrict__ src) {
    int i = blockIdx.x * blockDim.x + threadIdx.x;
    if (i < NOBJ * DD / 2) {
        float2 v = ((const float2*)src)[i];
        ((uint32_t*)g_objF[0])[i] = pack_h2(v.x, v.y);
    }
}
__global__ void cvt_pred_kernel(const float* __restrict__ src) {
    int i = blockIdx.x * blockDim.x + threadIdx.x;
    if (i < NTRI * DD / 2) {
        float2 v = ((const float2*)src)[i];
        ((uint32_t*)g_predF[0])[i] = pack_h2(v.x, v.y);
    }
}
// pooledF = fp16(pooled * inv)
__global__ void cvt_pooled_kernel() {
    int i = blockIdx.x * blockDim.x + threadIdx.x;
    if (i < NOBJ * HH / 2) {
        float2 v = ((const float2*)g_pooled)[i];
        float inv = g_inv[(i * 2) >> 9];
        ((uint32_t*)g_pooledF)[i] = pack_h2(v.x * inv, v.y * inv);
    }
}
__global__ void bias12_kernel(const float* __restrict__ b1, const float* __restrict__ W2,
                              const float* __restrict__ b2) {
    int l = blockIdx.z;
    int c = blockIdx.x * blockDim.x + threadIdx.x;
    if (c >= N1) return;
    const float* b1l = b1 + l * HH;
    const float* W2l = W2 + (long)l * HH * N1;
    float s = b2[(long)l * N1 + c];
    for (int k = 0; k < HH; k++) s = fmaf(b1l[k], W2l[(long)k * N1 + c], s);
    g_b12[l * N1 + c] = s;
}
__global__ void bias34_kernel(const float* __restrict__ b3, const float* __restrict__ W4,
                              const float* __restrict__ b4) {
    int l = blockIdx.z;
    int c = blockIdx.x * blockDim.x + threadIdx.x;
    if (c >= DD) return;
    const float* b3l = b3 + l * HH;
    const float* W4l = W4 + (long)l * HH * DD;
    float s = b4[(long)l * DD + c];
    for (int k = 0; k < HH; k++) s = fmaf(b3l[k], W4l[(long)k * DD + c], s);
    g_b34[l * DD + c] = s;
}

// W2 [L][512][1280] fp32 -> W2T hi/lo fp16 planes [L][1280][512]
__global__ void transpose_w2hl_kernel(const float* __restrict__ W2) {
    __shared__ float tile[32][33];
    int l = blockIdx.z;
    const float* src = W2 + (long)l * HH * N1;
    __half* Hp = g_W2Thi + (long)l * N1 * HH;
    __half* Lp = g_W2Tlo + (long)l * N1 * HH;
    int k0 = blockIdx.x * 32;
    int n0 = blockIdx.y * 32;
    int tx = threadIdx.x, ty = threadIdx.y;
    #pragma unroll
    for (int i = 0; i < 32; i += 8)
        tile[ty + i][tx] = src[(long)(k0 + ty + i) * N1 + n0 + tx];
    __syncthreads();
    #pragma unroll
    for (int i = 0; i < 32; i += 8) {
        float v = tile[tx][ty + i];
        __half h, lo; split_h16(v, h, lo);
        long o = (long)(n0 + ty + i) * HH + k0 + tx;
        Hp[o] = h; Lp[o] = lo;
    }
}

// W34 composite [L][512][256] fp32 -> W34T fp16 [L][256][512]
__global__ void transpose_w34_kernel() {
    __shared__ float tile[32][33];
    int l = blockIdx.z;
    const float* src = g_W34 + (long)l * HH * DD;
    __half* Hp = g_W34T + (long)l * DD * HH;
    int k0 = blockIdx.x * 32;
    int n0 = blockIdx.y * 32;
    int tx = threadIdx.x, ty = threadIdx.y;
    #pragma unroll
    for (int i = 0; i < 32; i += 8)
        tile[ty + i][tx] = src[(long)(k0 + ty + i) * DD + n0 + tx];
    __syncthreads();
    #pragma unroll
    for (int i = 0; i < 32; i += 8) {
        float v = tile[tx][ty + i];
        Hp[(long)(n0 + ty + i) * HH + k0 + tx] = __float2half_rn(v);
    }
}

// ---------------- fp32 prep GEMM (W34 composite only; small) ----------------
__global__ __launch_bounds__(256, 2)
void sgemm_prep(const float* __restrict__ A, const float* __restrict__ B,
                int M, int N, int K) {
    float* C = g_W34;
    long z = blockIdx.z;
    A += z * (long)M * K; B += z * (long)K * N; C += z * (long)M * N;
    __shared__ float As[16][128];
    __shared__ float Bs[16][128];
    int tid = threadIdx.x;
    int tx = tid & 15, ty = tid >> 4;
    int blockRow = blockIdx.y * 128, blockCol = blockIdx.x * 128;
    float acc[8][8];
    #pragma unroll
    for (int i = 0; i < 8; i++)
        #pragma unroll
        for (int j = 0; j < 8; j++) acc[i][j] = 0.f;
    int lr = tid >> 1, lc = (tid & 1) * 8;
    int br = tid >> 4, bc = (tid & 15) * 8;
    for (int k0 = 0; k0 < K; k0 += 16) {
        int gr = blockRow + lr;
        float4 a0, a1;
        if (gr < M) {
            const float* rp = A + (long)gr * K + k0;
            a0 = *(const float4*)(rp + lc); a1 = *(const float4*)(rp + lc + 4);
        } else { a0 = make_float4(0,0,0,0); a1 = a0; }
        As[lc+0][lr]=a0.x; As[lc+1][lr]=a0.y; As[lc+2][lr]=a0.z; As[lc+3][lr]=a0.w;
        As[lc+4][lr]=a1.x; As[lc+5][lr]=a1.y; As[lc+6][lr]=a1.z; As[lc+7][lr]=a1.w;
        const float* bp = B + (long)(k0 + br) * N + blockCol + bc;
        *(float4*)&Bs[br][bc]     = *(const float4*)bp;
        *(float4*)&Bs[br][bc + 4] = *(const float4*)(bp + 4);
        __syncthreads();
        #pragma unroll
        for (int k = 0; k < 16; k++) {
            float4 x0 = *(float4*)&As[k][ty * 8];
            float4 x1 = *(float4*)&As[k][ty * 8 + 4];
            float4 y0 = *(float4*)&Bs[k][tx * 8];
            float4 y1 = *(float4*)&Bs[k][tx * 8 + 4];
            float ra[8] = {x0.x,x0.y,x0.z,x0.w,x1.x,x1.y,x1.z,x1.w};
            float rb[8] = {y0.x,y0.y,y0.z,y0.w,y1.x,y1.y,y1.z,y1.w};
            #pragma unroll
            for (int i = 0; i < 8; i++)
                #pragma unroll
                for (int j = 0; j < 8; j++) acc[i][j] = fmaf(ra[i], rb[j], acc[i][j]);
        }
        __syncthreads();
    }
    #pragma unroll
    for (int i = 0; i < 8; i++) {
        int gr = blockRow + ty * 8 + i;
        if (gr >= M) continue;
        #pragma unroll
        for (int j = 0; j < 8; j++) {
            int gc = blockCol + tx * 8 + j;
            if (gc < N) C[(long)gr * N + gc] = acc[i][j];
        }
    }
}

// ======================= fp16 MMA cores =======================
#define MM_SMEMP (1024 + 1024 + 2 * 32768)      // mainloop kernels: 2 stages of 32KB
#define PRE_SMEM (1024 + 129 * 128 * 4)         // prep16: 4 planes (64KB) overlaid by Cs(129-stride)

#define MMA_COMPUTE_CHUNK()                                                          \
    _Pragma("unroll")                                                                \
    for (int ks = 0; ks < 4; ks++) {                                                 \
        uint32_t af[2][4];                                                           \
        _Pragma("unroll")                                                            \
        for (int mt = 0; mt < 2; mt++) {                                             \
            int mrow = warpM * 32 + mt * 16 + (lane & 15);                           \
            uint32_t cb = (uint32_t)(ks * 32) + ((lane >> 4) << 4);                  \
            uint32_t ad = SW128((uint32_t)(mrow * 128) + cb);                        \
            ldsm_x4(af[mt][0], af[mt][1], af[mt][2], af[mt][3], uA + ad);            \
        }                                                                            \
        _Pragma("unroll")                                                            \
        for (int np = 0; np < 4; np++) {                                             \
            int nrow = warpN * 64 + np * 16 + (lane & 7) + ((lane >> 4) << 3);       \
            uint32_t cb = (uint32_t)(ks * 32) + (((lane >> 3) & 1) << 4);            \
            uint32_t bd = SW128((uint32_t)(nrow * 128) + cb);                        \
            uint32_t bf[4];                                                          \
            ldsm_x4(bf[0], bf[1], bf[2], bf[3], uB + bd);                            \
            _Pragma("unroll")                                                        \
            for (int mt = 0; mt < 2; mt++)                                           \
                _Pragma("unroll")                                                    \
                for (int s = 0; s < 2; s++)                                          \
                    mma_f16(acc[mt][np * 2 + s], af[mt], bf + s * 2);                \
        }                                                                            \
    }

// 3-term compensated (hi/lo planes both sides; drops lo*lo)
#define MMA_COMPUTE_CHUNK3()                                                         \
    _Pragma("unroll")                                                                \
    for (int ks = 0; ks < 4; ks++) {                                                 \
        uint32_t ah[2][4], al[2][4];                                                 \
        _Pragma("unroll")                                                            \
        for (int mt = 0; mt < 2; mt++) {                                             \
            int mrow = warpM * 32 + mt * 16 + (lane & 15);                           \
            uint32_t cb = (uint32_t)(ks * 32) + ((lane >> 4) << 4);                  \
            uint32_t ad = SW128((uint32_t)(mrow * 128) + cb);                        \
            ldsm_x4(ah[mt][0], ah[mt][1], ah[mt][2], ah[mt][3], uAh + ad);           \
            ldsm_x4(al[mt][0], al[mt][1], al[mt][2], al[mt][3], uAl + ad);           \
        }                                                                            \
        _Pragma("unroll")                                                            \
        for (int np = 0; np < 4; np++) {                                             \
            int nrow = warpN * 64 + np * 16 + (lane & 7) + ((lane >> 4) << 3);       \
            uint32_t cb = (uint32_t)(ks * 32) + (((lane >> 3) & 1) << 4);            \
            uint32_t bd = SW128((uint32_t)(nrow * 128) + cb);                        \
            uint32_t bh[4], bl[4];                                                   \
            ldsm_x4(bh[0], bh[1], bh[2], bh[3], uBh + bd);                           \
            ldsm_x4(bl[0], bl[1], bl[2], bl[3], uBl + bd);                           \
            _Pragma("unroll")                                                        \
            for (int mt = 0; mt < 2; mt++)                                           \
                _Pragma("unroll")                                                    \
                for (int s = 0; s < 2; s++) {                                        \
                    float* c = acc[mt][np * 2 + s];                                  \
                    mma_f16(c, ah[mt], bh + s * 2);                                  \
                    mma_f16(c, ah[mt], bl + s * 2);                                  \
                    mma_f16(c, al[mt], bh + s * 2);                                  \
                }                                                                    \
        }                                                                            \
    }

#define MMA_STAGE_C()                                                                \
    _Pragma("unroll")                                                                \
    for (int mt = 0; mt < 2; mt++)                                                   \
        _Pragma("unroll")                                                            \
        for (int nt = 0; nt < 8; nt++) {                                             \
            int r0 = warpM * 32 + mt * 16 + (lane >> 2);                             \
            int cc = warpN * 64 + nt * 8 + (lane & 3) * 2;                           \
            float* c = acc[mt][nt];                                                  \
            *(float2*)&Cs[r0 * 128 + cc]       = make_float2(c[0], c[1]);            \
            *(float2*)&Cs[(r0 + 8) * 128 + cc] = make_float2(c[2], c[3]);            \
        }

// cp.async fill of one 32KB stage (A rows linear+clamped, B weight rows), K-stride Kstr_
#define PIPE_FILL(stg, c0_, srcF_, Mmax_, Kstr_)                                     \
    do {                                                                             \
        uint32_t sb_ = stage0 + (uint32_t)(stg) * 32768u;                            \
        _Pragma("unroll")                                                            \
        for (int it = 0; it < 4; it++) {                                             \
            int idx = tid + it * 256;                                                \
            int row = idx >> 3, q = idx & 7;                                         \
            int gr = blockRow + row; if (gr >= (Mmax_)) gr = (Mmax_) - 1;            \
            uint32_t d_ = sb_ + SW128((uint32_t)(row * 128 + q * 16));               \
            cp_async16(d_, (const char*)((srcF_) + (long)gr * (Kstr_) + (c0_)) + q * 16); \
            long bo_ = (long)(blockCol + row) * (Kstr_) + (c0_);                     \
            cp_async16(d_ + 16384u, (const char*)(WT + bo_) + q * 16);               \
        }                                                                            \
    } while (0)

// ====== gemm_prep16: W12 = W1@W2 (fp16x3), epilogue writes transposed WacT/WbT fp16 ======
// M=768 (y=6), N=1280 (x=10), K=512, z=layer. A = W1 fp32 (cvt+split in fill), B = W2T hi/lo.
__global__ __launch_bounds__(256)
void gemm_prep16(const float* __restrict__ W1) {
    extern __shared__ char smem[];
    uint32_t raw  = smem_u32(smem);
    uint32_t base = (raw + 1023u) & ~1023u;
    char* pal = smem + (base - raw);
    const uint32_t uAh = base, uAl = base + 16384u, uBh = base + 32768u, uBl = base + 49152u;
    char* pAh = pal; char* pAl = pAh + 16384; char* pBh = pAl + 16384; char* pBl = pBh + 16384;

    int tid = threadIdx.x;
    int wid = tid >> 5, lane = tid & 31;
    int warpM = wid & 3, warpN = wid >> 2;
    int l = blockIdx.z;
    int blockRow = blockIdx.y * 128;   // m (768)
    int blockCol = blockIdx.x * 128;   // n (1280)

    const float* W1l = W1 + (long)l * K1 * HH;
    const __half* W2h = g_W2Thi + (long)l * N1 * HH;
    const __half* W2l_ = g_W2Tlo + (long)l * N1 * HH;

    float acc[2][8][4];
    #pragma unroll
    for (int a = 0; a < 2; a++)
        #pragma unroll
        for (int b = 0; b < 8; b++)
            #pragma unroll
            for (int c = 0; c < 4; c++) acc[a][b][c] = 0.f;

    for (int ck = 0; ck < HH / KCH; ck++) {   // 8 chunks
        int c0 = ck * KCH;
        #pragma unroll
        for (int it = 0; it < 4; it++) {
            int idx = tid + it * 256;
            int row = idx >> 3, q = idx & 7;
            // A: W1 fp32 -> hi/lo fp16 (16B-aligned staging)
            const float* ap = W1l + (long)(blockRow + row) * HH + c0 + q * 8;
            float4 f0 = *(const float4*)ap;
            float4 f1 = *(const float4*)(ap + 4);
            __align__(16) __half h[8];
            __align__(16) __half lo[8];
            split_h16(f0.x, h[0], lo[0]); split_h16(f0.y, h[1], lo[1]);
            split_h16(f0.z, h[2], lo[2]); split_h16(f0.w, h[3], lo[3]);
            split_h16(f1.x, h[4], lo[4]); split_h16(f1.y, h[5], lo[5]);
            split_h16(f1.z, h[6], lo[6]); split_h16(f1.w, h[7], lo[7]);
            uint32_t d = SW128((uint32_t)(row * 128 + q * 16));
            *(uint4*)(pAh + d) = *(uint4*)h;
            *(uint4*)(pAl + d) = *(uint4*)lo;
            // B: precomputed fp16 planes
            long bo = (long)(blockCol + row) * HH + c0;
            *(uint4*)(pBh + d) = ((const uint4*)(W2h + bo))[q];
            *(uint4*)(pBl + d) = ((const uint4*)(W2l_ + bo))[q];
        }
        __syncthreads();
        MMA_COMPUTE_CHUNK3();
        __syncthreads();
    }

    // stage C with 129-stride (conflict-free column reads).
    // SCALAR stores only: odd stride 129 makes r0*129+cc odd for odd r0, so a
    // float2 (STS.64) here is a misaligned-address trap — the round-11..14 bug.
    float* Cs = (float*)pal;
    #pragma unroll
    for (int mt = 0; mt < 2; mt++)
        #pragma unroll
        for (int nt = 0; nt < 8; nt++) {
            int r0 = warpM * 32 + mt * 16 + (lane >> 2);
            int cc = warpN * 64 + nt * 8 + (lane & 3) * 2;
            float* c = acc[mt][nt];
            Cs[r0 * 129 + cc]           = c[0];
            Cs[r0 * 129 + cc + 1]       = c[1];
            Cs[(r0 + 8) * 129 + cc]     = c[2];
            Cs[(r0 + 8) * 129 + cc + 1] = c[3];
        }
    __syncthreads();

    // transposed fp16 write: W12[m][n] -> WacT/WbT [n][k]
    {
        int c  = tid >> 1;             // local n
        int kp = (tid & 1) * 64;       // k half
        int n_global = blockCol + c;
        __half* dst;
        if (blockRow < 256)
            dst = g_WacT + (long)l * N13 * DD + (long)n_global * DD + blockRow + kp;
        else if (blockRow < 512)
            dst = g_WbT + (long)l * N1 * DD + (long)n_global * DD + (blockRow - 256) + kp;
        else
            dst = g_WacT + (long)l * N13 * DD + (long)(N1 + n_global) * DD + (blockRow - 512) + kp;
        #pragma unroll
        for (int i = 0; i < 64; i += 8) {
            __align__(16) __half h[8];
            #pragma unroll
            for (int j = 0; j < 8; j++)
                h[j] = __float2half_rn(Cs[(kp + i + j) * 129 + c]);
            *(uint4*)(dst + i) = *(uint4*)h;
        }
    }
}

// ================ gemmP13: P13 = obj @ [Wa|Wc]   (M=NOBJ, N=2560, K=256) ================
__global__ __launch_bounds__(256, 2)
void gemmP13(int srcBuf, int layer) {
    extern __shared__ char smem[];
    uint32_t raw  = smem_u32(smem);
    uint32_t base = (raw + 1023u) & ~1023u;
    const uint32_t stage0 = base + 1024;

    int tid = threadIdx.x;
    int wid = tid >> 5, lane = tid & 31;
    int warpM = wid & 3, warpN = wid >> 2;
    int blockRow = blockIdx.y * 128;
    int blockCol = blockIdx.x * 128;

    const __half* aF = g_objF[srcBuf];
    const __half* WT = g_WacT + (long)layer * N13 * DD;

    float acc[2][8][4];
    #pragma unroll
    for (int a = 0; a < 2; a++)
        #pragma unroll
        for (int b = 0; b < 8; b++)
            #pragma unroll
            for (int c = 0; c < 4; c++) acc[a][b][c] = 0.f;

    const int NCH = DD / KCH;   // 4
    PIPE_FILL(0, 0, aF, NOBJ, DD);
    CP_COMMIT();
    for (int ck = 0; ck < NCH; ck++) {
        int cur = ck & 1;
        if (ck + 1 < NCH) {
            PIPE_FILL((ck + 1) & 1, (ck + 1) * KCH, aF, NOBJ, DD);
            CP_COMMIT();
            CP_WAIT1();
        } else {
            CP_WAIT0();
        }
        __syncthreads();
        uint32_t sb = stage0 + (uint32_t)cur * 32768u;
        uint32_t uA = sb, uB = sb + 16384u;
        MMA_COMPUTE_CHUNK();
        __syncthreads();
    }

    // direct epilogue: acc -> global (8B-aligned float2 per pair)
    #pragma unroll
    for (int mt = 0; mt < 2; mt++) {
        int r0 = blockRow + warpM * 32 + mt * 16 + (lane >> 2);
        #pragma unroll
        for (int nt = 0; nt < 8; nt++) {
            int gc = blockCol + warpN * 64 + nt * 8 + (lane & 3) * 2;
            float* c = acc[mt][nt];
            if (r0 < NOBJ)
                *(float2*)&g_P13[(long)r0 * N13 + gc] = make_float2(c[0], c[1]);
            if (r0 + 8 < NOBJ)
                *(float2*)&g_P13[(long)(r0 + 8) * N13 + gc] = make_float2(c[2], c[3]);
        }
    }
}

// ========== gemmP2: new_t = pred@Wb + P13[s] + P13[o,+N1] + b12, fused scatter ==========
__global__ __launch_bounds__(256, 2)
void gemmP2(int srcBuf, int layer, int last, float* __restrict__ predExtOut) {
    extern __shared__ char smem[];
    uint32_t raw  = smem_u32(smem);
    uint32_t base = (raw + 1023u) & ~1023u;
    char* pal = smem + (base - raw);
    int* sIdxS = (int*)(pal);
    int* oIdxS = (int*)(pal + 512);
    const uint32_t stage0 = base + 1024;

    int tid = threadIdx.x;
    int wid = tid >> 5, lane = tid & 31;
    int warpM = wid & 3, warpN = wid >> 2;
    int blockRow = blockIdx.y * 128;
    int blockCol = blockIdx.x * 128;

    const __half* aF = g_predF[srcBuf];
    const __half* WT = g_WbT + (long)layer * N1 * DD;

    if (tid < 128) {
        int gr = blockRow + tid; if (gr >= NTRI) gr = NTRI - 1;
        sIdxS[tid] = g_sidx[gr];
        oIdxS[tid] = g_oidx[gr];
    }

    float acc[2][8][4];
    #pragma unroll
    for (int a = 0; a < 2; a++)
        #pragma unroll
        for (int b = 0; b < 8; b++)
            #pragma unroll
            for (int c = 0; c < 4; c++) acc[a][b][c] = 0.f;

    const int NCH = DD / KCH;   // 4
    PIPE_FILL(0, 0, aF, NTRI, DD);
    CP_COMMIT();
    for (int ck = 0; ck < NCH; ck++) {
        int cur = ck & 1;
        if (ck + 1 < NCH) {
            PIPE_FILL((ck + 1) & 1, (ck + 1) * KCH, aF, NTRI, DD);
            CP_COMMIT();
            CP_WAIT1();
        } else {
            CP_WAIT0();
        }
        __syncthreads();
        uint32_t sb = stage0 + (uint32_t)cur * 32768u;
        uint32_t uA = sb, uB = sb + 16384u;
        MMA_COMPUTE_CHUNK();
        __syncthreads();
    }

    float* Cs = (float*)(pal + 1024);
    MMA_STAGE_C();
    __syncthreads();

    const float* biasL = g_b12 + layer * N1;
    __half* pOut = g_predF[srcBuf ^ 1];
    #pragma unroll
    for (int i = 0; i < 16; i++) {
        int f = tid + i * 256;
        int row = f >> 5;
        int c4 = (f & 31) << 2;
        int gr = blockRow + row;
        if (gr >= NTRI) continue;
        int sI = sIdxS[row], oI = oIdxS[row];
        int gc0 = blockCol + c4;
        float4 v  = *(float4*)&Cs[row * 128 + c4];
        float4 bb = *(const float4*)&biasL[gc0];
        float4 ps = *(const float4*)&g_P13[(long)sI * N13 + gc0];
        float4 po = *(const float4*)&g_P13[(long)oI * N13 + N1 + gc0];
        v.x += bb.x + ps.x + po.x;
        v.y += bb.y + ps.y + po.y;
        v.z += bb.z + ps.z + po.z;
        v.w += bb.w + ps.w + po.w;
        if (gc0 < HH) {
            red_add4(&g_pooled[(long)sI * HH + gc0], v.x, v.y, v.z, v.w);
        } else if (gc0 < HH + DD) {
            int pc = gc0 - HH;
            if (last) {
                *(float4*)&predExtOut[(long)gr * DD + pc] = v;
            } else {
                *(uint2*)(pOut + (long)gr * DD + pc) =
                    make_uint2(pack_h2(v.x, v.y), pack_h2(v.z, v.w));
            }
        } else {
            red_add4(&g_pooled[(long)oI * HH + (gc0 - HH - DD)], v.x, v.y, v.z, v.w);
        }
    }
}

// ====== gemmB: obj' = pooledF @ W34 + b34 (M=NOBJ, N=256, K=512, pipelined fp16) ======
__global__ __launch_bounds__(256, 2)
void gemmB_mma(int layer, int dstBuf, int last, float* __restrict__ objExtOut) {
    extern __shared__ char smem[];
    uint32_t raw  = smem_u32(smem);
    uint32_t base = (raw + 1023u) & ~1023u;
    char* pal = smem + (base - raw);
    const uint32_t stage0 = base + 1024;

    int tid = threadIdx.x;
    int wid = tid >> 5, lane = tid & 31;
    int warpM = wid & 3, warpN = wid >> 2;
    int blockRow = blockIdx.y * 128;
    int blockCol = blockIdx.x * 128;

    const __half* aF = g_pooledF;
    const __half* WT = g_W34T + (long)layer * DD * HH;

    float acc[2][8][4];
    #pragma unroll
    for (int a = 0; a < 2; a++)
        #pragma unroll
        for (int b = 0; b < 8; b++)
            #pragma unroll
            for (int c = 0; c < 4; c++) acc[a][b][c] = 0.f;

    const int NCH = HH / KCH;   // 8
    PIPE_FILL(0, 0, aF, NOBJ, HH);
    CP_COMMIT();
    for (int ck = 0; ck < NCH; ck++) {
        int cur = ck & 1;
        if (ck + 1 < NCH) {
            PIPE_FILL((ck + 1) & 1, (ck + 1) * KCH, aF, NOBJ, HH);
            CP_COMMIT();
            CP_WAIT1();
        } else {
            CP_WAIT0();
        }
        __syncthreads();
        uint32_t sb = stage0 + (uint32_t)cur * 32768u;
        uint32_t uA = sb, uB = sb + 16384u;
        MMA_COMPUTE_CHUNK();
        __syncthreads();
    }

    float* Cs = (float*)(pal + 1024);
    MMA_STAGE_C();
    __syncthreads();

    const float* biasL = g_b34 + layer * DD;
    __half* oOut = g_objF[dstBuf];
    #pragma unroll
    for (int i = 0; i < 16; i++) {
        int f = tid + i * 256;
        int row = f >> 5;
        int c4 = (f & 31) << 2;
        int gr = blockRow + row;
        if (gr >= NOBJ) continue;
        int gc0 = blockCol + c4;
        float4 v = *(float4*)&Cs[row * 128 + c4];
        float4 bb = *(const float4*)&biasL[gc0];
        v.x += bb.x; v.y += bb.y; v.z += bb.z; v.w += bb.w;
        if (last) {
            *(float4*)&objExtOut[(long)gr * DD + gc0] = v;
        } else {
            *(uint2*)(oOut + (long)gr * DD + gc0) =
                make_uint2(pack_h2(v.x, v.y), pack_h2(v.z, v.w));
        }
    }
}

// ======================= launcher =======================
extern "C" void kernel_launch(void* const* d_in, const int* in_sizes, int n_in,
                              void* d_out, int out_size) {
    const float* obj_in  = (const float*)d_in[0];
    const float* pred_in = (const float*)d_in[1];
    const void*  edges   = d_in[2];
    const float* W1 = (const float*)d_in[3];
    const float* b1 = (const float*)d_in[4];
    const float* W2 = (const float*)d_in[5];
    const float* b2 = (const float*)d_in[6];
    const float* W3 = (const float*)d_in[7];
    const float* b3 = (const float*)d_in[8];
    const float* W4 = (const float*)d_in[9];
    const float* b4 = (const float*)d_in[10];

    float* out_obj  = (float*)d_out;                     // [20000, 256]
    float* out_pred = (float*)d_out + (long)NOBJ * DD;   // [60000, 256]

    static int attr_done = 0;
    static void *cnt_addr = nullptr, *pooled_addr = nullptr;
    if (!attr_done) {
        cudaFuncSetAttribute(gemmP13,    cudaFuncAttributeMaxDynamicSharedMemorySize, MM_SMEMP);
        cudaFuncSetAttribute(gemmP2,     cudaFuncAttributeMaxDynamicSharedMemorySize, MM_SMEMP);
        cudaFuncSetAttribute(gemmB_mma,  cudaFuncAttributeMaxDynamicSharedMemorySize, MM_SMEMP);
        cudaFuncSetAttribute(gemm_prep16, cudaFuncAttributeMaxDynamicSharedMemorySize, PRE_SMEM);
        cudaGetSymbolAddress(&cnt_addr, g_cnt);
        cudaGetSymbolAddress(&pooled_addr, g_pooled);
        attr_done = 1;
    }

    dim3 gridP13(N13 / 128, cdiv_h(NOBJ, 128));  // (20, 157)
    dim3 gridP2(N1 / 128, cdiv_h(NTRI, 128));    // (10, 469)
    dim3 gridB(DD / 128, cdiv_h(NOBJ, 128));     // (2, 157)

    // ---- launches 1-3: minimal chain so launch 4 = gemmP13 (ncu capture slot) ----
    transpose_w2hl_kernel<<<dim3(HH / 32, N1 / 32, LL), dim3(32, 8)>>>(W2);         // 1
    gemm_prep16<<<dim3(N1 / 128, K1 / 128, LL), 256, PRE_SMEM>>>(W1);               // 2
    cvt_obj_kernel<<<cdiv_h(NOBJ * DD / 2, 256), 256>>>(obj_in);                    // 3
    gemmP13<<<gridP13, 256, MM_SMEMP>>>(0, 0);                                      // 4 (profiled)

    // ---- remaining prep ----
    cudaMemsetAsync(cnt_addr, 0, NOBJ * sizeof(int));
    convert_kernel<<<cdiv_h(NTRI, 256), 256>>>(edges);
    inv_kernel<<<cdiv_h(NOBJ, 256), 256>>>();
    sgemm_prep<<<dim3(DD / 128, HH / 128, LL), 256>>>(W3, W4, HH, DD, HH);
    transpose_w34_kernel<<<dim3(HH / 32, DD / 32, LL), dim3(32, 8)>>>();
    bias12_kernel<<<dim3(cdiv_h(N1, 256), 1, LL), 256>>>(b1, W2, b2);
    bias34_kernel<<<dim3(cdiv_h(DD, 256), 1, LL), 256>>>(b3, W4, b4);
    cvt_pred_kernel<<<cdiv_h(NTRI * DD / 2, 256), 256>>>(pred_in);

    // ---- layer 0 (P13 already computed) ----
    cudaMemsetAsync(pooled_addr, 0, (size_t)NOBJ * HH * sizeof(float));
    gemmP2<<<gridP2, 256, MM_SMEMP>>>(0, 0, 0, nullptr);
    cvt_pooled_kernel<<<cdiv_h(NOBJ * HH / 2, 256), 256>>>();
    gemmB_mma<<<gridB, 256, MM_SMEMP>>>(0, 1, 0, nullptr);

    // ---- layers 1..4 ----
    for (int l = 1; l < LL; l++) {
        int src = l & 1, dst = src ^ 1, last = (l == LL - 1);
        cudaMemsetAsync(pooled_addr, 0, (size_t)NOBJ * HH * sizeof(float));
        gemmP13<<<gridP13, 256, MM_SMEMP>>>(src, l);
        gemmP2<<<gridP2, 256, MM_SMEMP>>>(src, l, last, out_pred);
        cvt_pooled_kernel<<<cdiv_h(NOBJ * HH / 2, 256), 256>>>();
        gemmB_mma<<<gridB, 256, MM_SMEMP>>>(l, dst, last, out_obj);
    }
}

// round 17
// speedup vs baseline: 7.8383x; 1.2438x over previous
#include <cuda_runtime.h>
#include <cuda_fp16.h>
#include <cstdint>

#define NOBJ 20000
#define NTRI 60000
#define DD   256
#define HH   512
#define LL   5
#define K1   768
#define N1   1280
#define N13  1536   // P13 cols: Wa[0:768) | Wc[512:1280)
#define KAGG 1024   // aggregate K: [Ps|No|Ns|Po]
#define KCH  64

static inline int cdiv_h(int a, int b) { return (a + b - 1) / b; }

// ======================= PTX helpers =======================
__device__ __forceinline__ uint32_t smem_u32(const void* p) {
    uint32_t a;
    asm("{ .reg .u64 t; cvta.to.shared.u64 t, %1; cvt.u32.u64 %0, t; }" : "=r"(a) : "l"(p));
    return a;
}
#define SW128(off) ((off) ^ (((off) >> 3) & 0x70))

__device__ __forceinline__ void ldsm_x4(uint32_t& r0, uint32_t& r1, uint32_t& r2, uint32_t& r3,
                                        uint32_t addr) {
    asm volatile("ldmatrix.sync.aligned.m8n8.x4.shared.b16 {%0,%1,%2,%3}, [%4];"
                 : "=r"(r0), "=r"(r1), "=r"(r2), "=r"(r3) : "r"(addr));
}
__device__ __forceinline__ void mma_f16(float* c, const uint32_t* a, const uint32_t* b) {
    asm volatile("mma.sync.aligned.m16n8k16.row.col.f32.f16.f16.f32 "
                 "{%0,%1,%2,%3}, {%4,%5,%6,%7}, {%8,%9}, {%0,%1,%2,%3};"
                 : "+f"(c[0]), "+f"(c[1]), "+f"(c[2]), "+f"(c[3])
                 : "r"(a[0]), "r"(a[1]), "r"(a[2]), "r"(a[3]), "r"(b[0]), "r"(b[1]));
}
__device__ __forceinline__ void red_add4(float* p, float a, float b, float c, float d) {
    asm volatile("red.global.add.v4.f32 [%0], {%1, %2, %3, %4};"
                 :: "l"(p), "f"(a), "f"(b), "f"(c), "f"(d) : "memory");
}
__device__ __forceinline__ void cp_async16(uint32_t s, const void* g) {
    asm volatile("cp.async.cg.shared.global [%0], [%1], 16;" :: "r"(s), "l"(g));
}
#define CP_COMMIT() asm volatile("cp.async.commit_group;" ::: "memory")
#define CP_WAIT1()  asm volatile("cp.async.wait_group 1;" ::: "memory")
#define CP_WAIT0()  asm volatile("cp.async.wait_group 0;" ::: "memory")

__device__ __forceinline__ uint32_t pack_h2(float a, float b) {
    __half2 h = __floats2half2_rn(a, b);
    return *(uint32_t*)&h;
}
__device__ __forceinline__ void split_h16(float x, __half& h, __half& l) {
    h = __float2half_rn(x);
    l = __float2half_rn(x - __half2float(h));
}

// ========== device globals (no allocation; 128B-aligned) ==========
__device__ __align__(128) __half g_objF[2][NOBJ * DD];
__device__ __align__(128) __half g_predF[2][NTRI * DD];
__device__ __align__(128) __half g_W13T[LL * N13 * DD];    // [l][n][k] gemmP13 B
__device__ __align__(128) __half g_WpoolT[LL * HH * KAGG]; // [l][n][k] pool GEMM B
__device__ __align__(128) __half g_WbMidT[LL * DD * DD];   // [l][n][k] gemmP2 B (Wb cols 512..767)
__device__ __align__(128) __half g_W34T[LL * DD * HH];     // [l][n][k]
__device__ __align__(128) __half g_W2Thi[LL * N1 * HH];
__device__ __align__(128) __half g_W2Tlo[LL * N1 * HH];
__device__ __align__(128) __half g_pooledF[NOBJ * HH];
__device__ __align__(128) __half g_aggF[(long)NOBJ * KAGG];
__device__ __align__(128) float g_agg[(long)NOBJ * KAGG];
__device__ __align__(128) float g_P13[(long)NOBJ * N13];
__device__ __align__(128) float g_b12[LL * N1];
__device__ __align__(128) float g_W34[LL * HH * DD];
__device__ __align__(128) float g_b34[LL * DD];
__device__ __align__(128) int   g_sidx[NTRI];
__device__ __align__(128) int   g_oidx[NTRI];
__device__ __align__(128) int   g_degS[NOBJ];
__device__ __align__(128) int   g_degO[NOBJ];
__device__ __align__(128) float g_inv[NOBJ];

// ======================= small utility kernels =======================
__global__ void convert_kernel(const void* edges) {
    int i = blockIdx.x * blockDim.x + threadIdx.x;
    if (i >= NTRI) return;
    const int* e32 = (const int*)edges;
    int ok = 1;
    #pragma unroll
    for (int w = 1; w < 16; w += 2) ok &= (e32[w] == 0);
    int s, o;
    if (ok) {
        const long long* p = (const long long*)edges;
        s = (int)p[2 * i]; o = (int)p[2 * i + 1];
    } else {
        s = e32[2 * i]; o = e32[2 * i + 1];
    }
    g_sidx[i] = s; g_oidx[i] = o;
    atomicAdd(&g_degS[s], 1);
    atomicAdd(&g_degO[o], 1);
}
__global__ void inv_kernel() {
    int i = blockIdx.x * blockDim.x + threadIdx.x;
    if (i < NOBJ) {
        int c = g_degS[i] + g_degO[i];
        g_inv[i] = 1.0f / (float)(c > 0 ? c : 1);
    }
}
__global__ void cvt_obj_kernel(const float* __restrict__ src) {
    int i = blockIdx.x * blockDim.x + threadIdx.x;
    if (i < NOBJ * DD / 2) {
        float2 v = ((const float2*)src)[i];
        ((uint32_t*)g_objF[0])[i] = pack_h2(v.x, v.y);
    }
}
__global__ void cvt_pred_kernel(const float* __restrict__ src) {
    int i = blockIdx.x * blockDim.x + threadIdx.x;
    if (i < NTRI * DD / 2) {
        float2 v = ((const float2*)src)[i];
        ((uint32_t*)g_predF[0])[i] = pack_h2(v.x, v.y);
    }
}
// aggregate scatter: per (edge, seg, 4cols): Ps|No|Ns|Po
__global__ void agg_scatter(int srcBuf) {
    int i = blockIdx.x * blockDim.x + threadIdx.x;
    if (i >= NTRI * 256) return;
    int e = i >> 8, r = i & 255;
    int seg = r >> 6, c4 = (r & 63) << 2;
    int s = g_sidx[e], o = g_oidx[e];
    const __half* src;
    float* dst;
    if (seg == 0)      { src = g_predF[srcBuf] + (long)e * DD + c4; dst = g_agg + (long)s * KAGG + c4; }
    else if (seg == 1) { src = g_objF[srcBuf] + (long)o * DD + c4;  dst = g_agg + (long)s * KAGG + 256 + c4; }
    else if (seg == 2) { src = g_objF[srcBuf] + (long)s * DD + c4;  dst = g_agg + (long)o * KAGG + 512 + c4; }
    else               { src = g_predF[srcBuf] + (long)e * DD + c4; dst = g_agg + (long)o * KAGG + 768 + c4; }
    uint2 hv = *(const uint2*)src;
    float2 f0 = __half22float2(*(__half2*)&hv.x);
    float2 f1 = __half22float2(*(__half2*)&hv.y);
    red_add4(dst, f0.x, f0.y, f1.x, f1.y);
}
__global__ void cvt_agg_kernel() {
    int i = blockIdx.x * blockDim.x + threadIdx.x;
    if (i < NOBJ * KAGG / 2) {
        float2 v = ((const float2*)g_agg)[i];
        ((uint32_t*)g_aggF)[i] = pack_h2(v.x, v.y);
    }
}
__global__ void bias12_kernel(const float* __restrict__ b1, const float* __restrict__ W2,
                              const float* __restrict__ b2) {
    int l = blockIdx.z;
    int c = blockIdx.x * blockDim.x + threadIdx.x;
    if (c >= N1) return;
    const float* b1l = b1 + l * HH;
    const float* W2l = W2 + (long)l * HH * N1;
    float s = b2[(long)l * N1 + c];
    for (int k = 0; k < HH; k++) s = fmaf(b1l[k], W2l[(long)k * N1 + c], s);
    g_b12[l * N1 + c] = s;
}
__global__ void bias34_kernel(const float* __restrict__ b3, const float* __restrict__ W4,
                              const float* __restrict__ b4) {
    int l = blockIdx.z;
    int c = blockIdx.x * blockDim.x + threadIdx.x;
    if (c >= DD) return;
    const float* b3l = b3 + l * HH;
    const float* W4l = W4 + (long)l * HH * DD;
    float s = b4[(long)l * DD + c];
    for (int k = 0; k < HH; k++) s = fmaf(b3l[k], W4l[(long)k * DD + c], s);
    g_b34[l * DD + c] = s;
}
// W2 fp32 -> W2T hi/lo fp16 planes [L][1280][512]
__global__ void transpose_w2hl_kernel(const float* __restrict__ W2) {
    __shared__ float tile[32][33];
    int l = blockIdx.z;
    const float* src = W2 + (long)l * HH * N1;
    __half* Hp = g_W2Thi + (long)l * N1 * HH;
    __half* Lp = g_W2Tlo + (long)l * N1 * HH;
    int k0 = blockIdx.x * 32, n0 = blockIdx.y * 32;
    int tx = threadIdx.x, ty = threadIdx.y;
    #pragma unroll
    for (int i = 0; i < 32; i += 8)
        tile[ty + i][tx] = src[(long)(k0 + ty + i) * N1 + n0 + tx];
    __syncthreads();
    #pragma unroll
    for (int i = 0; i < 32; i += 8) {
        float v = tile[tx][ty + i];
        __half h, lo; split_h16(v, h, lo);
        long o = (long)(n0 + ty + i) * HH + k0 + tx;
        Hp[o] = h; Lp[o] = lo;
    }
}
// W34 composite fp32 -> W34T fp16 [L][256][512]
__global__ void transpose_w34_kernel() {
    __shared__ float tile[32][33];
    int l = blockIdx.z;
    const float* src = g_W34 + (long)l * HH * DD;
    __half* Hp = g_W34T + (long)l * DD * HH;
    int k0 = blockIdx.x * 32, n0 = blockIdx.y * 32;
    int tx = threadIdx.x, ty = threadIdx.y;
    #pragma unroll
    for (int i = 0; i < 32; i += 8)
        tile[ty + i][tx] = src[(long)(k0 + ty + i) * DD + n0 + tx];
    __syncthreads();
    #pragma unroll
    for (int i = 0; i < 32; i += 8) {
        float v = tile[tx][ty + i];
        Hp[(long)(n0 + ty + i) * HH + k0 + tx] = __float2half_rn(v);
    }
}

// ---------------- fp32 prep GEMM (W34 composite only) ----------------
__global__ __launch_bounds__(256, 2)
void sgemm_prep(const float* __restrict__ A, const float* __restrict__ B,
                int M, int N, int K) {
    float* C = g_W34;
    long z = blockIdx.z;
    A += z * (long)M * K; B += z * (long)K * N; C += z * (long)M * N;
    __shared__ float As[16][128];
    __shared__ float Bs[16][128];
    int tid = threadIdx.x;
    int tx = tid & 15, ty = tid >> 4;
    int blockRow = blockIdx.y * 128, blockCol = blockIdx.x * 128;
    float acc[8][8];
    #pragma unroll
    for (int i = 0; i < 8; i++)
        #pragma unroll
        for (int j = 0; j < 8; j++) acc[i][j] = 0.f;
    int lr = tid >> 1, lc = (tid & 1) * 8;
    int br = tid >> 4, bc = (tid & 15) * 8;
    for (int k0 = 0; k0 < K; k0 += 16) {
        int gr = blockRow + lr;
        float4 a0, a1;
        if (gr < M) {
            const float* rp = A + (long)gr * K + k0;
            a0 = *(const float4*)(rp + lc); a1 = *(const float4*)(rp + lc + 4);
        } else { a0 = make_float4(0,0,0,0); a1 = a0; }
        As[lc+0][lr]=a0.x; As[lc+1][lr]=a0.y; As[lc+2][lr]=a0.z; As[lc+3][lr]=a0.w;
        As[lc+4][lr]=a1.x; As[lc+5][lr]=a1.y; As[lc+6][lr]=a1.z; As[lc+7][lr]=a1.w;
        const float* bp = B + (long)(k0 + br) * N + blockCol + bc;
        *(float4*)&Bs[br][bc]     = *(const float4*)bp;
        *(float4*)&Bs[br][bc + 4] = *(const float4*)(bp + 4);
        __syncthreads();
        #pragma unroll
        for (int k = 0; k < 16; k++) {
            float4 x0 = *(float4*)&As[k][ty * 8];
            float4 x1 = *(float4*)&As[k][ty * 8 + 4];
            float4 y0 = *(float4*)&Bs[k][tx * 8];
            float4 y1 = *(float4*)&Bs[k][tx * 8 + 4];
            float ra[8] = {x0.x,x0.y,x0.z,x0.w,x1.x,x1.y,x1.z,x1.w};
            float rb[8] = {y0.x,y0.y,y0.z,y0.w,y1.x,y1.y,y1.z,y1.w};
            #pragma unroll
            for (int i = 0; i < 8; i++)
                #pragma unroll
                for (int j = 0; j < 8; j++) acc[i][j] = fmaf(ra[i], rb[j], acc[i][j]);
        }
        __syncthreads();
    }
    #pragma unroll
    for (int i = 0; i < 8; i++) {
        int gr = blockRow + ty * 8 + i;
        if (gr >= M) continue;
        #pragma unroll
        for (int j = 0; j < 8; j++) {
            int gc = blockCol + tx * 8 + j;
            if (gc < N) C[(long)gr * N + gc] = acc[i][j];
        }
    }
}

// ======================= fp16 MMA cores =======================
#define MM_SMEMP (1024 + 1024 + 2 * 32768)
#define PRE_SMEM (1024 + 129 * 128 * 4)

#define MMA_COMPUTE_CHUNK()                                                          \
    _Pragma("unroll")                                                                \
    for (int ks = 0; ks < 4; ks++) {                                                 \
        uint32_t af[2][4];                                                           \
        _Pragma("unroll")                                                            \
        for (int mt = 0; mt < 2; mt++) {                                             \
            int mrow = warpM * 32 + mt * 16 + (lane & 15);                           \
            uint32_t cb = (uint32_t)(ks * 32) + ((lane >> 4) << 4);                  \
            uint32_t ad = SW128((uint32_t)(mrow * 128) + cb);                        \
            ldsm_x4(af[mt][0], af[mt][1], af[mt][2], af[mt][3], uA + ad);            \
        }                                                                            \
        _Pragma("unroll")                                                            \
        for (int np = 0; np < 4; np++) {                                             \
            int nrow = warpN * 64 + np * 16 + (lane & 7) + ((lane >> 4) << 3);       \
            uint32_t cb = (uint32_t)(ks * 32) + (((lane >> 3) & 1) << 4);            \
            uint32_t bd = SW128((uint32_t)(nrow * 128) + cb);                        \
            uint32_t bf[4];                                                          \
            ldsm_x4(bf[0], bf[1], bf[2], bf[3], uB + bd);                            \
            _Pragma("unroll")                                                        \
            for (int mt = 0; mt < 2; mt++)                                           \
                _Pragma("unroll")                                                    \
                for (int s = 0; s < 2; s++)                                          \
                    mma_f16(acc[mt][np * 2 + s], af[mt], bf + s * 2);                \
        }                                                                            \
    }

#define MMA_COMPUTE_CHUNK3()                                                         \
    _Pragma("unroll")                                                                \
    for (int ks = 0; ks < 4; ks++) {                                                 \
        uint32_t ah[2][4], al[2][4];                                                 \
        _Pragma("unroll")                                                            \
        for (int mt = 0; mt < 2; mt++) {                                             \
            int mrow = warpM * 32 + mt * 16 + (lane & 15);                           \
            uint32_t cb = (uint32_t)(ks * 32) + ((lane >> 4) << 4);                  \
            uint32_t ad = SW128((uint32_t)(mrow * 128) + cb);                        \
            ldsm_x4(ah[mt][0], ah[mt][1], ah[mt][2], ah[mt][3], uAh + ad);           \
            ldsm_x4(al[mt][0], al[mt][1], al[mt][2], al[mt][3], uAl + ad);           \
        }                                                                            \
        _Pragma("unroll")                                                            \
        for (int np = 0; np < 4; np++) {                                             \
            int nrow = warpN * 64 + np * 16 + (lane & 7) + ((lane >> 4) << 3);       \
            uint32_t cb = (uint32_t)(ks * 32) + (((lane >> 3) & 1) << 4);            \
            uint32_t bd = SW128((uint32_t)(nrow * 128) + cb);                        \
            uint32_t bh[4], bl[4];                                                   \
            ldsm_x4(bh[0], bh[1], bh[2], bh[3], uBh + bd);                           \
            ldsm_x4(bl[0], bl[1], bl[2], bl[3], uBl + bd);                           \
            _Pragma("unroll")                                                        \
            for (int mt = 0; mt < 2; mt++)                                           \
                _Pragma("unroll")                                                    \
                for (int s = 0; s < 2; s++) {                                        \
                    float* c = acc[mt][np * 2 + s];                                  \
                    mma_f16(c, ah[mt], bh + s * 2);                                  \
                    mma_f16(c, ah[mt], bl + s * 2);                                  \
                    mma_f16(c, al[mt], bh + s * 2);                                  \
                }                                                                    \
        }                                                                            \
    }

#define MMA_STAGE_C()                                                                \
    _Pragma("unroll")                                                                \
    for (int mt = 0; mt < 2; mt++)                                                   \
        _Pragma("unroll")                                                            \
        for (int nt = 0; nt < 8; nt++) {                                             \
            int r0 = warpM * 32 + mt * 16 + (lane >> 2);                             \
            int cc = warpN * 64 + nt * 8 + (lane & 3) * 2;                           \
            float* c = acc[mt][nt];                                                  \
            *(float2*)&Cs[r0 * 128 + cc]       = make_float2(c[0], c[1]);            \
            *(float2*)&Cs[(r0 + 8) * 128 + cc] = make_float2(c[2], c[3]);            \
        }

#define PIPE_FILL(stg, c0_, srcF_, Mmax_, Kstr_)                                     \
    do {                                                                             \
        uint32_t sb_ = stage0 + (uint32_t)(stg) * 32768u;                            \
        _Pragma("unroll")                                                            \
        for (int it = 0; it < 4; it++) {                                             \
            int idx = tid + it * 256;                                                \
            int row = idx >> 3, q = idx & 7;                                         \
            int gr = blockRow + row; if (gr >= (Mmax_)) gr = (Mmax_) - 1;            \
            uint32_t d_ = sb_ + SW128((uint32_t)(row * 128 + q * 16));               \
            cp_async16(d_, (const char*)((srcF_) + (long)gr * (Kstr_) + (c0_)) + q * 16); \
            long bo_ = (long)(blockCol + row) * (Kstr_) + (c0_);                     \
            cp_async16(d_ + 16384u, (const char*)(WT + bo_) + q * 16);               \
        }                                                                            \
    } while (0)

#define MMA_PIPE_LOOP(NCH_, aF_, Mmax_, Kstr_)                                       \
    do {                                                                             \
        PIPE_FILL(0, 0, aF_, Mmax_, Kstr_);                                          \
        CP_COMMIT();                                                                 \
        for (int ck = 0; ck < (NCH_); ck++) {                                        \
            int cur = ck & 1;                                                        \
            if (ck + 1 < (NCH_)) {                                                   \
                PIPE_FILL((ck + 1) & 1, (ck + 1) * KCH, aF_, Mmax_, Kstr_);          \
                CP_COMMIT();                                                         \
                CP_WAIT1();                                                          \
            } else {                                                                 \
                CP_WAIT0();                                                          \
            }                                                                        \
            __syncthreads();                                                         \
            uint32_t sb = stage0 + (uint32_t)cur * 32768u;                           \
            uint32_t uA = sb, uB = sb + 16384u;                                      \
            MMA_COMPUTE_CHUNK();                                                     \
            __syncthreads();                                                         \
        }                                                                            \
    } while (0)

// ====== gemm_prep16: W12 = W1@W2 (fp16x3); epilogue routes to W13T/WpoolT/WbMidT ======
__global__ __launch_bounds__(256)
void gemm_prep16(const float* __restrict__ W1) {
    extern __shared__ char smem[];
    uint32_t raw  = smem_u32(smem);
    uint32_t base = (raw + 1023u) & ~1023u;
    char* pal = smem + (base - raw);
    const uint32_t uAh = base, uAl = base + 16384u, uBh = base + 32768u, uBl = base + 49152u;
    char* pAh = pal; char* pAl = pAh + 16384; char* pBh = pAl + 16384; char* pBl = pBh + 16384;

    int tid = threadIdx.x;
    int wid = tid >> 5, lane = tid & 31;
    int warpM = wid & 3, warpN = wid >> 2;
    int l = blockIdx.z;
    int blockRow = blockIdx.y * 128;   // W12 rows (k-dim of layer GEMMs)
    int blockCol = blockIdx.x * 128;   // W12 cols

    const float* W1l = W1 + (long)l * K1 * HH;
    const __half* W2h = g_W2Thi + (long)l * N1 * HH;
    const __half* W2l_ = g_W2Tlo + (long)l * N1 * HH;

    float acc[2][8][4];
    #pragma unroll
    for (int a = 0; a < 2; a++)
        #pragma unroll
        for (int b = 0; b < 8; b++)
            #pragma unroll
            for (int c = 0; c < 4; c++) acc[a][b][c] = 0.f;

    for (int ck = 0; ck < HH / KCH; ck++) {
        int c0 = ck * KCH;
        #pragma unroll
        for (int it = 0; it < 4; it++) {
            int idx = tid + it * 256;
            int row = idx >> 3, q = idx & 7;
            const float* ap = W1l + (long)(blockRow + row) * HH + c0 + q * 8;
            float4 f0 = *(const float4*)ap;
            float4 f1 = *(const float4*)(ap + 4);
            __align__(16) __half h[8];
            __align__(16) __half lo[8];
            split_h16(f0.x, h[0], lo[0]); split_h16(f0.y, h[1], lo[1]);
            split_h16(f0.z, h[2], lo[2]); split_h16(f0.w, h[3], lo[3]);
            split_h16(f1.x, h[4], lo[4]); split_h16(f1.y, h[5], lo[5]);
            split_h16(f1.z, h[6], lo[6]); split_h16(f1.w, h[7], lo[7]);
            uint32_t d = SW128((uint32_t)(row * 128 + q * 16));
            *(uint4*)(pAh + d) = *(uint4*)h;
            *(uint4*)(pAl + d) = *(uint4*)lo;
            long bo = (long)(blockCol + row) * HH + c0;
            *(uint4*)(pBh + d) = ((const uint4*)(W2h + bo))[q];
            *(uint4*)(pBl + d) = ((const uint4*)(W2l_ + bo))[q];
        }
        __syncthreads();
        MMA_COMPUTE_CHUNK3();
        __syncthreads();
    }

    // stage C, 129-stride (scalar stores — odd stride!)
    float* Cs = (float*)pal;
    #pragma unroll
    for (int mt = 0; mt < 2; mt++)
        #pragma unroll
        for (int nt = 0; nt < 8; nt++) {
            int r0 = warpM * 32 + mt * 16 + (lane >> 2);
            int cc = warpN * 64 + nt * 8 + (lane & 3) * 2;
            float* c = acc[mt][nt];
            Cs[r0 * 129 + cc]           = c[0];
            Cs[r0 * 129 + cc + 1]       = c[1];
            Cs[(r0 + 8) * 129 + cc]     = c[2];
            Cs[(r0 + 8) * 129 + cc + 1] = c[3];
        }
    __syncthreads();

    // route W12[m][n] -> destination arrays (each region has exactly one consumer)
    {
        int c  = tid >> 1;
        int kp = (tid & 1) * 64;
        int n = blockCol + c;
        int rowBase = blockRow + kp;        // 64-aligned, never crosses 256-boundary
        int region = rowBase >> 8;          // 0=Wa,1=Wb,2=Wc
        int kl = rowBase & 255;
        __half* dst;
        if (region == 0) {
            if (n < 768) dst = g_W13T + (long)l * N13 * DD + (long)n * DD + kl;
            else         dst = g_WpoolT + (long)l * HH * KAGG + (long)(n - 768) * KAGG + 512 + kl;
        } else if (region == 1) {
            if (n < 512)      dst = g_WpoolT + (long)l * HH * KAGG + (long)n * KAGG + 0 + kl;
            else if (n < 768) dst = g_WbMidT + (long)l * DD * DD + (long)(n - 512) * DD + kl;
            else              dst = g_WpoolT + (long)l * HH * KAGG + (long)(n - 768) * KAGG + 768 + kl;
        } else {
            if (n < 512) dst = g_WpoolT + (long)l * HH * KAGG + (long)n * KAGG + 256 + kl;
            else         dst = g_W13T + (long)l * N13 * DD + (long)(768 + n - 512) * DD + kl;
        }
        #pragma unroll
        for (int i = 0; i < 64; i += 8) {
            __align__(16) __half h[8];
            #pragma unroll
            for (int j = 0; j < 8; j++)
                h[j] = __float2half_rn(Cs[(kp + i + j) * 129 + c]);
            *(uint4*)(dst + i) = *(uint4*)h;
        }
    }
}

// ============ gemmP13: P13 = obj @ [Wa(0:768) | Wc(512:1280)]  (N=1536, K=256) ============
__global__ __launch_bounds__(256, 2)
void gemmP13(int srcBuf, int layer) {
    extern __shared__ char smem[];
    uint32_t raw  = smem_u32(smem);
    uint32_t base = (raw + 1023u) & ~1023u;
    const uint32_t stage0 = base + 1024;

    int tid = threadIdx.x;
    int wid = tid >> 5, lane = tid & 31;
    int warpM = wid & 3, warpN = wid >> 2;
    int blockRow = blockIdx.y * 128;
    int blockCol = blockIdx.x * 128;

    const __half* aF = g_objF[srcBuf];
    const __half* WT = g_W13T + (long)layer * N13 * DD;

    float acc[2][8][4];
    #pragma unroll
    for (int a = 0; a < 2; a++)
        #pragma unroll
        for (int b = 0; b < 8; b++)
            #pragma unroll
            for (int c = 0; c < 4; c++) acc[a][b][c] = 0.f;

    MMA_PIPE_LOOP(DD / KCH, aF, NOBJ, DD);

    #pragma unroll
    for (int mt = 0; mt < 2; mt++) {
        int r0 = blockRow + warpM * 32 + mt * 16 + (lane >> 2);
        #pragma unroll
        for (int nt = 0; nt < 8; nt++) {
            int gc = blockCol + warpN * 64 + nt * 8 + (lane & 3) * 2;
            float* c = acc[mt][nt];
            if (r0 < NOBJ)
                *(float2*)&g_P13[(long)r0 * N13 + gc] = make_float2(c[0], c[1]);
            if (r0 + 8 < NOBJ)
                *(float2*)&g_P13[(long)(r0 + 8) * N13 + gc] = make_float2(c[2], c[3]);
        }
    }
}

// ====== gemmPool: pooledF = ([Ps|No|Ns|Po]@Wpool + degS*(P13a+bS) + degO*(P13c+bO)) * inv ======
__global__ __launch_bounds__(256, 2)
void gemmPool(int layer) {
    extern __shared__ char smem[];
    uint32_t raw  = smem_u32(smem);
    uint32_t base = (raw + 1023u) & ~1023u;
    char* pal = smem + (base - raw);
    const uint32_t stage0 = base + 1024;

    int tid = threadIdx.x;
    int wid = tid >> 5, lane = tid & 31;
    int warpM = wid & 3, warpN = wid >> 2;
    int blockRow = blockIdx.y * 128;
    int blockCol = blockIdx.x * 128;

    const __half* aF = g_aggF;
    const __half* WT = g_WpoolT + (long)layer * HH * KAGG;

    float acc[2][8][4];
    #pragma unroll
    for (int a = 0; a < 2; a++)
        #pragma unroll
        for (int b = 0; b < 8; b++)
            #pragma unroll
            for (int c = 0; c < 4; c++) acc[a][b][c] = 0.f;

    MMA_PIPE_LOOP(KAGG / KCH, aF, NOBJ, KAGG);

    float* Cs = (float*)(pal + 1024);
    MMA_STAGE_C();
    __syncthreads();

    const float* biasL = g_b12 + layer * N1;
    #pragma unroll
    for (int i = 0; i < 16; i++) {
        int f = tid + i * 256;
        int row = f >> 5;
        int c4 = (f & 31) << 2;
        int gr = blockRow + row;
        if (gr >= NOBJ) continue;
        int gc0 = blockCol + c4;                     // pooled col n in [0,512)
        float4 v = *(float4*)&Cs[row * 128 + c4];
        float dS = (float)g_degS[gr], dO = (float)g_degO[gr];
        float4 pa = *(const float4*)&g_P13[(long)gr * N13 + gc0];          // Wa col n
        float4 pc = *(const float4*)&g_P13[(long)gr * N13 + 1024 + gc0];   // Wc col 768+n
        float4 bS = *(const float4*)&biasL[gc0];
        float4 bO = *(const float4*)&biasL[768 + gc0];
        float inv = g_inv[gr];
        float r0 = (v.x + dS * (pa.x + bS.x) + dO * (pc.x + bO.x)) * inv;
        float r1 = (v.y + dS * (pa.y + bS.y) + dO * (pc.y + bO.y)) * inv;
        float r2 = (v.z + dS * (pa.z + bS.z) + dO * (pc.z + bO.z)) * inv;
        float r3 = (v.w + dS * (pa.w + bS.w) + dO * (pc.w + bO.w)) * inv;
        *(uint2*)(g_pooledF + (long)gr * HH + gc0) =
            make_uint2(pack_h2(r0, r1), pack_h2(r2, r3));
    }
}

// ====== gemmP2: new_p = pred@WbMid + P13[s](Wa mid) + P13[o](Wc mid) + b12mid  (N=256) ======
__global__ __launch_bounds__(256, 2)
void gemmP2(int srcBuf, int layer, int last, float* __restrict__ predExtOut) {
    extern __shared__ char smem[];
    uint32_t raw  = smem_u32(smem);
    uint32_t base = (raw + 1023u) & ~1023u;
    char* pal = smem + (base - raw);
    int* sIdxS = (int*)(pal);
    int* oIdxS = (int*)(pal + 512);
    const uint32_t stage0 = base + 1024;

    int tid = threadIdx.x;
    int wid = tid >> 5, lane = tid & 31;
    int warpM = wid & 3, warpN = wid >> 2;
    int blockRow = blockIdx.y * 128;
    int blockCol = blockIdx.x * 128;

    const __half* aF = g_predF[srcBuf];
    const __half* WT = g_WbMidT + (long)layer * DD * DD;

    if (tid < 128) {
        int gr = blockRow + tid; if (gr >= NTRI) gr = NTRI - 1;
        sIdxS[tid] = g_sidx[gr];
        oIdxS[tid] = g_oidx[gr];
    }

    float acc[2][8][4];
    #pragma unroll
    for (int a = 0; a < 2; a++)
        #pragma unroll
        for (int b = 0; b < 8; b++)
            #pragma unroll
            for (int c = 0; c < 4; c++) acc[a][b][c] = 0.f;

    MMA_PIPE_LOOP(DD / KCH, aF, NTRI, DD);

    float* Cs = (float*)(pal + 1024);
    MMA_STAGE_C();
    __syncthreads();

    const float* biasL = g_b12 + layer * N1;
    __half* pOut = g_predF[srcBuf ^ 1];
    #pragma unroll
    for (int i = 0; i < 16; i++) {
        int f = tid + i * 256;
        int row = f >> 5;
        int c4 = (f & 31) << 2;
        int gr = blockRow + row;
        if (gr >= NTRI) continue;
        int sI = sIdxS[row], oI = oIdxS[row];
        int pc = blockCol + c4;                      // pred col in [0,256)
        float4 v  = *(float4*)&Cs[row * 128 + c4];
        float4 bb = *(const float4*)&biasL[512 + pc];
        float4 ps = *(const float4*)&g_P13[(long)sI * N13 + 512 + pc];   // Wa col 512+pc
        float4 po = *(const float4*)&g_P13[(long)oI * N13 + 768 + pc];   // Wc col 512+pc
        v.x += bb.x + ps.x + po.x;
        v.y += bb.y + ps.y + po.y;
        v.z += bb.z + ps.z + po.z;
        v.w += bb.w + ps.w + po.w;
        if (last) {
            *(float4*)&predExtOut[(long)gr * DD + pc] = v;
        } else {
            *(uint2*)(pOut + (long)gr * DD + pc) =
                make_uint2(pack_h2(v.x, v.y), pack_h2(v.z, v.w));
        }
    }
}

// ====== gemmB: obj' = pooledF @ W34 + b34  (N=256, K=512) ======
__global__ __launch_bounds__(256, 2)
void gemmB_mma(int layer, int dstBuf, int last, float* __restrict__ objExtOut) {
    extern __shared__ char smem[];
    uint32_t raw  = smem_u32(smem);
    uint32_t base = (raw + 1023u) & ~1023u;
    char* pal = smem + (base - raw);
    const uint32_t stage0 = base + 1024;

    int tid = threadIdx.x;
    int wid = tid >> 5, lane = tid & 31;
    int warpM = wid & 3, warpN = wid >> 2;
    int blockRow = blockIdx.y * 128;
    int blockCol = blockIdx.x * 128;

    const __half* aF = g_pooledF;
    const __half* WT = g_W34T + (long)layer * DD * HH;

    float acc[2][8][4];
    #pragma unroll
    for (int a = 0; a < 2; a++)
        #pragma unroll
        for (int b = 0; b < 8; b++)
            #pragma unroll
            for (int c = 0; c < 4; c++) acc[a][b][c] = 0.f;

    MMA_PIPE_LOOP(HH / KCH, aF, NOBJ, HH);

    float* Cs = (float*)(pal + 1024);
    MMA_STAGE_C();
    __syncthreads();

    const float* biasL = g_b34 + layer * DD;
    __half* oOut = g_objF[dstBuf];
    #pragma unroll
    for (int i = 0; i < 16; i++) {
        int f = tid + i * 256;
        int row = f >> 5;
        int c4 = (f & 31) << 2;
        int gr = blockRow + row;
        if (gr >= NOBJ) continue;
        int gc0 = blockCol + c4;
        float4 v = *(float4*)&Cs[row * 128 + c4];
        float4 bb = *(const float4*)&biasL[gc0];
        v.x += bb.x; v.y += bb.y; v.z += bb.z; v.w += bb.w;
        if (last) {
            *(float4*)&objExtOut[(long)gr * DD + gc0] = v;
        } else {
            *(uint2*)(oOut + (long)gr * DD + gc0) =
                make_uint2(pack_h2(v.x, v.y), pack_h2(v.z, v.w));
        }
    }
}

// ======================= launcher =======================
extern "C" void kernel_launch(void* const* d_in, const int* in_sizes, int n_in,
                              void* d_out, int out_size) {
    const float* obj_in  = (const float*)d_in[0];
    const float* pred_in = (const float*)d_in[1];
    const void*  edges   = d_in[2];
    const float* W1 = (const float*)d_in[3];
    const float* b1 = (const float*)d_in[4];
    const float* W2 = (const float*)d_in[5];
    const float* b2 = (const float*)d_in[6];
    const float* W3 = (const float*)d_in[7];
    const float* b3 = (const float*)d_in[8];
    const float* W4 = (const float*)d_in[9];
    const float* b4 = (const float*)d_in[10];

    float* out_obj  = (float*)d_out;                     // [20000, 256]
    float* out_pred = (float*)d_out + (long)NOBJ * DD;   // [60000, 256]

    static int attr_done = 0;
    static void *degS_addr = nullptr, *degO_addr = nullptr, *agg_addr = nullptr;
    if (!attr_done) {
        cudaFuncSetAttribute(gemmP13,    cudaFuncAttributeMaxDynamicSharedMemorySize, MM_SMEMP);
        cudaFuncSetAttribute(gemmPool,   cudaFuncAttributeMaxDynamicSharedMemorySize, MM_SMEMP);
        cudaFuncSetAttribute(gemmP2,     cudaFuncAttributeMaxDynamicSharedMemorySize, MM_SMEMP);
        cudaFuncSetAttribute(gemmB_mma,  cudaFuncAttributeMaxDynamicSharedMemorySize, MM_SMEMP);
        cudaFuncSetAttribute(gemm_prep16, cudaFuncAttributeMaxDynamicSharedMemorySize, PRE_SMEM);
        cudaGetSymbolAddress(&degS_addr, g_degS);
        cudaGetSymbolAddress(&degO_addr, g_degO);
        cudaGetSymbolAddress(&agg_addr, g_agg);
        attr_done = 1;
    }

    dim3 gridP13(N13 / 128, cdiv_h(NOBJ, 128));   // (12, 157)
    dim3 gridPool(HH / 128, cdiv_h(NOBJ, 128));   // (4, 157)
    dim3 gridP2(DD / 128, cdiv_h(NTRI, 128));     // (2, 469)
    dim3 gridB(DD / 128, cdiv_h(NOBJ, 128));      // (2, 157)
    size_t aggBytes = (size_t)NOBJ * KAGG * sizeof(float);

    // ---- launches 1-3 minimal so launch 4 = gemmP13 (ncu capture slot) ----
    transpose_w2hl_kernel<<<dim3(HH / 32, N1 / 32, LL), dim3(32, 8)>>>(W2);          // 1
    gemm_prep16<<<dim3(N1 / 128, K1 / 128, LL), 256, PRE_SMEM>>>(W1);                // 2
    cvt_obj_kernel<<<cdiv_h(NOBJ * DD / 2, 256), 256>>>(obj_in);                     // 3
    gemmP13<<<gridP13, 256, MM_SMEMP>>>(0, 0);                                       // 4 (profiled)

    // ---- remaining prep ----
    cudaMemsetAsync(degS_addr, 0, NOBJ * sizeof(int));
    cudaMemsetAsync(degO_addr, 0, NOBJ * sizeof(int));
    convert_kernel<<<cdiv_h(NTRI, 256), 256>>>(edges);
    inv_kernel<<<cdiv_h(NOBJ, 256), 256>>>();
    sgemm_prep<<<dim3(DD / 128, HH / 128, LL), 256>>>(W3, W4, HH, DD, HH);
    transpose_w34_kernel<<<dim3(HH / 32, DD / 32, LL), dim3(32, 8)>>>();
    bias12_kernel<<<dim3(cdiv_h(N1, 256), 1, LL), 256>>>(b1, W2, b2);
    bias34_kernel<<<dim3(cdiv_h(DD, 256), 1, LL), 256>>>(b3, W4, b4);
    cvt_pred_kernel<<<cdiv_h(NTRI * DD / 2, 256), 256>>>(pred_in);

    // ---- layer 0 (P13 already computed) ----
    cudaMemsetAsync(agg_addr, 0, aggBytes);
    agg_scatter<<<cdiv_h(NTRI * 256, 256), 256>>>(0);
    cvt_agg_kernel<<<cdiv_h(NOBJ * KAGG / 2, 256), 256>>>();
    gemmPool<<<gridPool, 256, MM_SMEMP>>>(0);
    gemmP2<<<gridP2, 256, MM_SMEMP>>>(0, 0, 0, nullptr);
    gemmB_mma<<<gridB, 256, MM_SMEMP>>>(0, 1, 0, nullptr);

    // ---- layers 1..4 ----
    for (int l = 1; l < LL; l++) {
        int src = l & 1, dst = src ^ 1, last = (l == LL - 1);
        gemmP13<<<gridP13, 256, MM_SMEMP>>>(src, l);
        cudaMemsetAsync(agg_addr, 0, aggBytes);
        agg_scatter<<<cdiv_h(NTRI * 256, 256), 256>>>(src);
        cvt_agg_kernel<<<cdiv_h(NOBJ * KAGG / 2, 256), 256>>>();
        gemmPool<<<gridPool, 256, MM_SMEMP>>>(l);
        gemmP2<<<gridP2, 256, MM_SMEMP>>>(src, l, last, out_pred);
        gemmB_mma<<<gridB, 256, MM_SMEMP>>>(l, dst, last, out_obj);
    }
}